// round 1
// baseline (speedup 1.0000x reference)
#include <cuda_runtime.h>
#include <math.h>

#define BT    4096      // B*T
#define DIMD  1024
#define NH    16
#define HD    64
#define TT    2048
#define MLPH  4096

// ---------------- scratch (static device allocations; no cudaMalloc) ----------
__device__ float g_h  [BT * DIMD];      // rmsnorm output / ae1 temp
__device__ float g_q  [BT * DIMD];
__device__ float g_k  [BT * DIMD];
__device__ float g_v  [BT * DIMD];
__device__ float g_ao [BT * DIMD];      // attention output
__device__ float g_ae [BT * DIMD];      // silu(ae)
__device__ float g_x1 [BT * DIMD];      // running x after attn residual / modulated x
__device__ float g_mod[BT * 2048];      // only shift1|scale1 halves of mod
__device__ float g_hid[BT * MLPH];      // mlp hidden

// ---------------- rmsnorm over rows of 1024 ----------------------------------
__global__ void rmsnorm_kernel(const float* __restrict__ x,
                               const float* __restrict__ w,
                               float* __restrict__ y)
{
    int row = blockIdx.x;
    const float* xr = x + (size_t)row * DIMD;
    float v[4];
    float s = 0.f;
#pragma unroll
    for (int i = 0; i < 4; i++) {
        v[i] = xr[threadIdx.x + i * 256];
        s += v[i] * v[i];
    }
#pragma unroll
    for (int o = 16; o > 0; o >>= 1) s += __shfl_xor_sync(0xffffffffu, s, o);
    __shared__ float red[8];
    if ((threadIdx.x & 31) == 0) red[threadIdx.x >> 5] = s;
    __syncthreads();
    if (threadIdx.x == 0) {
        float t = 0.f;
#pragma unroll
        for (int i = 0; i < 8; i++) t += red[i];
        red[0] = rsqrtf(t * (1.0f / DIMD) + 1e-6f);
    }
    __syncthreads();
    float r = red[0];
    float* yr = y + (size_t)row * DIMD;
#pragma unroll
    for (int i = 0; i < 4; i++) {
        int c = threadIdx.x + i * 256;
        yr[c] = v[i] * r * w[c];
    }
}

// ---------------- per-head rmsnorm (rows of 64), in place ---------------------
__global__ void headnorm_kernel(float* __restrict__ q, const float* __restrict__ w)
{
    int gw   = (blockIdx.x * blockDim.x + threadIdx.x) >> 5;  // row index
    int lane = threadIdx.x & 31;
    if (gw >= BT * NH) return;
    float* p = q + (size_t)gw * HD;
    float a = p[lane];
    float b = p[lane + 32];
    float s = a * a + b * b;
#pragma unroll
    for (int o = 16; o > 0; o >>= 1) s += __shfl_xor_sync(0xffffffffu, s, o);
    float r = rsqrtf(s * (1.0f / HD) + 1e-6f);
    p[lane]      = a * r * w[lane];
    p[lane + 32] = b * r * w[lane + 32];
}

// ---------------- modulate: x = x*(1+scale1)+shift1 ---------------------------
__global__ void modulate_kernel(float* __restrict__ x, const float* __restrict__ mod)
{
    int idx = blockIdx.x * 256 + threadIdx.x;
    int row = idx >> 10;
    int col = idx & 1023;
    float shift = mod[(size_t)row * 2048 + col];
    float scale = mod[(size_t)row * 2048 + 1024 + col];
    x[idx] = x[idx] * (1.0f + scale) + shift;
}

// ---------------- SGEMM 128x128x8, TM=TN=8, 256 threads -----------------------
// C[M,N] = A[M,K] @ W[K,N](ldw) + bias, epilogue: none/silu/gelu/residual-add
#define EPI_NONE 0
#define EPI_SILU 1
#define EPI_GELU 2
#define EPI_RES  3

template<int EPI>
__global__ void __launch_bounds__(256) sgemm_kernel(
    const float* __restrict__ A, const float* __restrict__ W,
    const float* __restrict__ bias, const float* __restrict__ Res,
    float* __restrict__ C, int M, int N, int K, int ldw)
{
    __shared__ float As[8 * 128];
    __shared__ float Bs[8 * 128];

    int tid  = threadIdx.x;
    int brow = blockIdx.y * 128;
    int bcol = blockIdx.x * 128;

    int arow = tid >> 1;            // 0..127
    int acol = (tid & 1) << 2;      // 0 or 4
    int wrow = tid >> 5;            // 0..7
    int wcol = (tid & 31) << 2;     // 0..124

    const float* Ag = A + (size_t)(brow + arow) * K + acol;
    const float* Wg = W + (size_t)wrow * ldw + bcol + wcol;

    int tr = (tid >> 4) << 3;       // output row base within tile
    int tc = (tid & 15) << 3;       // output col base within tile

    float acc[8][8];
#pragma unroll
    for (int i = 0; i < 8; i++)
#pragma unroll
        for (int j = 0; j < 8; j++) acc[i][j] = 0.f;

    for (int k0 = 0; k0 < K; k0 += 8) {
        float4 av = *(const float4*)Ag;  Ag += 8;
        float4 bv = *(const float4*)Wg;  Wg += (size_t)8 * ldw;

        As[(acol + 0) * 128 + arow] = av.x;
        As[(acol + 1) * 128 + arow] = av.y;
        As[(acol + 2) * 128 + arow] = av.z;
        As[(acol + 3) * 128 + arow] = av.w;
        *(float4*)&Bs[wrow * 128 + wcol] = bv;
        __syncthreads();

#pragma unroll
        for (int k = 0; k < 8; k++) {
            float ra[8], rb[8];
            *(float4*)&ra[0] = *(float4*)&As[k * 128 + tr];
            *(float4*)&ra[4] = *(float4*)&As[k * 128 + tr + 4];
            *(float4*)&rb[0] = *(float4*)&Bs[k * 128 + tc];
            *(float4*)&rb[4] = *(float4*)&Bs[k * 128 + tc + 4];
#pragma unroll
            for (int i = 0; i < 8; i++)
#pragma unroll
                for (int j = 0; j < 8; j++)
                    acc[i][j] += ra[i] * rb[j];
        }
        __syncthreads();
    }

#pragma unroll
    for (int i = 0; i < 8; i++) {
        int row = brow + tr + i;
#pragma unroll
        for (int j = 0; j < 8; j += 4) {
            int col = bcol + tc + j;
            float4 r;
            r.x = acc[i][j + 0] + bias[col + 0];
            r.y = acc[i][j + 1] + bias[col + 1];
            r.z = acc[i][j + 2] + bias[col + 2];
            r.w = acc[i][j + 3] + bias[col + 3];
            if (EPI == EPI_SILU) {
                r.x = r.x / (1.f + expf(-r.x));
                r.y = r.y / (1.f + expf(-r.y));
                r.z = r.z / (1.f + expf(-r.z));
                r.w = r.w / (1.f + expf(-r.w));
            } else if (EPI == EPI_GELU) {
                const float c = 0.70710678118654752f;
                r.x = 0.5f * r.x * (1.f + erff(r.x * c));
                r.y = 0.5f * r.y * (1.f + erff(r.y * c));
                r.z = 0.5f * r.z * (1.f + erff(r.z * c));
                r.w = 0.5f * r.w * (1.f + erff(r.w * c));
            } else if (EPI == EPI_RES) {
                float4 rv = *(const float4*)&Res[(size_t)row * N + col];
                r.x += rv.x; r.y += rv.y; r.z += rv.z; r.w += rv.w;
            }
            *(float4*)&C[(size_t)row * N + col] = r;
        }
    }
}

// ---------------- causal flash attention, 64x64 tiles, HD=64 ------------------
// q,k,v layout: [B, T, H, HD] (i.e. [B,T,D] with head-major last dim)
__global__ void __launch_bounds__(256) attn_kernel(
    const float* __restrict__ Q, const float* __restrict__ K,
    const float* __restrict__ V, float* __restrict__ O)
{
    extern __shared__ float sm[];
    float* Qs = sm;            // [d][r] 64*64
    float* Ks = Qs + 4096;     // [d][c] 64*64
    float* Vs = Ks + 4096;     // [c][d] 64*64
    float* Ps = Vs + 4096;     // [r][c] 64*68 (padded)

    int tid = threadIdx.x;
    int qt  = blockIdx.x;          // q tile 0..31
    int bh  = blockIdx.y;          // b*H + h
    int b   = bh >> 4;
    int h   = bh & 15;

    const float* Qg = Q + (size_t)b * TT * DIMD + (size_t)h * HD;
    const float* Kg = K + (size_t)b * TT * DIMD + (size_t)h * HD;
    const float* Vg = V + (size_t)b * TT * DIMD + (size_t)h * HD;

    int lr = tid >> 4;             // 0..15 (row within load pass)
    int ld = (tid & 15) << 2;      // 0..60 (d, float4)

    // load Q tile transposed [d][r]
#pragma unroll
    for (int rr = 0; rr < 64; rr += 16) {
        int r = rr + lr;
        float4 qv = *(const float4*)(Qg + (size_t)(qt * 64 + r) * DIMD + ld);
        Qs[(ld + 0) * 64 + r] = qv.x;
        Qs[(ld + 1) * 64 + r] = qv.y;
        Qs[(ld + 2) * 64 + r] = qv.z;
        Qs[(ld + 3) * 64 + r] = qv.w;
    }

    int tr = (tid >> 4) << 2;      // output rows tr..tr+3
    int tc = (tid & 15) << 2;      // output cols tc..tc+3

    float m_i[4], l_i[4], oa[4][4];
#pragma unroll
    for (int i = 0; i < 4; i++) {
        m_i[i] = -1e30f; l_i[i] = 0.f;
#pragma unroll
        for (int j = 0; j < 4; j++) oa[i][j] = 0.f;
    }
    const float scale = 0.125f;    // HD^-0.5

    for (int kt = 0; kt <= qt; kt++) {
        __syncthreads();   // prev PV reads of Ks/Vs done (also covers Q load on iter0)
        // load K transposed [d][c], V natural [c][d]
#pragma unroll
        for (int rr = 0; rr < 64; rr += 16) {
            int c = rr + lr;
            float4 kv = *(const float4*)(Kg + (size_t)(kt * 64 + c) * DIMD + ld);
            Ks[(ld + 0) * 64 + c] = kv.x;
            Ks[(ld + 1) * 64 + c] = kv.y;
            Ks[(ld + 2) * 64 + c] = kv.z;
            Ks[(ld + 3) * 64 + c] = kv.w;
            float4 vv = *(const float4*)(Vg + (size_t)(kt * 64 + c) * DIMD + ld);
            *(float4*)&Vs[c * 64 + ld] = vv;
        }
        __syncthreads();

        // S = Q K^T  (4x4 fragment)
        float s[4][4];
#pragma unroll
        for (int i = 0; i < 4; i++)
#pragma unroll
            for (int j = 0; j < 4; j++) s[i][j] = 0.f;
#pragma unroll 8
        for (int d = 0; d < 64; d++) {
            float4 qv = *(float4*)&Qs[d * 64 + tr];
            float4 kv = *(float4*)&Ks[d * 64 + tc];
            float qa[4] = {qv.x, qv.y, qv.z, qv.w};
            float ka[4] = {kv.x, kv.y, kv.z, kv.w};
#pragma unroll
            for (int i = 0; i < 4; i++)
#pragma unroll
                for (int j = 0; j < 4; j++)
                    s[i][j] += qa[i] * ka[j];
        }

        bool diag = (kt == qt);
#pragma unroll
        for (int i = 0; i < 4; i++)
#pragma unroll
            for (int j = 0; j < 4; j++) {
                s[i][j] *= scale;
                if (diag && (tc + j > tr + i)) s[i][j] = -1e30f;
            }

        // online softmax (reduce across the 16 lanes of each row group)
        float mt[4], lt[4], al[4];
#pragma unroll
        for (int i = 0; i < 4; i++) {
            mt[i] = fmaxf(fmaxf(s[i][0], s[i][1]), fmaxf(s[i][2], s[i][3]));
        }
#pragma unroll
        for (int o = 8; o > 0; o >>= 1)
#pragma unroll
            for (int i = 0; i < 4; i++)
                mt[i] = fmaxf(mt[i], __shfl_xor_sync(0xffffffffu, mt[i], o));
#pragma unroll
        for (int i = 0; i < 4; i++) {
            float mn = fmaxf(m_i[i], mt[i]);
            al[i] = __expf(m_i[i] - mn);
            m_i[i] = mn;
            lt[i] = 0.f;
#pragma unroll
            for (int j = 0; j < 4; j++) {
                s[i][j] = __expf(s[i][j] - mn);
                lt[i] += s[i][j];
            }
        }
#pragma unroll
        for (int o = 8; o > 0; o >>= 1)
#pragma unroll
            for (int i = 0; i < 4; i++)
                lt[i] += __shfl_xor_sync(0xffffffffu, lt[i], o);
#pragma unroll
        for (int i = 0; i < 4; i++) {
            l_i[i] = l_i[i] * al[i] + lt[i];
#pragma unroll
            for (int j = 0; j < 4; j++) oa[i][j] *= al[i];
        }

        // write P to smem
#pragma unroll
        for (int i = 0; i < 4; i++) {
            float4 pv = make_float4(s[i][0], s[i][1], s[i][2], s[i][3]);
            *(float4*)&Ps[(tr + i) * 68 + tc] = pv;
        }
        __syncthreads();

        // O += P @ V
#pragma unroll 8
        for (int c = 0; c < 64; c++) {
            float pv[4];
#pragma unroll
            for (int i = 0; i < 4; i++) pv[i] = Ps[(tr + i) * 68 + c];
            float4 vv = *(float4*)&Vs[c * 64 + tc];
            float va[4] = {vv.x, vv.y, vv.z, vv.w};
#pragma unroll
            for (int i = 0; i < 4; i++)
#pragma unroll
                for (int j = 0; j < 4; j++)
                    oa[i][j] += pv[i] * va[j];
        }
    }

    float* Og = O + (size_t)b * TT * DIMD + (size_t)(qt * 64) * DIMD + (size_t)h * HD;
#pragma unroll
    for (int i = 0; i < 4; i++) {
        float inv = 1.f / l_i[i];
        float4 r = make_float4(oa[i][0] * inv, oa[i][1] * inv, oa[i][2] * inv, oa[i][3] * inv);
        *(float4*)&Og[(size_t)(tr + i) * DIMD + tc] = r;
    }
}

// ------------------------------- launch ---------------------------------------
extern "C" void kernel_launch(void* const* d_in, const int* in_sizes, int n_in,
                              void* d_out, int out_size)
{
    const float* x       = (const float*)d_in[0];
    const float* actions = (const float*)d_in[1];
    const float* n1_w    = (const float*)d_in[2];
    const float* n2_w    = (const float*)d_in[3];
    const float* q_w     = (const float*)d_in[4];
    const float* q_b     = (const float*)d_in[5];
    const float* k_w     = (const float*)d_in[6];
    const float* k_b     = (const float*)d_in[7];
    const float* v_w     = (const float*)d_in[8];
    const float* v_b     = (const float*)d_in[9];
    const float* qn_w    = (const float*)d_in[10];
    const float* kn_w    = (const float*)d_in[11];
    const float* o_w     = (const float*)d_in[12];
    const float* o_b     = (const float*)d_in[13];
    const float* ae1_w   = (const float*)d_in[14];
    const float* ae1_b   = (const float*)d_in[15];
    const float* ae2_w   = (const float*)d_in[16];
    const float* ae2_b   = (const float*)d_in[17];
    const float* mod_w   = (const float*)d_in[18];
    const float* mod_b   = (const float*)d_in[19];
    const float* m1_w    = (const float*)d_in[20];
    const float* m1_b    = (const float*)d_in[21];
    const float* m2_w    = (const float*)d_in[22];
    const float* m2_b    = (const float*)d_in[23];
    float* out           = (float*)d_out;

    float *h, *q, *k, *v, *ao, *ae, *x1, *mod, *hid;
    cudaGetSymbolAddress((void**)&h,   g_h);
    cudaGetSymbolAddress((void**)&q,   g_q);
    cudaGetSymbolAddress((void**)&k,   g_k);
    cudaGetSymbolAddress((void**)&v,   g_v);
    cudaGetSymbolAddress((void**)&ao,  g_ao);
    cudaGetSymbolAddress((void**)&ae,  g_ae);
    cudaGetSymbolAddress((void**)&x1,  g_x1);
    cudaGetSymbolAddress((void**)&mod, g_mod);
    cudaGetSymbolAddress((void**)&hid, g_hid);

    static int smem_set = 0;
    const int ATTN_SMEM = (4096 * 3 + 64 * 68) * 4;  // 66560 B
    if (!smem_set) {
        cudaFuncSetAttribute(attn_kernel, cudaFuncAttributeMaxDynamicSharedMemorySize, ATTN_SMEM);
        smem_set = 1;
    }

    dim3 g1024(DIMD / 128, BT / 128);   // (8, 32)
    dim3 g2048(2048 / 128, BT / 128);   // (16, 32)
    dim3 g4096(MLPH / 128, BT / 128);   // (32, 32)

    // 1) h = rmsnorm(x, n1_w)
    rmsnorm_kernel<<<BT, 256>>>(x, n1_w, h);
    // 2) q,k,v projections
    sgemm_kernel<EPI_NONE><<<g1024, 256>>>(h, q_w, q_b, nullptr, q, BT, DIMD, DIMD, DIMD);
    sgemm_kernel<EPI_NONE><<<g1024, 256>>>(h, k_w, k_b, nullptr, k, BT, DIMD, DIMD, DIMD);
    sgemm_kernel<EPI_NONE><<<g1024, 256>>>(h, v_w, v_b, nullptr, v, BT, DIMD, DIMD, DIMD);
    // 3) per-head RMSNorm of q,k
    headnorm_kernel<<<(BT * NH) / 8, 256>>>(q, qn_w);
    headnorm_kernel<<<(BT * NH) / 8, 256>>>(k, kn_w);
    // 4) causal attention
    attn_kernel<<<dim3(TT / 64, 2 * NH), 256, ATTN_SMEM>>>(q, k, v, ao);
    // 5) x1 = x + ao @ o_w + o_b
    sgemm_kernel<EPI_RES><<<g1024, 256>>>(ao, o_w, o_b, x, x1, BT, DIMD, DIMD, DIMD);
    // 6) t1 = silu(actions @ ae1_w + ae1_b)
    sgemm_kernel<EPI_SILU><<<g1024, 256>>>(actions, ae1_w, ae1_b, nullptr, h, BT, DIMD, 16, DIMD);
    // 7) ae_s = silu(t1 @ ae2_w + ae2_b)
    sgemm_kernel<EPI_SILU><<<g1024, 256>>>(h, ae2_w, ae2_b, nullptr, ae, BT, DIMD, DIMD, DIMD);
    // 8) mod = ae_s @ mod_w[:, :2048] + mod_b[:2048]   (shift1 | scale1)
    sgemm_kernel<EPI_NONE><<<g2048, 256>>>(ae, mod_w, mod_b, nullptr, mod, BT, 2048, DIMD, 4096);
    // 9) x1 = x1*(1+scale1)+shift1
    modulate_kernel<<<(BT * DIMD) / 256, 256>>>(x1, mod);
    // 10) h = rmsnorm(x1, n2_w)
    rmsnorm_kernel<<<BT, 256>>>(x1, n2_w, h);
    // 11) hid = gelu(h @ m1_w + m1_b)
    sgemm_kernel<EPI_GELU><<<g4096, 256>>>(h, m1_w, m1_b, nullptr, hid, BT, MLPH, DIMD, MLPH);
    // 12) out = x1 + hid @ m2_w + m2_b
    sgemm_kernel<EPI_RES><<<g1024, 256>>>(hid, m2_w, m2_b, x1, out, BT, DIMD, MLPH, DIMD);
}

// round 2
// speedup vs baseline: 1.7963x; 1.7963x over previous
#include <cuda_runtime.h>
#include <math.h>
#include <stdint.h>

#define BT    4096      // B*T
#define DIMD  1024
#define NH    16
#define HD    64
#define TT    2048
#define MLPH  4096

// ---------------- scratch (static device arrays; no cudaMalloc) ---------------
__device__ float g_h  [BT * DIMD];
__device__ float g_q  [BT * DIMD];
__device__ float g_k  [BT * DIMD];
__device__ float g_v  [BT * DIMD];
__device__ float g_ao [BT * DIMD];
__device__ float g_ae [BT * DIMD];
__device__ float g_x1 [BT * DIMD];
__device__ float g_mod[BT * 2048];
__device__ float g_hid[BT * MLPH];
// tf32-rounded weights
__device__ float g_wq  [DIMD * DIMD];
__device__ float g_wk  [DIMD * DIMD];
__device__ float g_wv  [DIMD * DIMD];
__device__ float g_wo  [DIMD * DIMD];
__device__ float g_wae2[DIMD * DIMD];
__device__ float g_wmod[DIMD * 2048];
__device__ float g_wm1 [DIMD * MLPH];
__device__ float g_wm2 [MLPH * DIMD];

__device__ __forceinline__ float tf32r(float x) {
    uint32_t o;
    asm("cvt.rna.tf32.f32 %0, %1;" : "=r"(o) : "f"(x));
    return __uint_as_float(o);
}

// ---------------- weight rounding --------------------------------------------
__global__ void round_kernel(const float* __restrict__ src, float* __restrict__ dst, int n4)
{
    int i = blockIdx.x * 256 + threadIdx.x;
    if (i >= n4) return;
    float4 v = ((const float4*)src)[i];
    v.x = tf32r(v.x); v.y = tf32r(v.y); v.z = tf32r(v.z); v.w = tf32r(v.w);
    ((float4*)dst)[i] = v;
}

// mod_w [1024][4096] -> take cols [0,2048) -> compact [1024][2048]
__global__ void round_mod_kernel(const float* __restrict__ src, float* __restrict__ dst)
{
    int i = blockIdx.x * 256 + threadIdx.x;   // over 1024*512 float4
    int row = i >> 9;
    int c4  = (i & 511) << 2;
    float4 v = *(const float4*)(src + (size_t)row * 4096 + c4);
    v.x = tf32r(v.x); v.y = tf32r(v.y); v.z = tf32r(v.z); v.w = tf32r(v.w);
    *(float4*)(dst + (size_t)row * 2048 + c4) = v;
}

// ---------------- rmsnorm over rows of 1024 (output tf32-rounded) -------------
__global__ void rmsnorm_kernel(const float* __restrict__ x,
                               const float* __restrict__ w,
                               float* __restrict__ y)
{
    int row = blockIdx.x;
    const float* xr = x + (size_t)row * DIMD;
    float v[4];
    float s = 0.f;
#pragma unroll
    for (int i = 0; i < 4; i++) {
        v[i] = xr[threadIdx.x + i * 256];
        s += v[i] * v[i];
    }
#pragma unroll
    for (int o = 16; o > 0; o >>= 1) s += __shfl_xor_sync(0xffffffffu, s, o);
    __shared__ float red[8];
    if ((threadIdx.x & 31) == 0) red[threadIdx.x >> 5] = s;
    __syncthreads();
    if (threadIdx.x == 0) {
        float t = 0.f;
#pragma unroll
        for (int i = 0; i < 8; i++) t += red[i];
        red[0] = rsqrtf(t * (1.0f / DIMD) + 1e-6f);
    }
    __syncthreads();
    float r = red[0];
    float* yr = y + (size_t)row * DIMD;
#pragma unroll
    for (int i = 0; i < 4; i++) {
        int c = threadIdx.x + i * 256;
        yr[c] = tf32r(v[i] * r * w[c]);
    }
}

// ---------------- per-head rmsnorm (rows of 64), in place ---------------------
__global__ void headnorm_kernel(float* __restrict__ q, const float* __restrict__ w)
{
    int gw   = (blockIdx.x * blockDim.x + threadIdx.x) >> 5;
    int lane = threadIdx.x & 31;
    if (gw >= BT * NH) return;
    float* p = q + (size_t)gw * HD;
    float a = p[lane];
    float b = p[lane + 32];
    float s = a * a + b * b;
#pragma unroll
    for (int o = 16; o > 0; o >>= 1) s += __shfl_xor_sync(0xffffffffu, s, o);
    float r = rsqrtf(s * (1.0f / HD) + 1e-6f);
    p[lane]      = a * r * w[lane];
    p[lane + 32] = b * r * w[lane + 32];
}

// ---------------- modulate: x = x*(1+scale1)+shift1 ---------------------------
__global__ void modulate_kernel(float* __restrict__ x, const float* __restrict__ mod)
{
    int idx = blockIdx.x * 256 + threadIdx.x;
    int row = idx >> 10;
    int col = idx & 1023;
    float shift = mod[(size_t)row * 2048 + col];
    float scale = mod[(size_t)row * 2048 + 1024 + col];
    x[idx] = x[idx] * (1.0f + scale) + shift;
}

// ---------------- ae1: actions[4096,16] @ ae1_w[16,1024] + b, silu, round -----
__global__ void __launch_bounds__(256) ae1_kernel(
    const float* __restrict__ A, const float* __restrict__ W,
    const float* __restrict__ bias, float* __restrict__ C)
{
    // one block per 128 rows x 1024 cols? keep simple: block = 64 rows, 256 thr
    // each thread computes 16 outputs along N.
    __shared__ float Ws[16 * 1024];
    __shared__ float As[64 * 16];
    int tid = blockIdx.y * 0 + threadIdx.x;
    // load full W (16x1024) once per block
    for (int i = tid; i < 16 * 1024 / 4; i += 256) {
        ((float4*)Ws)[i] = ((const float4*)W)[i];
    }
    int brow = blockIdx.x * 64;
    for (int i = tid; i < 64 * 16 / 4; i += 256) {
        ((float4*)As)[i] = *(const float4*)(A + (size_t)brow * 16 + i * 4);
    }
    __syncthreads();
    // thread -> (row r within 64, col block c within 1024): 64*4 thread-groups
    int r = tid >> 2;                 // 0..63
    int cb = (tid & 3) * 256;         // 4 col blocks of 256
    float a[16];
#pragma unroll
    for (int k = 0; k < 16; k++) a[k] = As[r * 16 + k];
    float* Cr = C + (size_t)(brow + r) * 1024;
    for (int cc = 0; cc < 256; cc += 4) {
        int col = cb + cc;
        float4 o = make_float4(bias[col], bias[col + 1], bias[col + 2], bias[col + 3]);
#pragma unroll
        for (int k = 0; k < 16; k++) {
            float4 wv = *(float4*)&Ws[k * 1024 + col];
            o.x += a[k] * wv.x; o.y += a[k] * wv.y;
            o.z += a[k] * wv.z; o.w += a[k] * wv.w;
        }
        o.x = tf32r(o.x / (1.f + expf(-o.x)));
        o.y = tf32r(o.y / (1.f + expf(-o.y)));
        o.z = tf32r(o.z / (1.f + expf(-o.z)));
        o.w = tf32r(o.w / (1.f + expf(-o.w)));
        *(float4*)&Cr[col] = o;
    }
}

// ---------------- tf32 tensor-core GEMM 128x128x32 ----------------------------
// C[M,N] = A[M,K] @ W[K,N] + bias (+ epilogue). A,W must be tf32-pre-rounded.
#define EPI_NONE   0
#define EPI_SILU_R 1
#define EPI_GELU_R 2
#define EPI_RES    3

#define BM 128
#define BN 128
#define BK 32
#define ASTR 36
#define BSTR 136
#define TMMA_SMEM ((2 * BM * ASTR + 2 * BK * BSTR) * 4)   // 71680 B

__device__ __forceinline__ void cp16(float* s, const float* g)
{
    uint32_t sa = (uint32_t)__cvta_generic_to_shared(s);
    asm volatile("cp.async.cg.shared.global [%0], [%1], 16;\n" :: "r"(sa), "l"(g));
}

template<int EPI>
__global__ void __launch_bounds__(256, 2) tmma_kernel(
    const float* __restrict__ A, const float* __restrict__ W,
    const float* __restrict__ bias, const float* __restrict__ Res,
    float* __restrict__ C, int M, int N, int K)
{
    extern __shared__ float sm[];
    float* Asm = sm;                       // [2][BM][ASTR]
    float* Bsm = sm + 2 * BM * ASTR;       // [2][BK][BSTR]

    int tid  = threadIdx.x;
    int brow = blockIdx.y * BM;
    int bcol = blockIdx.x * BN;
    int warp = tid >> 5, lane = tid & 31;
    int g = lane >> 2, t = lane & 3;
    int wr = warp & 1, wc = warp >> 1;

    int ar = tid >> 1, ak = (tid & 1) << 4;       // A row, k-base
    int bk = tid >> 3, bn = (tid & 7) << 4;       // B k-row, col-base
    const float* Ag = A + (size_t)(brow + ar) * K + ak;
    const float* Wg = W + (size_t)bk * N + bcol + bn;

    float acc[4][4][4];
#pragma unroll
    for (int i = 0; i < 4; i++)
#pragma unroll
        for (int j = 0; j < 4; j++)
#pragma unroll
            for (int c = 0; c < 4; c++) acc[i][j][c] = 0.f;

    int nk = K / BK;

    // prologue: chunk 0 -> buf 0
    {
        float* Ab = Asm; float* Bb = Bsm;
#pragma unroll
        for (int j = 0; j < 4; j++) cp16(Ab + ar * ASTR + ak + j * 4, Ag + j * 4);
#pragma unroll
        for (int j = 0; j < 4; j++) cp16(Bb + bk * BSTR + bn + j * 4, Wg + j * 4);
        asm volatile("cp.async.commit_group;");
    }

    for (int i = 0; i < nk; i++) {
        int buf = i & 1;
        if (i + 1 < nk) {
            int kc = (i + 1) * BK;
            float* Ab = Asm + (buf ^ 1) * BM * ASTR;
            float* Bb = Bsm + (buf ^ 1) * BK * BSTR;
#pragma unroll
            for (int j = 0; j < 4; j++) cp16(Ab + ar * ASTR + ak + j * 4, Ag + kc + j * 4);
#pragma unroll
            for (int j = 0; j < 4; j++) cp16(Bb + bk * BSTR + bn + j * 4, Wg + (size_t)kc * N + j * 4);
            asm volatile("cp.async.commit_group;");
            asm volatile("cp.async.wait_group 1;");
        } else {
            asm volatile("cp.async.wait_group 0;");
        }
        __syncthreads();

        const float* Ab = Asm + buf * BM * ASTR + (wr * 64) * ASTR;
        const float* Bb = Bsm + buf * BK * BSTR + wc * 32;
#pragma unroll
        for (int ks = 0; ks < 4; ks++) {
            int k0 = ks * 8;
            uint32_t af[4][4], bf[4][2];
#pragma unroll
            for (int ti = 0; ti < 4; ti++) {
                const float* p = Ab + (ti * 16 + g) * ASTR + k0 + t;
                af[ti][0] = __float_as_uint(p[0]);
                af[ti][1] = __float_as_uint(p[8 * ASTR]);
                af[ti][2] = __float_as_uint(p[4]);
                af[ti][3] = __float_as_uint(p[8 * ASTR + 4]);
            }
#pragma unroll
            for (int tj = 0; tj < 4; tj++) {
                const float* p = Bb + (k0 + t) * BSTR + tj * 8 + g;
                bf[tj][0] = __float_as_uint(p[0]);
                bf[tj][1] = __float_as_uint(p[4 * BSTR]);
            }
#pragma unroll
            for (int ti = 0; ti < 4; ti++)
#pragma unroll
                for (int tj = 0; tj < 4; tj++)
                    asm volatile(
                        "mma.sync.aligned.m16n8k8.row.col.f32.tf32.tf32.f32 "
                        "{%0,%1,%2,%3},{%4,%5,%6,%7},{%8,%9},{%0,%1,%2,%3};"
                        : "+f"(acc[ti][tj][0]), "+f"(acc[ti][tj][1]),
                          "+f"(acc[ti][tj][2]), "+f"(acc[ti][tj][3])
                        : "r"(af[ti][0]), "r"(af[ti][1]), "r"(af[ti][2]), "r"(af[ti][3]),
                          "r"(bf[tj][0]), "r"(bf[tj][1]));
        }
        __syncthreads();
    }

    // epilogue
#pragma unroll
    for (int ti = 0; ti < 4; ti++) {
        int r0 = brow + wr * 64 + ti * 16 + g;
#pragma unroll
        for (int tj = 0; tj < 4; tj++) {
            int c0 = bcol + wc * 32 + tj * 8 + 2 * t;
            float b0 = bias[c0], b1 = bias[c0 + 1];
#pragma unroll
            for (int half = 0; half < 2; half++) {
                int row = r0 + half * 8;
                float vx = acc[ti][tj][half * 2 + 0] + b0;
                float vy = acc[ti][tj][half * 2 + 1] + b1;
                if (EPI == EPI_SILU_R) {
                    vx = tf32r(vx / (1.f + expf(-vx)));
                    vy = tf32r(vy / (1.f + expf(-vy)));
                } else if (EPI == EPI_GELU_R) {
                    const float cst = 0.70710678118654752f;
                    vx = tf32r(0.5f * vx * (1.f + erff(vx * cst)));
                    vy = tf32r(0.5f * vy * (1.f + erff(vy * cst)));
                } else if (EPI == EPI_RES) {
                    float2 rv = *(const float2*)&Res[(size_t)row * N + c0];
                    vx += rv.x; vy += rv.y;
                }
                float2 o = make_float2(vx, vy);
                *(float2*)&C[(size_t)row * N + c0] = o;
            }
        }
    }
}

// ---------------- causal flash attention, 64x64 tiles, HD=64 ------------------
__global__ void __launch_bounds__(256) attn_kernel(
    const float* __restrict__ Q, const float* __restrict__ K,
    const float* __restrict__ V, float* __restrict__ O)
{
    extern __shared__ float smx[];
    float* Qs = smx;
    float* Ks = Qs + 4096;
    float* Vs = Ks + 4096;
    float* Ps = Vs + 4096;

    int tid = threadIdx.x;
    int qt  = blockIdx.x;
    int bh  = blockIdx.y;
    int b   = bh >> 4;
    int h   = bh & 15;

    const float* Qg = Q + (size_t)b * TT * DIMD + (size_t)h * HD;
    const float* Kg = K + (size_t)b * TT * DIMD + (size_t)h * HD;
    const float* Vg = V + (size_t)b * TT * DIMD + (size_t)h * HD;

    int lr = tid >> 4;
    int ld = (tid & 15) << 2;

#pragma unroll
    for (int rr = 0; rr < 64; rr += 16) {
        int r = rr + lr;
        float4 qv = *(const float4*)(Qg + (size_t)(qt * 64 + r) * DIMD + ld);
        Qs[(ld + 0) * 64 + r] = qv.x;
        Qs[(ld + 1) * 64 + r] = qv.y;
        Qs[(ld + 2) * 64 + r] = qv.z;
        Qs[(ld + 3) * 64 + r] = qv.w;
    }

    int tr = (tid >> 4) << 2;
    int tc = (tid & 15) << 2;

    float m_i[4], l_i[4], oa[4][4];
#pragma unroll
    for (int i = 0; i < 4; i++) {
        m_i[i] = -1e30f; l_i[i] = 0.f;
#pragma unroll
        for (int j = 0; j < 4; j++) oa[i][j] = 0.f;
    }
    const float scale = 0.125f;

    for (int kt = 0; kt <= qt; kt++) {
        __syncthreads();
#pragma unroll
        for (int rr = 0; rr < 64; rr += 16) {
            int c = rr + lr;
            float4 kv = *(const float4*)(Kg + (size_t)(kt * 64 + c) * DIMD + ld);
            Ks[(ld + 0) * 64 + c] = kv.x;
            Ks[(ld + 1) * 64 + c] = kv.y;
            Ks[(ld + 2) * 64 + c] = kv.z;
            Ks[(ld + 3) * 64 + c] = kv.w;
            float4 vv = *(const float4*)(Vg + (size_t)(kt * 64 + c) * DIMD + ld);
            *(float4*)&Vs[c * 64 + ld] = vv;
        }
        __syncthreads();

        float s[4][4];
#pragma unroll
        for (int i = 0; i < 4; i++)
#pragma unroll
            for (int j = 0; j < 4; j++) s[i][j] = 0.f;
#pragma unroll 8
        for (int d = 0; d < 64; d++) {
            float4 qv = *(float4*)&Qs[d * 64 + tr];
            float4 kv = *(float4*)&Ks[d * 64 + tc];
            float qa[4] = {qv.x, qv.y, qv.z, qv.w};
            float ka[4] = {kv.x, kv.y, kv.z, kv.w};
#pragma unroll
            for (int i = 0; i < 4; i++)
#pragma unroll
                for (int j = 0; j < 4; j++)
                    s[i][j] += qa[i] * ka[j];
        }

        bool diag = (kt == qt);
#pragma unroll
        for (int i = 0; i < 4; i++)
#pragma unroll
            for (int j = 0; j < 4; j++) {
                s[i][j] *= scale;
                if (diag && (tc + j > tr + i)) s[i][j] = -1e30f;
            }

        float mt[4], lt[4], al[4];
#pragma unroll
        for (int i = 0; i < 4; i++)
            mt[i] = fmaxf(fmaxf(s[i][0], s[i][1]), fmaxf(s[i][2], s[i][3]));
#pragma unroll
        for (int o = 8; o > 0; o >>= 1)
#pragma unroll
            for (int i = 0; i < 4; i++)
                mt[i] = fmaxf(mt[i], __shfl_xor_sync(0xffffffffu, mt[i], o));
#pragma unroll
        for (int i = 0; i < 4; i++) {
            float mn = fmaxf(m_i[i], mt[i]);
            al[i] = __expf(m_i[i] - mn);
            m_i[i] = mn;
            lt[i] = 0.f;
#pragma unroll
            for (int j = 0; j < 4; j++) {
                s[i][j] = __expf(s[i][j] - mn);
                lt[i] += s[i][j];
            }
        }
#pragma unroll
        for (int o = 8; o > 0; o >>= 1)
#pragma unroll
            for (int i = 0; i < 4; i++)
                lt[i] += __shfl_xor_sync(0xffffffffu, lt[i], o);
#pragma unroll
        for (int i = 0; i < 4; i++) {
            l_i[i] = l_i[i] * al[i] + lt[i];
#pragma unroll
            for (int j = 0; j < 4; j++) oa[i][j] *= al[i];
        }

#pragma unroll
        for (int i = 0; i < 4; i++) {
            float4 pv = make_float4(s[i][0], s[i][1], s[i][2], s[i][3]);
            *(float4*)&Ps[(tr + i) * 68 + tc] = pv;
        }
        __syncthreads();

#pragma unroll 8
        for (int c = 0; c < 64; c++) {
            float pv[4];
#pragma unroll
            for (int i = 0; i < 4; i++) pv[i] = Ps[(tr + i) * 68 + c];
            float4 vv = *(float4*)&Vs[c * 64 + tc];
            float va[4] = {vv.x, vv.y, vv.z, vv.w};
#pragma unroll
            for (int i = 0; i < 4; i++)
#pragma unroll
                for (int j = 0; j < 4; j++)
                    oa[i][j] += pv[i] * va[j];
        }
    }

    float* Og = O + (size_t)b * TT * DIMD + (size_t)(qt * 64) * DIMD + (size_t)h * HD;
#pragma unroll
    for (int i = 0; i < 4; i++) {
        float inv = 1.f / l_i[i];
        float4 r = make_float4(tf32r(oa[i][0] * inv), tf32r(oa[i][1] * inv),
                               tf32r(oa[i][2] * inv), tf32r(oa[i][3] * inv));
        *(float4*)&Og[(size_t)(tr + i) * DIMD + tc] = r;
    }
}

// ------------------------------- launch ---------------------------------------
extern "C" void kernel_launch(void* const* d_in, const int* in_sizes, int n_in,
                              void* d_out, int out_size)
{
    const float* x       = (const float*)d_in[0];
    const float* actions = (const float*)d_in[1];
    const float* n1_w    = (const float*)d_in[2];
    const float* n2_w    = (const float*)d_in[3];
    const float* q_w     = (const float*)d_in[4];
    const float* q_b     = (const float*)d_in[5];
    const float* k_w     = (const float*)d_in[6];
    const float* k_b     = (const float*)d_in[7];
    const float* v_w     = (const float*)d_in[8];
    const float* v_b     = (const float*)d_in[9];
    const float* qn_w    = (const float*)d_in[10];
    const float* kn_w    = (const float*)d_in[11];
    const float* o_w     = (const float*)d_in[12];
    const float* o_b     = (const float*)d_in[13];
    const float* ae1_w   = (const float*)d_in[14];
    const float* ae1_b   = (const float*)d_in[15];
    const float* ae2_w   = (const float*)d_in[16];
    const float* ae2_b   = (const float*)d_in[17];
    const float* mod_w   = (const float*)d_in[18];
    const float* mod_b   = (const float*)d_in[19];
    const float* m1_w    = (const float*)d_in[20];
    const float* m1_b    = (const float*)d_in[21];
    const float* m2_w    = (const float*)d_in[22];
    const float* m2_b    = (const float*)d_in[23];
    float* out           = (float*)d_out;

    float *h, *q, *k, *v, *ao, *ae, *x1, *mod, *hid;
    float *wq, *wk, *wv, *wo, *wae2, *wmod, *wm1, *wm2;
    cudaGetSymbolAddress((void**)&h,    g_h);
    cudaGetSymbolAddress((void**)&q,    g_q);
    cudaGetSymbolAddress((void**)&k,    g_k);
    cudaGetSymbolAddress((void**)&v,    g_v);
    cudaGetSymbolAddress((void**)&ao,   g_ao);
    cudaGetSymbolAddress((void**)&ae,   g_ae);
    cudaGetSymbolAddress((void**)&x1,   g_x1);
    cudaGetSymbolAddress((void**)&mod,  g_mod);
    cudaGetSymbolAddress((void**)&hid,  g_hid);
    cudaGetSymbolAddress((void**)&wq,   g_wq);
    cudaGetSymbolAddress((void**)&wk,   g_wk);
    cudaGetSymbolAddress((void**)&wv,   g_wv);
    cudaGetSymbolAddress((void**)&wo,   g_wo);
    cudaGetSymbolAddress((void**)&wae2, g_wae2);
    cudaGetSymbolAddress((void**)&wmod, g_wmod);
    cudaGetSymbolAddress((void**)&wm1,  g_wm1);
    cudaGetSymbolAddress((void**)&wm2,  g_wm2);

    static int attr_set = 0;
    const int ATTN_SMEM = (4096 * 3 + 64 * 68) * 4;
    if (!attr_set) {
        cudaFuncSetAttribute(attn_kernel, cudaFuncAttributeMaxDynamicSharedMemorySize, ATTN_SMEM);
        cudaFuncSetAttribute(tmma_kernel<EPI_NONE>,   cudaFuncAttributeMaxDynamicSharedMemorySize, TMMA_SMEM);
        cudaFuncSetAttribute(tmma_kernel<EPI_SILU_R>, cudaFuncAttributeMaxDynamicSharedMemorySize, TMMA_SMEM);
        cudaFuncSetAttribute(tmma_kernel<EPI_GELU_R>, cudaFuncAttributeMaxDynamicSharedMemorySize, TMMA_SMEM);
        cudaFuncSetAttribute(tmma_kernel<EPI_RES>,    cudaFuncAttributeMaxDynamicSharedMemorySize, TMMA_SMEM);
        attr_set = 1;
    }

    // 0) pre-round weights to tf32
    const int RB = 256;
    round_kernel<<<(DIMD * DIMD / 4 + RB - 1) / RB, RB>>>(q_w,   wq,   DIMD * DIMD / 4);
    round_kernel<<<(DIMD * DIMD / 4 + RB - 1) / RB, RB>>>(k_w,   wk,   DIMD * DIMD / 4);
    round_kernel<<<(DIMD * DIMD / 4 + RB - 1) / RB, RB>>>(v_w,   wv,   DIMD * DIMD / 4);
    round_kernel<<<(DIMD * DIMD / 4 + RB - 1) / RB, RB>>>(o_w,   wo,   DIMD * DIMD / 4);
    round_kernel<<<(DIMD * DIMD / 4 + RB - 1) / RB, RB>>>(ae2_w, wae2, DIMD * DIMD / 4);
    round_kernel<<<(DIMD * MLPH / 4 + RB - 1) / RB, RB>>>(m1_w,  wm1,  DIMD * MLPH / 4);
    round_kernel<<<(MLPH * DIMD / 4 + RB - 1) / RB, RB>>>(m2_w,  wm2,  MLPH * DIMD / 4);
    round_mod_kernel<<<(1024 * 512) / RB, RB>>>(mod_w, wmod);

    dim3 g1024(DIMD / BN, BT / BM);   // (8, 32)
    dim3 g2048(2048 / BN, BT / BM);   // (16, 32)
    dim3 g4096(MLPH / BN, BT / BM);   // (32, 32)

    // 1) h = rmsnorm(x, n1_w)  (tf32-rounded)
    rmsnorm_kernel<<<BT, 256>>>(x, n1_w, h);
    // 2) q,k,v projections (tensor core)
    tmma_kernel<EPI_NONE><<<g1024, 256, TMMA_SMEM>>>(h, wq, q_b, nullptr, q, BT, DIMD, DIMD);
    tmma_kernel<EPI_NONE><<<g1024, 256, TMMA_SMEM>>>(h, wk, k_b, nullptr, k, BT, DIMD, DIMD);
    tmma_kernel<EPI_NONE><<<g1024, 256, TMMA_SMEM>>>(h, wv, v_b, nullptr, v, BT, DIMD, DIMD);
    // 3) per-head RMSNorm of q,k
    headnorm_kernel<<<(BT * NH) / 8, 256>>>(q, qn_w);
    headnorm_kernel<<<(BT * NH) / 8, 256>>>(k, kn_w);
    // 4) causal attention (output tf32-rounded)
    attn_kernel<<<dim3(TT / 64, 2 * NH), 256, ATTN_SMEM>>>(q, k, v, ao);
    // 5) x1 = x + ao @ wo + o_b
    tmma_kernel<EPI_RES><<<g1024, 256, TMMA_SMEM>>>(ao, wo, o_b, x, x1, BT, DIMD, DIMD);
    // 6) h = silu(actions @ ae1_w + ae1_b)   (K=16, fp32, rounded out)
    ae1_kernel<<<BT / 64, 256>>>(actions, ae1_w, ae1_b, h);
    // 7) ae = silu(h @ wae2 + ae2_b)  (rounded)
    tmma_kernel<EPI_SILU_R><<<g1024, 256, TMMA_SMEM>>>(h, wae2, ae2_b, nullptr, ae, BT, DIMD, DIMD);
    // 8) mod = ae @ wmod + mod_b[:2048]
    tmma_kernel<EPI_NONE><<<g2048, 256, TMMA_SMEM>>>(ae, wmod, mod_b, nullptr, mod, BT, 2048, DIMD);
    // 9) x1 = x1*(1+scale1)+shift1
    modulate_kernel<<<(BT * DIMD) / 256, 256>>>(x1, mod);
    // 10) h = rmsnorm(x1, n2_w)  (rounded)
    rmsnorm_kernel<<<BT, 256>>>(x1, n2_w, h);
    // 11) hid = gelu(h @ wm1 + m1_b)  (rounded)
    tmma_kernel<EPI_GELU_R><<<g4096, 256, TMMA_SMEM>>>(h, wm1, m1_b, nullptr, hid, BT, MLPH, DIMD);
    // 12) out = x1 + hid @ wm2 + m2_b
    tmma_kernel<EPI_RES><<<g1024, 256, TMMA_SMEM>>>(hid, wm2, m2_b, x1, out, BT, DIMD, MLPH);
}

// round 4
// speedup vs baseline: 2.2341x; 1.2438x over previous
#include <cuda_runtime.h>
#include <math.h>
#include <stdint.h>

#define BT    4096
#define DIMD  1024
#define NH    16
#define HD    64
#define TT    2048
#define MLPH  4096

// ---------------- scratch -------------------------------------------------------
__device__ float g_h  [BT * DIMD];
__device__ float g_q  [BT * DIMD];
__device__ float g_k  [BT * DIMD];
__device__ float g_v  [BT * DIMD];
__device__ float g_ao [BT * DIMD];
__device__ float g_ae [BT * DIMD];
__device__ float g_x1 [BT * DIMD];
__device__ float g_mod[BT * 2048];
__device__ float g_hid[BT * MLPH];
// tf32-rounded weights (K-major as produced by round 2 layout: [K][N] row-major)
__device__ float g_wq  [DIMD * DIMD];
__device__ float g_wk  [DIMD * DIMD];
__device__ float g_wv  [DIMD * DIMD];
__device__ float g_wo  [DIMD * DIMD];
__device__ float g_wae2[DIMD * DIMD];
__device__ float g_wmod[DIMD * 2048];
__device__ float g_wm1 [DIMD * MLPH];
__device__ float g_wm2 [MLPH * DIMD];

__device__ __forceinline__ float tf32r(float x) {
    uint32_t o;
    asm("cvt.rna.tf32.f32 %0, %1;" : "=r"(o) : "f"(x));
    return __uint_as_float(o);
}

// ---------------- weight rounding ------------------------------------------------
__global__ void round_kernel(const float* __restrict__ src, float* __restrict__ dst, int n4)
{
    int i = blockIdx.x * 256 + threadIdx.x;
    if (i >= n4) return;
    float4 v = ((const float4*)src)[i];
    v.x = tf32r(v.x); v.y = tf32r(v.y); v.z = tf32r(v.z); v.w = tf32r(v.w);
    ((float4*)dst)[i] = v;
}

__global__ void round_mod_kernel(const float* __restrict__ src, float* __restrict__ dst)
{
    int i = blockIdx.x * 256 + threadIdx.x;
    int row = i >> 9;
    int c4  = (i & 511) << 2;
    float4 v = *(const float4*)(src + (size_t)row * 4096 + c4);
    v.x = tf32r(v.x); v.y = tf32r(v.y); v.z = tf32r(v.z); v.w = tf32r(v.w);
    *(float4*)(dst + (size_t)row * 2048 + c4) = v;
}

// ---------------- rmsnorm (tf32-rounded out) --------------------------------------
__global__ void rmsnorm_kernel(const float* __restrict__ x,
                               const float* __restrict__ w,
                               float* __restrict__ y)
{
    int row = blockIdx.x;
    const float* xr = x + (size_t)row * DIMD;
    float v[4];
    float s = 0.f;
#pragma unroll
    for (int i = 0; i < 4; i++) {
        v[i] = xr[threadIdx.x + i * 256];
        s += v[i] * v[i];
    }
#pragma unroll
    for (int o = 16; o > 0; o >>= 1) s += __shfl_xor_sync(0xffffffffu, s, o);
    __shared__ float red[8];
    if ((threadIdx.x & 31) == 0) red[threadIdx.x >> 5] = s;
    __syncthreads();
    if (threadIdx.x == 0) {
        float t = 0.f;
#pragma unroll
        for (int i = 0; i < 8; i++) t += red[i];
        red[0] = rsqrtf(t * (1.0f / DIMD) + 1e-6f);
    }
    __syncthreads();
    float r = red[0];
    float* yr = y + (size_t)row * DIMD;
#pragma unroll
    for (int i = 0; i < 4; i++) {
        int c = threadIdx.x + i * 256;
        yr[c] = tf32r(v[i] * r * w[c]);
    }
}

// ---------------- per-head rmsnorm, scale folded, tf32-rounded --------------------
__global__ void headnorm_kernel(float* __restrict__ q, const float* __restrict__ w,
                                float scale)
{
    int gw   = (blockIdx.x * blockDim.x + threadIdx.x) >> 5;
    int lane = threadIdx.x & 31;
    if (gw >= BT * NH) return;
    float* p = q + (size_t)gw * HD;
    float a = p[lane];
    float b = p[lane + 32];
    float s = a * a + b * b;
#pragma unroll
    for (int o = 16; o > 0; o >>= 1) s += __shfl_xor_sync(0xffffffffu, s, o);
    float r = rsqrtf(s * (1.0f / HD) + 1e-6f) * scale;
    p[lane]      = tf32r(a * r * w[lane]);
    p[lane + 32] = tf32r(b * r * w[lane + 32]);
}

// ---------------- modulate --------------------------------------------------------
__global__ void modulate_kernel(float* __restrict__ x, const float* __restrict__ mod)
{
    int idx = blockIdx.x * 256 + threadIdx.x;
    int row = idx >> 10;
    int col = idx & 1023;
    float shift = mod[(size_t)row * 2048 + col];
    float scale = mod[(size_t)row * 2048 + 1024 + col];
    x[idx] = x[idx] * (1.0f + scale) + shift;
}

// ---------------- ae1 (K=16) ------------------------------------------------------
__global__ void __launch_bounds__(256) ae1_kernel(
    const float* __restrict__ A, const float* __restrict__ W,
    const float* __restrict__ bias, float* __restrict__ C)
{
    __shared__ float Ws[16 * 1024];
    __shared__ float As[64 * 16];
    int tid = threadIdx.x;
    for (int i = tid; i < 16 * 1024 / 4; i += 256)
        ((float4*)Ws)[i] = ((const float4*)W)[i];
    int brow = blockIdx.x * 64;
    for (int i = tid; i < 64 * 16 / 4; i += 256)
        ((float4*)As)[i] = *(const float4*)(A + (size_t)brow * 16 + i * 4);
    __syncthreads();
    int r = tid >> 2;
    int cb = (tid & 3) * 256;
    float a[16];
#pragma unroll
    for (int k = 0; k < 16; k++) a[k] = As[r * 16 + k];
    float* Cr = C + (size_t)(brow + r) * 1024;
    for (int cc = 0; cc < 256; cc += 4) {
        int col = cb + cc;
        float4 o = make_float4(bias[col], bias[col + 1], bias[col + 2], bias[col + 3]);
#pragma unroll
        for (int k = 0; k < 16; k++) {
            float4 wv = *(float4*)&Ws[k * 1024 + col];
            o.x += a[k] * wv.x; o.y += a[k] * wv.y;
            o.z += a[k] * wv.z; o.w += a[k] * wv.w;
        }
        o.x = tf32r(o.x / (1.f + expf(-o.x)));
        o.y = tf32r(o.y / (1.f + expf(-o.y)));
        o.z = tf32r(o.z / (1.f + expf(-o.z)));
        o.w = tf32r(o.w / (1.f + expf(-o.w)));
        *(float4*)&Cr[col] = o;
    }
}

// ---------------- tf32 tensor-core GEMM 128x128x32 (round-2, known good) ----------
#define EPI_NONE   0
#define EPI_SILU_R 1
#define EPI_GELU_R 2
#define EPI_RES    3

#define BM 128
#define BN 128
#define BK 32
#define ASTR 36
#define BSTR 136
#define TMMA_SMEM ((2 * BM * ASTR + 2 * BK * BSTR) * 4)

__device__ __forceinline__ void cp16(float* s, const float* g)
{
    uint32_t sa = (uint32_t)__cvta_generic_to_shared(s);
    asm volatile("cp.async.cg.shared.global [%0], [%1], 16;\n" :: "r"(sa), "l"(g));
}

__device__ __forceinline__ void mma_tf32(float* c, const uint32_t* a, const uint32_t* b)
{
    asm volatile(
        "mma.sync.aligned.m16n8k8.row.col.f32.tf32.tf32.f32 "
        "{%0,%1,%2,%3},{%4,%5,%6,%7},{%8,%9},{%0,%1,%2,%3};"
        : "+f"(c[0]), "+f"(c[1]), "+f"(c[2]), "+f"(c[3])
        : "r"(a[0]), "r"(a[1]), "r"(a[2]), "r"(a[3]), "r"(b[0]), "r"(b[1]));
}

template<int EPI>
__global__ void __launch_bounds__(256, 2) tmma_kernel(
    const float* __restrict__ A, const float* __restrict__ W,
    const float* __restrict__ bias, const float* __restrict__ Res,
    float* __restrict__ C, int M, int N, int K)
{
    extern __shared__ float sm[];
    float* Asm = sm;
    float* Bsm = sm + 2 * BM * ASTR;

    int tid  = threadIdx.x;
    int brow = blockIdx.y * BM;
    int bcol = blockIdx.x * BN;
    int warp = tid >> 5, lane = tid & 31;
    int g = lane >> 2, t = lane & 3;
    int wr = warp & 1, wc = warp >> 1;

    int ar = tid >> 1, ak = (tid & 1) << 4;
    int bk = tid >> 3, bn = (tid & 7) << 4;
    const float* Ag = A + (size_t)(brow + ar) * K + ak;
    const float* Wg = W + (size_t)bk * N + bcol + bn;

    float acc[4][4][4];
#pragma unroll
    for (int i = 0; i < 4; i++)
#pragma unroll
        for (int j = 0; j < 4; j++)
#pragma unroll
            for (int c = 0; c < 4; c++) acc[i][j][c] = 0.f;

    int nk = K / BK;

    {
        float* Ab = Asm; float* Bb = Bsm;
#pragma unroll
        for (int j = 0; j < 4; j++) cp16(Ab + ar * ASTR + ak + j * 4, Ag + j * 4);
#pragma unroll
        for (int j = 0; j < 4; j++) cp16(Bb + bk * BSTR + bn + j * 4, Wg + j * 4);
        asm volatile("cp.async.commit_group;");
    }

    for (int i = 0; i < nk; i++) {
        int buf = i & 1;
        if (i + 1 < nk) {
            int kc = (i + 1) * BK;
            float* Ab = Asm + (buf ^ 1) * BM * ASTR;
            float* Bb = Bsm + (buf ^ 1) * BK * BSTR;
#pragma unroll
            for (int j = 0; j < 4; j++) cp16(Ab + ar * ASTR + ak + j * 4, Ag + kc + j * 4);
#pragma unroll
            for (int j = 0; j < 4; j++) cp16(Bb + bk * BSTR + bn + j * 4, Wg + (size_t)kc * N + j * 4);
            asm volatile("cp.async.commit_group;");
            asm volatile("cp.async.wait_group 1;");
        } else {
            asm volatile("cp.async.wait_group 0;");
        }
        __syncthreads();

        const float* Ab = Asm + buf * BM * ASTR + (wr * 64) * ASTR;
        const float* Bb = Bsm + buf * BK * BSTR + wc * 32;
#pragma unroll
        for (int ks = 0; ks < 4; ks++) {
            int k0 = ks * 8;
            uint32_t af[4][4], bf[4][2];
#pragma unroll
            for (int ti = 0; ti < 4; ti++) {
                const float* p = Ab + (ti * 16 + g) * ASTR + k0 + t;
                af[ti][0] = __float_as_uint(p[0]);
                af[ti][1] = __float_as_uint(p[8 * ASTR]);
                af[ti][2] = __float_as_uint(p[4]);
                af[ti][3] = __float_as_uint(p[8 * ASTR + 4]);
            }
#pragma unroll
            for (int tj = 0; tj < 4; tj++) {
                const float* p = Bb + (k0 + t) * BSTR + tj * 8 + g;
                bf[tj][0] = __float_as_uint(p[0]);
                bf[tj][1] = __float_as_uint(p[4 * BSTR]);
            }
#pragma unroll
            for (int ti = 0; ti < 4; ti++)
#pragma unroll
                for (int tj = 0; tj < 4; tj++)
                    mma_tf32(acc[ti][tj], af[ti], bf[tj]);
        }
        __syncthreads();
    }

#pragma unroll
    for (int ti = 0; ti < 4; ti++) {
        int r0 = brow + wr * 64 + ti * 16 + g;
#pragma unroll
        for (int tj = 0; tj < 4; tj++) {
            int c0 = bcol + wc * 32 + tj * 8 + 2 * t;
            float b0 = bias[c0], b1 = bias[c0 + 1];
#pragma unroll
            for (int half = 0; half < 2; half++) {
                int row = r0 + half * 8;
                float vx = acc[ti][tj][half * 2 + 0] + b0;
                float vy = acc[ti][tj][half * 2 + 1] + b1;
                if (EPI == EPI_SILU_R) {
                    vx = tf32r(vx / (1.f + expf(-vx)));
                    vy = tf32r(vy / (1.f + expf(-vy)));
                } else if (EPI == EPI_GELU_R) {
                    const float cst = 0.70710678118654752f;
                    vx = tf32r(0.5f * vx * (1.f + erff(vx * cst)));
                    vy = tf32r(0.5f * vy * (1.f + erff(vy * cst)));
                } else if (EPI == EPI_RES) {
                    float2 rv = *(const float2*)&Res[(size_t)row * N + c0];
                    vx += rv.x; vy += rv.y;
                }
                float2 o = make_float2(vx, vy);
                *(float2*)&C[(size_t)row * N + c0] = o;
            }
        }
    }
}

// ---------------- tensor-core flash attention (tf32 mma), 64x64 tiles -------------
// q pre-scaled by HD^-0.5 and tf32-rounded; k tf32-rounded.
#define ATSTR 76
#define ATTN_SMEM ((4 * 64 * ATSTR + 256) * 4)

__global__ void __launch_bounds__(256) attn_mma_kernel(
    const float* __restrict__ Q, const float* __restrict__ K,
    const float* __restrict__ V, float* __restrict__ O)
{
    extern __shared__ float smx[];
    float* Qs   = smx;                  // [64][ATSTR] row-major
    float* Ks   = Qs + 64 * ATSTR;      // [d][c]
    float* Vs   = Ks + 64 * ATSTR;      // [c][d]
    float* Ps   = Vs + 64 * ATSTR;      // [64][ATSTR]
    float* redM = Ps + 64 * ATSTR;      // [2][64]
    float* redL = redM + 128;           // [2][64]

    int tid = threadIdx.x, warp = tid >> 5, lane = tid & 31;
    int g = lane >> 2, t = lane & 3;
    int wr = warp & 3, wc = warp >> 2;
    int qt = (TT / 64 - 1) - blockIdx.x;     // heavy tiles first
    int bh = blockIdx.y, b = bh >> 4, h = bh & 15;

    const float* Qg = Q + (size_t)b * TT * DIMD + (size_t)h * HD;
    const float* Kg = K + (size_t)b * TT * DIMD + (size_t)h * HD;
    const float* Vg = V + (size_t)b * TT * DIMD + (size_t)h * HD;

    // loader mapping: thread -> row (tid>>2), 16-float slab ((tid&3)*16)
    int lrow = tid >> 2;
    int ld16 = (tid & 3) << 4;

    {   // load Q tile row-major
        const float* src = Qg + (size_t)(qt * 64 + lrow) * DIMD + ld16;
        float* dst = Qs + lrow * ATSTR + ld16;
#pragma unroll
        for (int p = 0; p < 4; p++)
            *(float4*)(dst + p * 4) = *(const float4*)(src + p * 4);
    }
    __syncthreads();

    // Q fragments register-resident (rows wr*16+g / +8)
    int r0 = wr * 16 + g;
    uint32_t qf[8][4];
#pragma unroll
    for (int ks = 0; ks < 8; ks++) {
        int k0 = ks * 8;
        qf[ks][0] = __float_as_uint(Qs[(r0)     * ATSTR + k0 + t]);
        qf[ks][1] = __float_as_uint(Qs[(r0 + 8) * ATSTR + k0 + t]);
        qf[ks][2] = __float_as_uint(Qs[(r0)     * ATSTR + k0 + t + 4]);
        qf[ks][3] = __float_as_uint(Qs[(r0 + 8) * ATSTR + k0 + t + 4]);
    }

    float m0 = -1e30f, m1 = -1e30f, l0 = 0.f, l1 = 0.f;
    float acc[4][4];
#pragma unroll
    for (int tj = 0; tj < 4; tj++)
#pragma unroll
        for (int c = 0; c < 4; c++) acc[tj][c] = 0.f;

    for (int kt = 0; kt <= qt; kt++) {
        __syncthreads();   // prev PV reads of Vs/Ps done
        {   // load K (transposed [d][c]) and V ([c][d], tf32-rounded)
            const float* kp = Kg + (size_t)(kt * 64 + lrow) * DIMD + ld16;
            const float* vp = Vg + (size_t)(kt * 64 + lrow) * DIMD + ld16;
#pragma unroll
            for (int p = 0; p < 4; p++) {
                float4 kv = *(const float4*)(kp + p * 4);
                int d0 = ld16 + p * 4;
                Ks[(d0 + 0) * ATSTR + lrow] = kv.x;
                Ks[(d0 + 1) * ATSTR + lrow] = kv.y;
                Ks[(d0 + 2) * ATSTR + lrow] = kv.z;
                Ks[(d0 + 3) * ATSTR + lrow] = kv.w;
                float4 vv = *(const float4*)(vp + p * 4);
                vv.x = tf32r(vv.x); vv.y = tf32r(vv.y);
                vv.z = tf32r(vv.z); vv.w = tf32r(vv.w);
                *(float4*)(Vs + lrow * ATSTR + d0) = vv;
            }
        }
        __syncthreads();

        // S = Q @ K^T
        float s[4][4];
#pragma unroll
        for (int tj = 0; tj < 4; tj++)
#pragma unroll
            for (int c = 0; c < 4; c++) s[tj][c] = 0.f;
#pragma unroll
        for (int ks = 0; ks < 8; ks++) {
            int k0 = ks * 8;
#pragma unroll
            for (int tj = 0; tj < 4; tj++) {
                uint32_t bf[2];
                int col = wc * 32 + tj * 8 + g;
                bf[0] = __float_as_uint(Ks[(k0 + t)     * ATSTR + col]);
                bf[1] = __float_as_uint(Ks[(k0 + t + 4) * ATSTR + col]);
                mma_tf32(s[tj], qf[ks], bf);
            }
        }

        // causal mask on diagonal tile (local row/col compare valid: same base)
        if (kt == qt) {
#pragma unroll
            for (int tj = 0; tj < 4; tj++) {
                int c0 = wc * 32 + tj * 8 + 2 * t;
                if (c0     > r0)     s[tj][0] = -1e30f;
                if (c0 + 1 > r0)     s[tj][1] = -1e30f;
                if (c0     > r0 + 8) s[tj][2] = -1e30f;
                if (c0 + 1 > r0 + 8) s[tj][3] = -1e30f;
            }
        }

        // row maxes (warp quad reduce, then 2-warp smem exchange)
        float rm0 = -1e30f, rm1 = -1e30f;
#pragma unroll
        for (int tj = 0; tj < 4; tj++) {
            rm0 = fmaxf(rm0, fmaxf(s[tj][0], s[tj][1]));
            rm1 = fmaxf(rm1, fmaxf(s[tj][2], s[tj][3]));
        }
#pragma unroll
        for (int o = 1; o < 4; o <<= 1) {
            rm0 = fmaxf(rm0, __shfl_xor_sync(0xffffffffu, rm0, o));
            rm1 = fmaxf(rm1, __shfl_xor_sync(0xffffffffu, rm1, o));
        }
        if (t == 0) {
            redM[wc * 64 + r0]     = rm0;
            redM[wc * 64 + r0 + 8] = rm1;
        }
        __syncthreads();
        float nm0 = fmaxf(m0, fmaxf(redM[r0],     redM[64 + r0]));
        float nm1 = fmaxf(m1, fmaxf(redM[r0 + 8], redM[64 + r0 + 8]));
        float a0 = __expf(m0 - nm0), a1 = __expf(m1 - nm1);
        m0 = nm0; m1 = nm1;

        float ls0 = 0.f, ls1 = 0.f;
#pragma unroll
        for (int tj = 0; tj < 4; tj++) {
            s[tj][0] = __expf(s[tj][0] - nm0);
            s[tj][1] = __expf(s[tj][1] - nm0);
            s[tj][2] = __expf(s[tj][2] - nm1);
            s[tj][3] = __expf(s[tj][3] - nm1);
            ls0 += s[tj][0] + s[tj][1];
            ls1 += s[tj][2] + s[tj][3];
        }
#pragma unroll
        for (int o = 1; o < 4; o <<= 1) {
            ls0 += __shfl_xor_sync(0xffffffffu, ls0, o);
            ls1 += __shfl_xor_sync(0xffffffffu, ls1, o);
        }
        if (t == 0) {
            redL[wc * 64 + r0]     = ls0;
            redL[wc * 64 + r0 + 8] = ls1;
        }
        // store P (tf32-rounded) to smem
#pragma unroll
        for (int tj = 0; tj < 4; tj++) {
            int c0 = wc * 32 + tj * 8 + 2 * t;
            float2 p01 = make_float2(tf32r(s[tj][0]), tf32r(s[tj][1]));
            float2 p23 = make_float2(tf32r(s[tj][2]), tf32r(s[tj][3]));
            *(float2*)&Ps[(r0)     * ATSTR + c0] = p01;
            *(float2*)&Ps[(r0 + 8) * ATSTR + c0] = p23;
        }
        __syncthreads();

        l0 = l0 * a0 + redL[r0]     + redL[64 + r0];
        l1 = l1 * a1 + redL[r0 + 8] + redL[64 + r0 + 8];
#pragma unroll
        for (int tj = 0; tj < 4; tj++) {
            acc[tj][0] *= a0; acc[tj][1] *= a0;
            acc[tj][2] *= a1; acc[tj][3] *= a1;
        }

        // O += P @ V
#pragma unroll
        for (int ks = 0; ks < 8; ks++) {
            int k0 = ks * 8;
            uint32_t pf[4];
            pf[0] = __float_as_uint(Ps[(r0)     * ATSTR + k0 + t]);
            pf[1] = __float_as_uint(Ps[(r0 + 8) * ATSTR + k0 + t]);
            pf[2] = __float_as_uint(Ps[(r0)     * ATSTR + k0 + t + 4]);
            pf[3] = __float_as_uint(Ps[(r0 + 8) * ATSTR + k0 + t + 4]);
#pragma unroll
            for (int tj = 0; tj < 4; tj++) {
                uint32_t bf[2];
                int col = wc * 32 + tj * 8 + g;
                bf[0] = __float_as_uint(Vs[(k0 + t)     * ATSTR + col]);
                bf[1] = __float_as_uint(Vs[(k0 + t + 4) * ATSTR + col]);
                mma_tf32(acc[tj], pf, bf);
            }
        }
    }

    float inv0 = 1.f / l0, inv1 = 1.f / l1;
    float* Og = O + (size_t)b * TT * DIMD + (size_t)(qt * 64) * DIMD + (size_t)h * HD;
#pragma unroll
    for (int tj = 0; tj < 4; tj++) {
        int c0 = wc * 32 + tj * 8 + 2 * t;
        float2 o01 = make_float2(tf32r(acc[tj][0] * inv0), tf32r(acc[tj][1] * inv0));
        float2 o23 = make_float2(tf32r(acc[tj][2] * inv1), tf32r(acc[tj][3] * inv1));
        *(float2*)&Og[(size_t)(r0)     * DIMD + c0] = o01;
        *(float2*)&Og[(size_t)(r0 + 8) * DIMD + c0] = o23;
    }
}

// ------------------------------- launch --------------------------------------------
extern "C" void kernel_launch(void* const* d_in, const int* in_sizes, int n_in,
                              void* d_out, int out_size)
{
    const float* x       = (const float*)d_in[0];
    const float* actions = (const float*)d_in[1];
    const float* n1_w    = (const float*)d_in[2];
    const float* n2_w    = (const float*)d_in[3];
    const float* q_w     = (const float*)d_in[4];
    const float* q_b     = (const float*)d_in[5];
    const float* k_w     = (const float*)d_in[6];
    const float* k_b     = (const float*)d_in[7];
    const float* v_w     = (const float*)d_in[8];
    const float* v_b     = (const float*)d_in[9];
    const float* qn_w    = (const float*)d_in[10];
    const float* kn_w    = (const float*)d_in[11];
    const float* o_w     = (const float*)d_in[12];
    const float* o_b     = (const float*)d_in[13];
    const float* ae1_w   = (const float*)d_in[14];
    const float* ae1_b   = (const float*)d_in[15];
    const float* ae2_w   = (const float*)d_in[16];
    const float* ae2_b   = (const float*)d_in[17];
    const float* mod_w   = (const float*)d_in[18];
    const float* mod_b   = (const float*)d_in[19];
    const float* m1_w    = (const float*)d_in[20];
    const float* m1_b    = (const float*)d_in[21];
    const float* m2_w    = (const float*)d_in[22];
    const float* m2_b    = (const float*)d_in[23];
    float* out           = (float*)d_out;

    float *h, *q, *k, *v, *ao, *ae, *x1, *mod, *hid;
    float *wq, *wk, *wv, *wo, *wae2, *wmod, *wm1, *wm2;
    cudaGetSymbolAddress((void**)&h,    g_h);
    cudaGetSymbolAddress((void**)&q,    g_q);
    cudaGetSymbolAddress((void**)&k,    g_k);
    cudaGetSymbolAddress((void**)&v,    g_v);
    cudaGetSymbolAddress((void**)&ao,   g_ao);
    cudaGetSymbolAddress((void**)&ae,   g_ae);
    cudaGetSymbolAddress((void**)&x1,   g_x1);
    cudaGetSymbolAddress((void**)&mod,  g_mod);
    cudaGetSymbolAddress((void**)&hid,  g_hid);
    cudaGetSymbolAddress((void**)&wq,   g_wq);
    cudaGetSymbolAddress((void**)&wk,   g_wk);
    cudaGetSymbolAddress((void**)&wv,   g_wv);
    cudaGetSymbolAddress((void**)&wo,   g_wo);
    cudaGetSymbolAddress((void**)&wae2, g_wae2);
    cudaGetSymbolAddress((void**)&wmod, g_wmod);
    cudaGetSymbolAddress((void**)&wm1,  g_wm1);
    cudaGetSymbolAddress((void**)&wm2,  g_wm2);

    static int attr_set = 0;
    if (!attr_set) {
        cudaFuncSetAttribute(attn_mma_kernel, cudaFuncAttributeMaxDynamicSharedMemorySize, ATTN_SMEM);
        cudaFuncSetAttribute(tmma_kernel<EPI_NONE>,   cudaFuncAttributeMaxDynamicSharedMemorySize, TMMA_SMEM);
        cudaFuncSetAttribute(tmma_kernel<EPI_SILU_R>, cudaFuncAttributeMaxDynamicSharedMemorySize, TMMA_SMEM);
        cudaFuncSetAttribute(tmma_kernel<EPI_GELU_R>, cudaFuncAttributeMaxDynamicSharedMemorySize, TMMA_SMEM);
        cudaFuncSetAttribute(tmma_kernel<EPI_RES>,    cudaFuncAttributeMaxDynamicSharedMemorySize, TMMA_SMEM);
        attr_set = 1;
    }

    // 0) pre-round weights to tf32 ([K][N] layout, as in round 2)
    const int RB = 256;
    round_kernel<<<(DIMD * DIMD / 4 + RB - 1) / RB, RB>>>(q_w,   wq,   DIMD * DIMD / 4);
    round_kernel<<<(DIMD * DIMD / 4 + RB - 1) / RB, RB>>>(k_w,   wk,   DIMD * DIMD / 4);
    round_kernel<<<(DIMD * DIMD / 4 + RB - 1) / RB, RB>>>(v_w,   wv,   DIMD * DIMD / 4);
    round_kernel<<<(DIMD * DIMD / 4 + RB - 1) / RB, RB>>>(o_w,   wo,   DIMD * DIMD / 4);
    round_kernel<<<(DIMD * DIMD / 4 + RB - 1) / RB, RB>>>(ae2_w, wae2, DIMD * DIMD / 4);
    round_kernel<<<(DIMD * MLPH / 4 + RB - 1) / RB, RB>>>(m1_w,  wm1,  DIMD * MLPH / 4);
    round_kernel<<<(MLPH * DIMD / 4 + RB - 1) / RB, RB>>>(m2_w,  wm2,  MLPH * DIMD / 4);
    round_mod_kernel<<<(1024 * 512) / RB, RB>>>(mod_w, wmod);

    dim3 g1024(DIMD / BN, BT / BM);
    dim3 g2048(2048 / BN, BT / BM);
    dim3 g4096(MLPH / BN, BT / BM);

    // 1) h = rmsnorm(x, n1_w)
    rmsnorm_kernel<<<BT, 256>>>(x, n1_w, h);
    // 2) q,k,v projections
    tmma_kernel<EPI_NONE><<<g1024, 256, TMMA_SMEM>>>(h, wq, q_b, nullptr, q, BT, DIMD, DIMD);
    tmma_kernel<EPI_NONE><<<g1024, 256, TMMA_SMEM>>>(h, wk, k_b, nullptr, k, BT, DIMD, DIMD);
    tmma_kernel<EPI_NONE><<<g1024, 256, TMMA_SMEM>>>(h, wv, v_b, nullptr, v, BT, DIMD, DIMD);
    // 3) QK head norms (scale folded into q; outputs tf32-rounded)
    headnorm_kernel<<<(BT * NH) / 8, 256>>>(q, qn_w, 0.125f);
    headnorm_kernel<<<(BT * NH) / 8, 256>>>(k, kn_w, 1.0f);
    // 4) attention (tensor core)
    attn_mma_kernel<<<dim3(TT / 64, 2 * NH), 256, ATTN_SMEM>>>(q, k, v, ao);
    // 5) x1 = x + ao @ o_w + o_b
    tmma_kernel<EPI_RES><<<g1024, 256, TMMA_SMEM>>>(ao, wo, o_b, x, x1, BT, DIMD, DIMD);
    // 6) h = silu(actions @ ae1_w + ae1_b)
    ae1_kernel<<<BT / 64, 256>>>(actions, ae1_w, ae1_b, h);
    // 7) ae = silu(h @ ae2_w + ae2_b)
    tmma_kernel<EPI_SILU_R><<<g1024, 256, TMMA_SMEM>>>(h, wae2, ae2_b, nullptr, ae, BT, DIMD, DIMD);
    // 8) mod = ae @ mod_w[:, :2048] + mod_b[:2048]
    tmma_kernel<EPI_NONE><<<g2048, 256, TMMA_SMEM>>>(ae, wmod, mod_b, nullptr, mod, BT, 2048, DIMD);
    // 9) modulate
    modulate_kernel<<<(BT * DIMD) / 256, 256>>>(x1, mod);
    // 10) h = rmsnorm(x1, n2_w)
    rmsnorm_kernel<<<BT, 256>>>(x1, n2_w, h);
    // 11) hid = gelu(h @ m1_w + m1_b)
    tmma_kernel<EPI_GELU_R><<<g4096, 256, TMMA_SMEM>>>(h, wm1, m1_b, nullptr, hid, BT, MLPH, DIMD);
    // 12) out = x1 + hid @ m2_w + m2_b
    tmma_kernel<EPI_RES><<<g1024, 256, TMMA_SMEM>>>(hid, wm2, m2_b, x1, out, BT, DIMD, MLPH);
}

// round 5
// speedup vs baseline: 4.3218x; 1.9344x over previous
#include <cuda_runtime.h>
#include <cuda_fp16.h>
#include <math.h>
#include <stdint.h>

#define BT    4096
#define DIMD  1024
#define NH    16
#define HD    64
#define TT    2048
#define MLPH  4096

// ---------------- scratch -------------------------------------------------------
__device__ __half g_h  [BT * DIMD];
__device__ __half g_q  [BT * DIMD];
__device__ __half g_k  [BT * DIMD];
__device__ __half g_v  [BT * DIMD];
__device__ __half g_ao [BT * DIMD];
__device__ __half g_ae [BT * DIMD];
__device__ __half g_hid[BT * MLPH];
__device__ float  g_x1 [BT * DIMD];
__device__ float  g_mod[BT * 2048];
// transposed ([N][K]) fp16 weights
__device__ __half g_wq  [DIMD * DIMD];
__device__ __half g_wk  [DIMD * DIMD];
__device__ __half g_wv  [DIMD * DIMD];
__device__ __half g_wo  [DIMD * DIMD];
__device__ __half g_wae2[DIMD * DIMD];
__device__ __half g_wmod[2048 * DIMD];
__device__ __half g_wm1 [MLPH * DIMD];
__device__ __half g_wm2 [DIMD * MLPH];

// ---------------- weight transpose + fp16 round: dst[n][k] = h(src[k][n]) -------
__global__ void tr_half_kernel(const float* __restrict__ src, __half* __restrict__ dst,
                               int ldsrc, int K)
{
    __shared__ float t[32][33];
    int n0 = blockIdx.x * 32, k0 = blockIdx.y * 32;
    int tx = threadIdx.x, ty = threadIdx.y;
#pragma unroll
    for (int i = ty; i < 32; i += 8)
        t[i][tx] = src[(size_t)(k0 + i) * ldsrc + n0 + tx];
    __syncthreads();
#pragma unroll
    for (int i = ty; i < 32; i += 8)
        dst[(size_t)(n0 + i) * K + k0 + tx] = __float2half_rn(t[tx][i]);
}

// ---------------- rmsnorm: float in -> half out ----------------------------------
__global__ void rmsnorm_kernel(const float* __restrict__ x,
                               const float* __restrict__ w,
                               __half* __restrict__ y)
{
    int row = blockIdx.x;
    const float* xr = x + (size_t)row * DIMD;
    float v[4];
    float s = 0.f;
#pragma unroll
    for (int i = 0; i < 4; i++) {
        v[i] = xr[threadIdx.x + i * 256];
        s += v[i] * v[i];
    }
#pragma unroll
    for (int o = 16; o > 0; o >>= 1) s += __shfl_xor_sync(0xffffffffu, s, o);
    __shared__ float red[8];
    if ((threadIdx.x & 31) == 0) red[threadIdx.x >> 5] = s;
    __syncthreads();
    if (threadIdx.x == 0) {
        float t = 0.f;
#pragma unroll
        for (int i = 0; i < 8; i++) t += red[i];
        red[0] = rsqrtf(t * (1.0f / DIMD) + 1e-6f);
    }
    __syncthreads();
    float r = red[0];
    __half* yr = y + (size_t)row * DIMD;
#pragma unroll
    for (int i = 0; i < 4; i++) {
        int c = threadIdx.x + i * 256;
        yr[c] = __float2half_rn(v[i] * r * w[c]);
    }
}

// ---------------- per-head rmsnorm on half, scale folded --------------------------
__global__ void headnorm_kernel(__half* __restrict__ q, const float* __restrict__ w,
                                float scale)
{
    int gw   = (blockIdx.x * blockDim.x + threadIdx.x) >> 5;
    int lane = threadIdx.x & 31;
    if (gw >= BT * NH) return;
    __half* p = q + (size_t)gw * HD;
    float a = __half2float(p[lane]);
    float b = __half2float(p[lane + 32]);
    float s = a * a + b * b;
#pragma unroll
    for (int o = 16; o > 0; o >>= 1) s += __shfl_xor_sync(0xffffffffu, s, o);
    float r = rsqrtf(s * (1.0f / HD) + 1e-6f) * scale;
    p[lane]      = __float2half_rn(a * r * w[lane]);
    p[lane + 32] = __float2half_rn(b * r * w[lane + 32]);
}

// ---------------- modulate (fp32) --------------------------------------------------
__global__ void modulate_kernel(float* __restrict__ x, const float* __restrict__ mod)
{
    int idx = blockIdx.x * 256 + threadIdx.x;
    int row = idx >> 10;
    int col = idx & 1023;
    float shift = mod[(size_t)row * 2048 + col];
    float scale = mod[(size_t)row * 2048 + 1024 + col];
    x[idx] = x[idx] * (1.0f + scale) + shift;
}

// ---------------- ae1 (K=16), fp32 compute, half out -------------------------------
__global__ void __launch_bounds__(256) ae1_kernel(
    const float* __restrict__ A, const float* __restrict__ W,
    const float* __restrict__ bias, __half* __restrict__ C)
{
    __shared__ float Ws[16 * 1024];
    __shared__ float As[64 * 16];
    int tid = threadIdx.x;
    for (int i = tid; i < 16 * 1024 / 4; i += 256)
        ((float4*)Ws)[i] = ((const float4*)W)[i];
    int brow = blockIdx.x * 64;
    for (int i = tid; i < 64 * 16 / 4; i += 256)
        ((float4*)As)[i] = *(const float4*)(A + (size_t)brow * 16 + i * 4);
    __syncthreads();
    int r = tid >> 2;
    int cb = (tid & 3) * 256;
    float a[16];
#pragma unroll
    for (int k = 0; k < 16; k++) a[k] = As[r * 16 + k];
    __half* Cr = C + (size_t)(brow + r) * 1024;
    for (int cc = 0; cc < 256; cc += 4) {
        int col = cb + cc;
        float4 o = make_float4(bias[col], bias[col + 1], bias[col + 2], bias[col + 3]);
#pragma unroll
        for (int k = 0; k < 16; k++) {
            float4 wv = *(float4*)&Ws[k * 1024 + col];
            o.x += a[k] * wv.x; o.y += a[k] * wv.y;
            o.z += a[k] * wv.z; o.w += a[k] * wv.w;
        }
        o.x = o.x / (1.f + expf(-o.x));
        o.y = o.y / (1.f + expf(-o.y));
        o.z = o.z / (1.f + expf(-o.z));
        o.w = o.w / (1.f + expf(-o.w));
        __half2 h01 = __floats2half2_rn(o.x, o.y);
        __half2 h23 = __floats2half2_rn(o.z, o.w);
        *(__half2*)&Cr[col]     = h01;
        *(__half2*)&Cr[col + 2] = h23;
    }
}

// ================= fp16 tensor-core GEMM 128x128x32 ===============================
// C[M,N] = A[M,K] @ Wt[N,K]^T + bias (+epilogue). fp32 accumulate.
#define EPI_NONE 0
#define EPI_SILU 1
#define EPI_GELU 2
#define EPI_RES  3

#define GBM 128
#define GBK 32          // halves
#define GSTR 40         // halves per row

__device__ __forceinline__ void cp16h(__half* s, const __half* g)
{
    uint32_t sa = (uint32_t)__cvta_generic_to_shared(s);
    asm volatile("cp.async.cg.shared.global [%0], [%1], 16;\n" :: "r"(sa), "l"(g));
}

__device__ __forceinline__ void mma_f16(float* c, const uint32_t* a, const uint32_t* b)
{
    asm volatile(
        "mma.sync.aligned.m16n8k16.row.col.f32.f16.f16.f32 "
        "{%0,%1,%2,%3},{%4,%5,%6,%7},{%8,%9},{%0,%1,%2,%3};"
        : "+f"(c[0]), "+f"(c[1]), "+f"(c[2]), "+f"(c[3])
        : "r"(a[0]), "r"(a[1]), "r"(a[2]), "r"(a[3]), "r"(b[0]), "r"(b[1]));
}

template<int EPI, int HOUT>
__global__ void __launch_bounds__(256, 2) hmma_kernel(
    const __half* __restrict__ A, const __half* __restrict__ Wt,
    const float* __restrict__ bias, const float* __restrict__ Res,
    void* __restrict__ Cv, int M, int N, int K)
{
    __shared__ __half Asm[2][GBM * GSTR];
    __shared__ __half Bsm[2][GBM * GSTR];

    int tid  = threadIdx.x;
    int brow = blockIdx.y * GBM;
    int bcol = blockIdx.x * GBM;
    int warp = tid >> 5, lane = tid & 31;
    int g = lane >> 2, t = lane & 31 & 3;
    int wr = warp & 1, wc = warp >> 1;

    // loader: unit u -> row u>>2, col8 (u&3)*8 halves; units tid and tid+256
    int r0u = tid >> 2,        c0u = (tid & 3) << 3;
    int r1u = (tid >> 2) + 64, c1u = c0u;
    const __half* Ag0 = A  + (size_t)(brow + r0u) * K + c0u;
    const __half* Ag1 = A  + (size_t)(brow + r1u) * K + c1u;
    const __half* Bg0 = Wt + (size_t)(bcol + r0u) * K + c0u;
    const __half* Bg1 = Wt + (size_t)(bcol + r1u) * K + c1u;

    float acc[4][4][4];
#pragma unroll
    for (int i = 0; i < 4; i++)
#pragma unroll
        for (int j = 0; j < 4; j++)
#pragma unroll
            for (int c = 0; c < 4; c++) acc[i][j][c] = 0.f;

    int nk = K / GBK;

    {
        cp16h(&Asm[0][r0u * GSTR + c0u], Ag0);
        cp16h(&Asm[0][r1u * GSTR + c1u], Ag1);
        cp16h(&Bsm[0][r0u * GSTR + c0u], Bg0);
        cp16h(&Bsm[0][r1u * GSTR + c1u], Bg1);
        asm volatile("cp.async.commit_group;");
    }

    for (int i = 0; i < nk; i++) {
        int buf = i & 1;
        if (i + 1 < nk) {
            int kc = (i + 1) * GBK;
            cp16h(&Asm[buf ^ 1][r0u * GSTR + c0u], Ag0 + kc);
            cp16h(&Asm[buf ^ 1][r1u * GSTR + c1u], Ag1 + kc);
            cp16h(&Bsm[buf ^ 1][r0u * GSTR + c0u], Bg0 + kc);
            cp16h(&Bsm[buf ^ 1][r1u * GSTR + c1u], Bg1 + kc);
            asm volatile("cp.async.commit_group;");
            asm volatile("cp.async.wait_group 1;");
        } else {
            asm volatile("cp.async.wait_group 0;");
        }
        __syncthreads();

        const __half* Ab = &Asm[buf][(wr * 64) * GSTR];
        const __half* Bb = &Bsm[buf][(wc * 32) * GSTR];
#pragma unroll
        for (int ks = 0; ks < 2; ks++) {
            int k0 = ks * 16;
            uint32_t af[4][4], bf[4][2];
#pragma unroll
            for (int ti = 0; ti < 4; ti++) {
                const __half* p = Ab + (ti * 16 + g) * GSTR + k0 + 2 * t;
                af[ti][0] = *(const uint32_t*)(p);
                af[ti][1] = *(const uint32_t*)(p + 8 * GSTR);
                af[ti][2] = *(const uint32_t*)(p + 8);
                af[ti][3] = *(const uint32_t*)(p + 8 * GSTR + 8);
            }
#pragma unroll
            for (int tj = 0; tj < 4; tj++) {
                const __half* p = Bb + (tj * 8 + g) * GSTR + k0 + 2 * t;
                bf[tj][0] = *(const uint32_t*)(p);
                bf[tj][1] = *(const uint32_t*)(p + 8);
            }
#pragma unroll
            for (int ti = 0; ti < 4; ti++)
#pragma unroll
                for (int tj = 0; tj < 4; tj++)
                    mma_f16(acc[ti][tj], af[ti], bf[tj]);
        }
        __syncthreads();
    }

    // epilogue
#pragma unroll
    for (int ti = 0; ti < 4; ti++) {
        int r0 = brow + wr * 64 + ti * 16 + g;
#pragma unroll
        for (int tj = 0; tj < 4; tj++) {
            int c0 = bcol + wc * 32 + tj * 8 + 2 * t;
            float b0 = bias[c0], b1 = bias[c0 + 1];
#pragma unroll
            for (int half_i = 0; half_i < 2; half_i++) {
                int row = r0 + half_i * 8;
                float vx = acc[ti][tj][half_i * 2 + 0] + b0;
                float vy = acc[ti][tj][half_i * 2 + 1] + b1;
                if (EPI == EPI_SILU) {
                    vx = vx / (1.f + expf(-vx));
                    vy = vy / (1.f + expf(-vy));
                } else if (EPI == EPI_GELU) {
                    const float cst = 0.70710678118654752f;
                    vx = 0.5f * vx * (1.f + erff(vx * cst));
                    vy = 0.5f * vy * (1.f + erff(vy * cst));
                } else if (EPI == EPI_RES) {
                    float2 rv = *(const float2*)&Res[(size_t)row * N + c0];
                    vx += rv.x; vy += rv.y;
                }
                if (HOUT) {
                    __half2 hv = __floats2half2_rn(vx, vy);
                    *(__half2*)((__half*)Cv + (size_t)row * N + c0) = hv;
                } else {
                    *(float2*)((float*)Cv + (size_t)row * N + c0) = make_float2(vx, vy);
                }
            }
        }
    }
}

// ---------------- fp16 tensor-core flash attention, 64x64 tiles --------------------
#define AST 72   // halves per row

__global__ void __launch_bounds__(256) attn_mma_kernel(
    const __half* __restrict__ Q, const __half* __restrict__ K,
    const __half* __restrict__ V, __half* __restrict__ O)
{
    __shared__ __half Qs[64 * AST];
    __shared__ __half Ks[64 * AST];   // natural [c][d]
    __shared__ __half Vt[64 * AST];   // transposed [d][c]
    __shared__ __half Ps[64 * AST];
    __shared__ float  redM[128], redL[128];

    int tid = threadIdx.x, warp = tid >> 5, lane = tid & 31;
    int g = lane >> 2, t = lane & 3;
    int wr = warp & 3, wc = warp >> 2;
    int qt = (TT / 64 - 1) - blockIdx.x;
    int bh = blockIdx.y, b = bh >> 4, h = bh & 15;

    const __half* Qg = Q + (size_t)b * TT * DIMD + (size_t)h * HD;
    const __half* Kg = K + (size_t)b * TT * DIMD + (size_t)h * HD;
    const __half* Vg = V + (size_t)b * TT * DIMD + (size_t)h * HD;

    int lrow = tid >> 2;            // token row within tile
    int ld16 = (tid & 3) << 4;      // d base (16 halves)

    {   // Q tile: direct copy (row-major [r][d])
        const __half* src = Qg + (size_t)(qt * 64 + lrow) * DIMD + ld16;
        *(uint4*)&Qs[lrow * AST + ld16]     = *(const uint4*)(src);
        *(uint4*)&Qs[lrow * AST + ld16 + 8] = *(const uint4*)(src + 8);
    }
    __syncthreads();

    int r0 = wr * 16 + g;
    uint32_t qf[4][4];
#pragma unroll
    for (int ks = 0; ks < 4; ks++) {
        int k0 = ks * 16;
        qf[ks][0] = *(const uint32_t*)&Qs[(r0)     * AST + k0 + 2 * t];
        qf[ks][1] = *(const uint32_t*)&Qs[(r0 + 8) * AST + k0 + 2 * t];
        qf[ks][2] = *(const uint32_t*)&Qs[(r0)     * AST + k0 + 2 * t + 8];
        qf[ks][3] = *(const uint32_t*)&Qs[(r0 + 8) * AST + k0 + 2 * t + 8];
    }

    float m0 = -1e30f, m1 = -1e30f, l0 = 0.f, l1 = 0.f;
    float acc[4][4];
#pragma unroll
    for (int tj = 0; tj < 4; tj++)
#pragma unroll
        for (int c = 0; c < 4; c++) acc[tj][c] = 0.f;

    for (int kt = 0; kt <= qt; kt++) {
        __syncthreads();
        {   // K natural copy; V transposed
            const __half* kp = Kg + (size_t)(kt * 64 + lrow) * DIMD + ld16;
            *(uint4*)&Ks[lrow * AST + ld16]     = *(const uint4*)(kp);
            *(uint4*)&Ks[lrow * AST + ld16 + 8] = *(const uint4*)(kp + 8);
            const __half* vp = Vg + (size_t)(kt * 64 + lrow) * DIMD + ld16;
            union { uint4 u4[2]; __half hh[16]; } vv;
            vv.u4[0] = *(const uint4*)(vp);
            vv.u4[1] = *(const uint4*)(vp + 8);
#pragma unroll
            for (int j = 0; j < 16; j++)
                Vt[(ld16 + j) * AST + lrow] = vv.hh[j];
        }
        __syncthreads();

        // S = Q @ K^T
        float s[4][4];
#pragma unroll
        for (int tj = 0; tj < 4; tj++)
#pragma unroll
            for (int c = 0; c < 4; c++) s[tj][c] = 0.f;
#pragma unroll
        for (int ks = 0; ks < 4; ks++) {
            int k0 = ks * 16;
#pragma unroll
            for (int tj = 0; tj < 4; tj++) {
                int col = wc * 32 + tj * 8 + g;
                uint32_t bf[2];
                bf[0] = *(const uint32_t*)&Ks[col * AST + k0 + 2 * t];
                bf[1] = *(const uint32_t*)&Ks[col * AST + k0 + 2 * t + 8];
                mma_f16(s[tj], qf[ks], bf);
            }
        }

        if (kt == qt) {
#pragma unroll
            for (int tj = 0; tj < 4; tj++) {
                int c0 = wc * 32 + tj * 8 + 2 * t;
                if (c0     > r0)     s[tj][0] = -1e30f;
                if (c0 + 1 > r0)     s[tj][1] = -1e30f;
                if (c0     > r0 + 8) s[tj][2] = -1e30f;
                if (c0 + 1 > r0 + 8) s[tj][3] = -1e30f;
            }
        }

        float rm0 = -1e30f, rm1 = -1e30f;
#pragma unroll
        for (int tj = 0; tj < 4; tj++) {
            rm0 = fmaxf(rm0, fmaxf(s[tj][0], s[tj][1]));
            rm1 = fmaxf(rm1, fmaxf(s[tj][2], s[tj][3]));
        }
#pragma unroll
        for (int o = 1; o < 4; o <<= 1) {
            rm0 = fmaxf(rm0, __shfl_xor_sync(0xffffffffu, rm0, o));
            rm1 = fmaxf(rm1, __shfl_xor_sync(0xffffffffu, rm1, o));
        }
        if (t == 0) {
            redM[wc * 64 + r0]     = rm0;
            redM[wc * 64 + r0 + 8] = rm1;
        }
        __syncthreads();
        float nm0 = fmaxf(m0, fmaxf(redM[r0],     redM[64 + r0]));
        float nm1 = fmaxf(m1, fmaxf(redM[r0 + 8], redM[64 + r0 + 8]));
        float a0 = __expf(m0 - nm0), a1 = __expf(m1 - nm1);
        m0 = nm0; m1 = nm1;

        float ls0 = 0.f, ls1 = 0.f;
#pragma unroll
        for (int tj = 0; tj < 4; tj++) {
            s[tj][0] = __expf(s[tj][0] - nm0);
            s[tj][1] = __expf(s[tj][1] - nm0);
            s[tj][2] = __expf(s[tj][2] - nm1);
            s[tj][3] = __expf(s[tj][3] - nm1);
            ls0 += s[tj][0] + s[tj][1];
            ls1 += s[tj][2] + s[tj][3];
        }
#pragma unroll
        for (int o = 1; o < 4; o <<= 1) {
            ls0 += __shfl_xor_sync(0xffffffffu, ls0, o);
            ls1 += __shfl_xor_sync(0xffffffffu, ls1, o);
        }
        if (t == 0) {
            redL[wc * 64 + r0]     = ls0;
            redL[wc * 64 + r0 + 8] = ls1;
        }
#pragma unroll
        for (int tj = 0; tj < 4; tj++) {
            int c0 = wc * 32 + tj * 8 + 2 * t;
            *(__half2*)&Ps[(r0)     * AST + c0] = __floats2half2_rn(s[tj][0], s[tj][1]);
            *(__half2*)&Ps[(r0 + 8) * AST + c0] = __floats2half2_rn(s[tj][2], s[tj][3]);
        }
        __syncthreads();

        l0 = l0 * a0 + redL[r0]     + redL[64 + r0];
        l1 = l1 * a1 + redL[r0 + 8] + redL[64 + r0 + 8];
#pragma unroll
        for (int tj = 0; tj < 4; tj++) {
            acc[tj][0] *= a0; acc[tj][1] *= a0;
            acc[tj][2] *= a1; acc[tj][3] *= a1;
        }

        // O += P @ V   (B = Vt[n=d][k=c])
#pragma unroll
        for (int ks = 0; ks < 4; ks++) {
            int k0 = ks * 16;
            uint32_t pf[4];
            pf[0] = *(const uint32_t*)&Ps[(r0)     * AST + k0 + 2 * t];
            pf[1] = *(const uint32_t*)&Ps[(r0 + 8) * AST + k0 + 2 * t];
            pf[2] = *(const uint32_t*)&Ps[(r0)     * AST + k0 + 2 * t + 8];
            pf[3] = *(const uint32_t*)&Ps[(r0 + 8) * AST + k0 + 2 * t + 8];
#pragma unroll
            for (int tj = 0; tj < 4; tj++) {
                int col = wc * 32 + tj * 8 + g;
                uint32_t bf[2];
                bf[0] = *(const uint32_t*)&Vt[col * AST + k0 + 2 * t];
                bf[1] = *(const uint32_t*)&Vt[col * AST + k0 + 2 * t + 8];
                mma_f16(acc[tj], pf, bf);
            }
        }
    }

    float inv0 = 1.f / l0, inv1 = 1.f / l1;
    __half* Og = O + (size_t)b * TT * DIMD + (size_t)(qt * 64) * DIMD + (size_t)h * HD;
#pragma unroll
    for (int tj = 0; tj < 4; tj++) {
        int c0 = wc * 32 + tj * 8 + 2 * t;
        *(__half2*)&Og[(size_t)(r0)     * DIMD + c0] = __floats2half2_rn(acc[tj][0] * inv0, acc[tj][1] * inv0);
        *(__half2*)&Og[(size_t)(r0 + 8) * DIMD + c0] = __floats2half2_rn(acc[tj][2] * inv1, acc[tj][3] * inv1);
    }
}

// ------------------------------- launch --------------------------------------------
extern "C" void kernel_launch(void* const* d_in, const int* in_sizes, int n_in,
                              void* d_out, int out_size)
{
    const float* x       = (const float*)d_in[0];
    const float* actions = (const float*)d_in[1];
    const float* n1_w    = (const float*)d_in[2];
    const float* n2_w    = (const float*)d_in[3];
    const float* q_w     = (const float*)d_in[4];
    const float* q_b     = (const float*)d_in[5];
    const float* k_w     = (const float*)d_in[6];
    const float* k_b     = (const float*)d_in[7];
    const float* v_w     = (const float*)d_in[8];
    const float* v_b     = (const float*)d_in[9];
    const float* qn_w    = (const float*)d_in[10];
    const float* kn_w    = (const float*)d_in[11];
    const float* o_w     = (const float*)d_in[12];
    const float* o_b     = (const float*)d_in[13];
    const float* ae1_w   = (const float*)d_in[14];
    const float* ae1_b   = (const float*)d_in[15];
    const float* ae2_w   = (const float*)d_in[16];
    const float* ae2_b   = (const float*)d_in[17];
    const float* mod_w   = (const float*)d_in[18];
    const float* mod_b   = (const float*)d_in[19];
    const float* m1_w    = (const float*)d_in[20];
    const float* m1_b    = (const float*)d_in[21];
    const float* m2_w    = (const float*)d_in[22];
    const float* m2_b    = (const float*)d_in[23];
    float* out           = (float*)d_out;

    __half *h, *q, *k, *v, *ao, *ae, *hid;
    float *x1, *mod;
    __half *wq, *wk, *wv, *wo, *wae2, *wmod, *wm1, *wm2;
    cudaGetSymbolAddress((void**)&h,    g_h);
    cudaGetSymbolAddress((void**)&q,    g_q);
    cudaGetSymbolAddress((void**)&k,    g_k);
    cudaGetSymbolAddress((void**)&v,    g_v);
    cudaGetSymbolAddress((void**)&ao,   g_ao);
    cudaGetSymbolAddress((void**)&ae,   g_ae);
    cudaGetSymbolAddress((void**)&hid,  g_hid);
    cudaGetSymbolAddress((void**)&x1,   g_x1);
    cudaGetSymbolAddress((void**)&mod,  g_mod);
    cudaGetSymbolAddress((void**)&wq,   g_wq);
    cudaGetSymbolAddress((void**)&wk,   g_wk);
    cudaGetSymbolAddress((void**)&wv,   g_wv);
    cudaGetSymbolAddress((void**)&wo,   g_wo);
    cudaGetSymbolAddress((void**)&wae2, g_wae2);
    cudaGetSymbolAddress((void**)&wmod, g_wmod);
    cudaGetSymbolAddress((void**)&wm1,  g_wm1);
    cudaGetSymbolAddress((void**)&wm2,  g_wm2);

    // 0) transpose + fp16-round weights: dst[n][k] = h(src[k][n])
    dim3 tb(32, 8);
    tr_half_kernel<<<dim3(32, 32),  tb>>>(q_w,   wq,   1024, 1024);
    tr_half_kernel<<<dim3(32, 32),  tb>>>(k_w,   wk,   1024, 1024);
    tr_half_kernel<<<dim3(32, 32),  tb>>>(v_w,   wv,   1024, 1024);
    tr_half_kernel<<<dim3(32, 32),  tb>>>(o_w,   wo,   1024, 1024);
    tr_half_kernel<<<dim3(32, 32),  tb>>>(ae2_w, wae2, 1024, 1024);
    tr_half_kernel<<<dim3(64, 32),  tb>>>(mod_w, wmod, 4096, 1024);   // first 2048 cols
    tr_half_kernel<<<dim3(128, 32), tb>>>(m1_w,  wm1,  4096, 1024);
    tr_half_kernel<<<dim3(32, 128), tb>>>(m2_w,  wm2,  1024, 4096);

    dim3 g1024(8, 32);
    dim3 g2048(16, 32);
    dim3 g4096(32, 32);

    // 1) h = rmsnorm(x, n1_w) -> half
    rmsnorm_kernel<<<BT, 256>>>(x, n1_w, h);
    // 2) q,k,v projections (fp16 mma) -> half
    hmma_kernel<EPI_NONE, 1><<<g1024, 256>>>(h, wq, q_b, nullptr, q, BT, DIMD, DIMD);
    hmma_kernel<EPI_NONE, 1><<<g1024, 256>>>(h, wk, k_b, nullptr, k, BT, DIMD, DIMD);
    hmma_kernel<EPI_NONE, 1><<<g1024, 256>>>(h, wv, v_b, nullptr, v, BT, DIMD, DIMD);
    // 3) QK head norms (scale folded into q)
    headnorm_kernel<<<(BT * NH) / 8, 256>>>(q, qn_w, 0.125f);
    headnorm_kernel<<<(BT * NH) / 8, 256>>>(k, kn_w, 1.0f);
    // 4) attention (fp16 mma) -> half
    attn_mma_kernel<<<dim3(TT / 64, 2 * NH), 256>>>(q, k, v, ao);
    // 5) x1 = x + ao @ o_w + o_b  (float out)
    hmma_kernel<EPI_RES, 0><<<g1024, 256>>>(ao, wo, o_b, x, x1, BT, DIMD, DIMD);
    // 6) h = silu(actions @ ae1_w + ae1_b) -> half
    ae1_kernel<<<BT / 64, 256>>>(actions, ae1_w, ae1_b, h);
    // 7) ae = silu(h @ ae2_w + ae2_b) -> half
    hmma_kernel<EPI_SILU, 1><<<g1024, 256>>>(h, wae2, ae2_b, nullptr, ae, BT, DIMD, DIMD);
    // 8) mod = ae @ mod_w[:, :2048] + mod_b[:2048]  (float out)
    hmma_kernel<EPI_NONE, 0><<<g2048, 256>>>(ae, wmod, mod_b, nullptr, mod, BT, 2048, DIMD);
    // 9) modulate x1 (fp32)
    modulate_kernel<<<(BT * DIMD) / 256, 256>>>(x1, mod);
    // 10) h = rmsnorm(x1, n2_w) -> half
    rmsnorm_kernel<<<BT, 256>>>(x1, n2_w, h);
    // 11) hid = gelu(h @ m1_w + m1_b) -> half
    hmma_kernel<EPI_GELU, 1><<<g4096, 256>>>(h, wm1, m1_b, nullptr, hid, BT, MLPH, DIMD);
    // 12) out = x1 + hid @ m2_w + m2_b  (float out)
    hmma_kernel<EPI_RES, 0><<<g1024, 256>>>(hid, wm2, m2_b, x1, out, BT, DIMD, MLPH);
}

// round 6
// speedup vs baseline: 4.5881x; 1.0616x over previous
#include <cuda_runtime.h>
#include <cuda_fp16.h>
#include <math.h>
#include <stdint.h>

#define BT    4096
#define DIMD  1024
#define NH    16
#define HD    64
#define TT    2048
#define MLPH  4096

// ---------------- scratch -------------------------------------------------------
__device__ __half g_h  [BT * DIMD];
__device__ __half g_q  [BT * DIMD];
__device__ __half g_k  [BT * DIMD];
__device__ __half g_v  [BT * DIMD];
__device__ __half g_ao [BT * DIMD];
__device__ __half g_ae [BT * DIMD];
__device__ __half g_hid[BT * MLPH];
__device__ float  g_x1 [BT * DIMD];
// transposed ([N][K]) fp16 weights
__device__ __half g_wq  [DIMD * DIMD];
__device__ __half g_wk  [DIMD * DIMD];
__device__ __half g_wv  [DIMD * DIMD];
__device__ __half g_wo  [DIMD * DIMD];
__device__ __half g_wae2[DIMD * DIMD];
__device__ __half g_wmod[2048 * DIMD];   // interleaved: row 2j=shift_j, 2j+1=scale_j
__device__ __half g_wm1 [MLPH * DIMD];
__device__ __half g_wm2 [DIMD * MLPH];

// ---------------- weight transpose + fp16 round: dst[n][k] = h(src[k][n]) -------
__global__ void tr_half_kernel(const float* __restrict__ src, __half* __restrict__ dst,
                               int ldsrc, int K)
{
    __shared__ float t[32][33];
    int n0 = blockIdx.x * 32, k0 = blockIdx.y * 32;
    int tx = threadIdx.x, ty = threadIdx.y;
#pragma unroll
    for (int i = ty; i < 32; i += 8)
        t[i][tx] = src[(size_t)(k0 + i) * ldsrc + n0 + tx];
    __syncthreads();
#pragma unroll
    for (int i = ty; i < 32; i += 8)
        dst[(size_t)(n0 + i) * K + k0 + tx] = __float2half_rn(t[tx][i]);
}

// mod_w [1024][4096]: src col c<1024 -> dst row 2c (shift); c in [1024,2048) -> 2(c-1024)+1
__global__ void tr_mod_kernel(const float* __restrict__ src, __half* __restrict__ dst)
{
    __shared__ float t[32][33];
    int c0 = blockIdx.x * 32, k0 = blockIdx.y * 32;    // c0 in [0,2048)
    int tx = threadIdx.x, ty = threadIdx.y;
#pragma unroll
    for (int i = ty; i < 32; i += 8)
        t[i][tx] = src[(size_t)(k0 + i) * 4096 + c0 + tx];
    __syncthreads();
#pragma unroll
    for (int i = ty; i < 32; i += 8) {
        int c = c0 + i;
        int n = (c < 1024) ? (2 * c) : (2 * (c - 1024) + 1);
        dst[(size_t)n * 1024 + k0 + tx] = __float2half_rn(t[tx][i]);
    }
}

// ---------------- rmsnorm: float in -> half out ----------------------------------
__global__ void rmsnorm_kernel(const float* __restrict__ x,
                               const float* __restrict__ w,
                               __half* __restrict__ y)
{
    int row = blockIdx.x;
    const float* xr = x + (size_t)row * DIMD;
    float v[4];
    float s = 0.f;
#pragma unroll
    for (int i = 0; i < 4; i++) {
        v[i] = xr[threadIdx.x + i * 256];
        s += v[i] * v[i];
    }
#pragma unroll
    for (int o = 16; o > 0; o >>= 1) s += __shfl_xor_sync(0xffffffffu, s, o);
    __shared__ float red[8];
    if ((threadIdx.x & 31) == 0) red[threadIdx.x >> 5] = s;
    __syncthreads();
    if (threadIdx.x == 0) {
        float t = 0.f;
#pragma unroll
        for (int i = 0; i < 8; i++) t += red[i];
        red[0] = rsqrtf(t * (1.0f / DIMD) + 1e-6f);
    }
    __syncthreads();
    float r = red[0];
    __half* yr = y + (size_t)row * DIMD;
#pragma unroll
    for (int i = 0; i < 4; i++) {
        int c = threadIdx.x + i * 256;
        yr[c] = __float2half_rn(v[i] * r * w[c]);
    }
}

// ---------------- per-head rmsnorm on half (q and k in one launch) ----------------
__global__ void headnorm_kernel(__half* __restrict__ q, __half* __restrict__ k,
                                const float* __restrict__ qw, const float* __restrict__ kw)
{
    __half* base = blockIdx.y ? k : q;
    const float* w = blockIdx.y ? kw : qw;
    float scale = blockIdx.y ? 1.0f : 0.125f;
    int gw   = (blockIdx.x * blockDim.x + threadIdx.x) >> 5;
    int lane = threadIdx.x & 31;
    if (gw >= BT * NH) return;
    __half* p = base + (size_t)gw * HD;
    float a = __half2float(p[lane]);
    float b = __half2float(p[lane + 32]);
    float s = a * a + b * b;
#pragma unroll
    for (int o = 16; o > 0; o >>= 1) s += __shfl_xor_sync(0xffffffffu, s, o);
    float r = rsqrtf(s * (1.0f / HD) + 1e-6f) * scale;
    p[lane]      = __float2half_rn(a * r * w[lane]);
    p[lane + 32] = __float2half_rn(b * r * w[lane + 32]);
}

// ---------------- ae1 (K=16), fp32 compute, half out -------------------------------
__global__ void __launch_bounds__(256) ae1_kernel(
    const float* __restrict__ A, const float* __restrict__ W,
    const float* __restrict__ bias, __half* __restrict__ C)
{
    __shared__ float Ws[16 * 1024];
    __shared__ float As[64 * 16];
    int tid = threadIdx.x;
    for (int i = tid; i < 16 * 1024 / 4; i += 256)
        ((float4*)Ws)[i] = ((const float4*)W)[i];
    int brow = blockIdx.x * 64;
    for (int i = tid; i < 64 * 16 / 4; i += 256)
        ((float4*)As)[i] = *(const float4*)(A + (size_t)brow * 16 + i * 4);
    __syncthreads();
    int r = tid >> 2;
    int cb = (tid & 3) * 256;
    float a[16];
#pragma unroll
    for (int kk = 0; kk < 16; kk++) a[kk] = As[r * 16 + kk];
    __half* Cr = C + (size_t)(brow + r) * 1024;
    for (int cc = 0; cc < 256; cc += 4) {
        int col = cb + cc;
        float4 o = make_float4(bias[col], bias[col + 1], bias[col + 2], bias[col + 3]);
#pragma unroll
        for (int kk = 0; kk < 16; kk++) {
            float4 wv = *(float4*)&Ws[kk * 1024 + col];
            o.x += a[kk] * wv.x; o.y += a[kk] * wv.y;
            o.z += a[kk] * wv.z; o.w += a[kk] * wv.w;
        }
        o.x = o.x / (1.f + expf(-o.x));
        o.y = o.y / (1.f + expf(-o.y));
        o.z = o.z / (1.f + expf(-o.z));
        o.w = o.w / (1.f + expf(-o.w));
        *(__half2*)&Cr[col]     = __floats2half2_rn(o.x, o.y);
        *(__half2*)&Cr[col + 2] = __floats2half2_rn(o.z, o.w);
    }
}

// ================= fp16 tensor-core GEMM 128x128x32, 3-stage pipeline =============
#define EPI_NONE 0
#define EPI_SILU 1
#define EPI_GELU 2
#define EPI_RES  3
#define EPI_MOD  4

#define GBM 128
#define GBK 32
#define GSTR 40
#define HPS  (GBM * GSTR)                       // halves per stage per matrix
#define HMMA_SMEM (3 * 2 * HPS * 2)             // 61440 B

__device__ __forceinline__ void cp16h(__half* s, const __half* g)
{
    uint32_t sa = (uint32_t)__cvta_generic_to_shared(s);
    asm volatile("cp.async.cg.shared.global [%0], [%1], 16;\n" :: "r"(sa), "l"(g));
}

__device__ __forceinline__ void mma_f16(float* c, const uint32_t* a, const uint32_t* b)
{
    asm volatile(
        "mma.sync.aligned.m16n8k16.row.col.f32.f16.f16.f32 "
        "{%0,%1,%2,%3},{%4,%5,%6,%7},{%8,%9},{%0,%1,%2,%3};"
        : "+f"(c[0]), "+f"(c[1]), "+f"(c[2]), "+f"(c[3])
        : "r"(a[0]), "r"(a[1]), "r"(a[2]), "r"(a[3]), "r"(b[0]), "r"(b[1]));
}

template<int EPI, int HOUT>
__global__ void __launch_bounds__(256, 2) hmma_kernel(
    const __half* __restrict__ A, const __half* __restrict__ Wt,
    const float* __restrict__ bias, const float* __restrict__ Res,
    void* __restrict__ Cv, int M, int N, int K)
{
    extern __shared__ __half hsm[];
    __half* Asm = hsm;
    __half* Bsm = hsm + 3 * HPS;

    int tid  = threadIdx.x;
    int brow = blockIdx.y * GBM;
    int bcol = blockIdx.x * GBM;
    int warp = tid >> 5, lane = tid & 31;
    int g = lane >> 2, t = lane & 3;
    int wr = warp & 1, wc = warp >> 1;

    int r0u = tid >> 2,        c0u = (tid & 3) << 3;
    int r1u = (tid >> 2) + 64;
    const __half* Ag0 = A  + (size_t)(brow + r0u) * K + c0u;
    const __half* Ag1 = A  + (size_t)(brow + r1u) * K + c0u;
    const __half* Bg0 = Wt + (size_t)(bcol + r0u) * K + c0u;
    const __half* Bg1 = Wt + (size_t)(bcol + r1u) * K + c0u;

    float acc[4][4][4];
#pragma unroll
    for (int i = 0; i < 4; i++)
#pragma unroll
        for (int j = 0; j < 4; j++)
#pragma unroll
            for (int c = 0; c < 4; c++) acc[i][j][c] = 0.f;

    int nk = K / GBK;

    // prologue: chunks 0,1 into stages 0,1
#pragma unroll
    for (int p = 0; p < 2; p++) {
        int kc = p * GBK;
        cp16h(&Asm[p * HPS + r0u * GSTR + c0u], Ag0 + kc);
        cp16h(&Asm[p * HPS + r1u * GSTR + c0u], Ag1 + kc);
        cp16h(&Bsm[p * HPS + r0u * GSTR + c0u], Bg0 + kc);
        cp16h(&Bsm[p * HPS + r1u * GSTR + c0u], Bg1 + kc);
        asm volatile("cp.async.commit_group;");
    }

    int st = 0;                 // stage of chunk i
    for (int i = 0; i < nk; i++) {
        asm volatile("cp.async.wait_group 1;" ::: "memory");
        __syncthreads();        // all warps past compute of chunk i-1

        // issue chunk i+2 into stage (st+2)%3
        if (i + 2 < nk) {
            int kc = (i + 2) * GBK;
            int s2 = st + 2; if (s2 >= 3) s2 -= 3;
            cp16h(&Asm[s2 * HPS + r0u * GSTR + c0u], Ag0 + kc);
            cp16h(&Asm[s2 * HPS + r1u * GSTR + c0u], Ag1 + kc);
            cp16h(&Bsm[s2 * HPS + r0u * GSTR + c0u], Bg0 + kc);
            cp16h(&Bsm[s2 * HPS + r1u * GSTR + c0u], Bg1 + kc);
        }
        asm volatile("cp.async.commit_group;");

        const __half* Ab = &Asm[st * HPS + (wr * 64) * GSTR];
        const __half* Bb = &Bsm[st * HPS + (wc * 32) * GSTR];
#pragma unroll
        for (int ks = 0; ks < 2; ks++) {
            int k0 = ks * 16;
            uint32_t af[4][4], bf[4][2];
#pragma unroll
            for (int ti = 0; ti < 4; ti++) {
                const __half* p = Ab + (ti * 16 + g) * GSTR + k0 + 2 * t;
                af[ti][0] = *(const uint32_t*)(p);
                af[ti][1] = *(const uint32_t*)(p + 8 * GSTR);
                af[ti][2] = *(const uint32_t*)(p + 8);
                af[ti][3] = *(const uint32_t*)(p + 8 * GSTR + 8);
            }
#pragma unroll
            for (int tj = 0; tj < 4; tj++) {
                const __half* p = Bb + (tj * 8 + g) * GSTR + k0 + 2 * t;
                bf[tj][0] = *(const uint32_t*)(p);
                bf[tj][1] = *(const uint32_t*)(p + 8);
            }
#pragma unroll
            for (int ti = 0; ti < 4; ti++)
#pragma unroll
                for (int tj = 0; tj < 4; tj++)
                    mma_f16(acc[ti][tj], af[ti], bf[tj]);
        }
        if (++st == 3) st = 0;
    }

    // epilogue
#pragma unroll
    for (int ti = 0; ti < 4; ti++) {
        int r0 = brow + wr * 64 + ti * 16 + g;
#pragma unroll
        for (int tj = 0; tj < 4; tj++) {
            int c0 = bcol + wc * 32 + tj * 8 + 2 * t;
#pragma unroll
            for (int half_i = 0; half_i < 2; half_i++) {
                int row = r0 + half_i * 8;
                float vx = acc[ti][tj][half_i * 2 + 0];
                float vy = acc[ti][tj][half_i * 2 + 1];
                if (EPI == EPI_MOD) {
                    int j = c0 >> 1;
                    float shift = vx + bias[j];
                    float scale = vy + bias[1024 + j];
                    float res = Res[(size_t)row * (N >> 1) + j];
                    ((float*)Cv)[(size_t)row * (N >> 1) + j] = res * (1.f + scale) + shift;
                    continue;
                }
                vx += bias[c0]; vy += bias[c0 + 1];
                if (EPI == EPI_SILU) {
                    vx = vx / (1.f + expf(-vx));
                    vy = vy / (1.f + expf(-vy));
                } else if (EPI == EPI_GELU) {
                    const float cst = 0.70710678118654752f;
                    vx = 0.5f * vx * (1.f + erff(vx * cst));
                    vy = 0.5f * vy * (1.f + erff(vy * cst));
                } else if (EPI == EPI_RES) {
                    float2 rv = *(const float2*)&Res[(size_t)row * N + c0];
                    vx += rv.x; vy += rv.y;
                }
                if (HOUT) {
                    *(__half2*)((__half*)Cv + (size_t)row * N + c0) = __floats2half2_rn(vx, vy);
                } else {
                    *(float2*)((float*)Cv + (size_t)row * N + c0) = make_float2(vx, vy);
                }
            }
        }
    }
}

// ---------------- fp16 tensor-core flash attention, 64x64 tiles, ldmatrix ----------
#define AST 72

__global__ void __launch_bounds__(256) attn_mma_kernel(
    const __half* __restrict__ Q, const __half* __restrict__ K,
    const __half* __restrict__ V, __half* __restrict__ O)
{
    __shared__ __half Qs[64 * AST];
    __shared__ __half Ks[64 * AST];   // natural [c][d]
    __shared__ __half Vs[64 * AST];   // natural [c][d]
    __shared__ __half Ps[64 * AST];
    __shared__ float  redM[128], redL[128];

    int tid = threadIdx.x, warp = tid >> 5, lane = tid & 31;
    int g = lane >> 2, t = lane & 3;
    int wr = warp & 3, wc = warp >> 2;
    int qt = (TT / 64 - 1) - blockIdx.x;
    int bh = blockIdx.y, b = bh >> 4, h = bh & 15;

    const __half* Qg = Q + (size_t)b * TT * DIMD + (size_t)h * HD;
    const __half* Kg = K + (size_t)b * TT * DIMD + (size_t)h * HD;
    const __half* Vg = V + (size_t)b * TT * DIMD + (size_t)h * HD;

    int lrow = tid >> 2;
    int ld16 = (tid & 3) << 4;

    {
        const __half* src = Qg + (size_t)(qt * 64 + lrow) * DIMD + ld16;
        *(uint4*)&Qs[lrow * AST + ld16]     = *(const uint4*)(src);
        *(uint4*)&Qs[lrow * AST + ld16 + 8] = *(const uint4*)(src + 8);
    }
    __syncthreads();

    int r0 = wr * 16 + g;
    uint32_t qf[4][4];
#pragma unroll
    for (int ks = 0; ks < 4; ks++) {
        int k0 = ks * 16;
        qf[ks][0] = *(const uint32_t*)&Qs[(r0)     * AST + k0 + 2 * t];
        qf[ks][1] = *(const uint32_t*)&Qs[(r0 + 8) * AST + k0 + 2 * t];
        qf[ks][2] = *(const uint32_t*)&Qs[(r0)     * AST + k0 + 2 * t + 8];
        qf[ks][3] = *(const uint32_t*)&Qs[(r0 + 8) * AST + k0 + 2 * t + 8];
    }

    // ldmatrix source addresses (per-lane, fixed across iterations)
    // K (non-trans): lane<16 -> &Ks[(n0 + (lane&7))*AST + k0 + ((lane>>3)&1)*8]
    int kln = lane & 7, klk = ((lane >> 3) & 1) * 8;
    // V (trans): lane<16 -> &Vs[(k0 + (lane&15))*AST + n0]
    int vlk = lane & 15;

    float m0 = -1e30f, m1 = -1e30f, l0 = 0.f, l1 = 0.f;
    float acc[4][4];
#pragma unroll
    for (int tj = 0; tj < 4; tj++)
#pragma unroll
        for (int c = 0; c < 4; c++) acc[tj][c] = 0.f;

    for (int kt = 0; kt <= qt; kt++) {
        __syncthreads();
        {
            const __half* kp = Kg + (size_t)(kt * 64 + lrow) * DIMD + ld16;
            *(uint4*)&Ks[lrow * AST + ld16]     = *(const uint4*)(kp);
            *(uint4*)&Ks[lrow * AST + ld16 + 8] = *(const uint4*)(kp + 8);
            const __half* vp = Vg + (size_t)(kt * 64 + lrow) * DIMD + ld16;
            *(uint4*)&Vs[lrow * AST + ld16]     = *(const uint4*)(vp);
            *(uint4*)&Vs[lrow * AST + ld16 + 8] = *(const uint4*)(vp + 8);
        }
        __syncthreads();

        // S = Q @ K^T  (B fragments via ldmatrix.x2 non-trans)
        float s[4][4];
#pragma unroll
        for (int tj = 0; tj < 4; tj++)
#pragma unroll
            for (int c = 0; c < 4; c++) s[tj][c] = 0.f;
#pragma unroll
        for (int ks = 0; ks < 4; ks++) {
            int k0 = ks * 16;
#pragma unroll
            for (int tj = 0; tj < 4; tj++) {
                int n0 = wc * 32 + tj * 8;
                uint32_t bf[2];
                uint32_t addr = (uint32_t)__cvta_generic_to_shared(
                    &Ks[(n0 + kln) * AST + k0 + klk]);
                asm volatile("ldmatrix.sync.aligned.m8n8.x2.shared.b16 {%0,%1}, [%2];"
                             : "=r"(bf[0]), "=r"(bf[1]) : "r"(addr));
                mma_f16(s[tj], qf[ks], bf);
            }
        }

        if (kt == qt) {
#pragma unroll
            for (int tj = 0; tj < 4; tj++) {
                int c0 = wc * 32 + tj * 8 + 2 * t;
                if (c0     > r0)     s[tj][0] = -1e30f;
                if (c0 + 1 > r0)     s[tj][1] = -1e30f;
                if (c0     > r0 + 8) s[tj][2] = -1e30f;
                if (c0 + 1 > r0 + 8) s[tj][3] = -1e30f;
            }
        }

        float rm0 = -1e30f, rm1 = -1e30f;
#pragma unroll
        for (int tj = 0; tj < 4; tj++) {
            rm0 = fmaxf(rm0, fmaxf(s[tj][0], s[tj][1]));
            rm1 = fmaxf(rm1, fmaxf(s[tj][2], s[tj][3]));
        }
#pragma unroll
        for (int o = 1; o < 4; o <<= 1) {
            rm0 = fmaxf(rm0, __shfl_xor_sync(0xffffffffu, rm0, o));
            rm1 = fmaxf(rm1, __shfl_xor_sync(0xffffffffu, rm1, o));
        }
        if (t == 0) {
            redM[wc * 64 + r0]     = rm0;
            redM[wc * 64 + r0 + 8] = rm1;
        }
        __syncthreads();
        float nm0 = fmaxf(m0, fmaxf(redM[r0],     redM[64 + r0]));
        float nm1 = fmaxf(m1, fmaxf(redM[r0 + 8], redM[64 + r0 + 8]));
        float a0 = __expf(m0 - nm0), a1 = __expf(m1 - nm1);
        m0 = nm0; m1 = nm1;

        float ls0 = 0.f, ls1 = 0.f;
#pragma unroll
        for (int tj = 0; tj < 4; tj++) {
            s[tj][0] = __expf(s[tj][0] - nm0);
            s[tj][1] = __expf(s[tj][1] - nm0);
            s[tj][2] = __expf(s[tj][2] - nm1);
            s[tj][3] = __expf(s[tj][3] - nm1);
            ls0 += s[tj][0] + s[tj][1];
            ls1 += s[tj][2] + s[tj][3];
        }
#pragma unroll
        for (int o = 1; o < 4; o <<= 1) {
            ls0 += __shfl_xor_sync(0xffffffffu, ls0, o);
            ls1 += __shfl_xor_sync(0xffffffffu, ls1, o);
        }
        if (t == 0) {
            redL[wc * 64 + r0]     = ls0;
            redL[wc * 64 + r0 + 8] = ls1;
        }
#pragma unroll
        for (int tj = 0; tj < 4; tj++) {
            int c0 = wc * 32 + tj * 8 + 2 * t;
            *(__half2*)&Ps[(r0)     * AST + c0] = __floats2half2_rn(s[tj][0], s[tj][1]);
            *(__half2*)&Ps[(r0 + 8) * AST + c0] = __floats2half2_rn(s[tj][2], s[tj][3]);
        }
        __syncthreads();

        l0 = l0 * a0 + redL[r0]     + redL[64 + r0];
        l1 = l1 * a1 + redL[r0 + 8] + redL[64 + r0 + 8];
#pragma unroll
        for (int tj = 0; tj < 4; tj++) {
            acc[tj][0] *= a0; acc[tj][1] *= a0;
            acc[tj][2] *= a1; acc[tj][3] *= a1;
        }

        // O += P @ V   (B fragments via ldmatrix.x2.trans on natural Vs)
#pragma unroll
        for (int ks = 0; ks < 4; ks++) {
            int k0 = ks * 16;
            uint32_t pf[4];
            pf[0] = *(const uint32_t*)&Ps[(r0)     * AST + k0 + 2 * t];
            pf[1] = *(const uint32_t*)&Ps[(r0 + 8) * AST + k0 + 2 * t];
            pf[2] = *(const uint32_t*)&Ps[(r0)     * AST + k0 + 2 * t + 8];
            pf[3] = *(const uint32_t*)&Ps[(r0 + 8) * AST + k0 + 2 * t + 8];
#pragma unroll
            for (int tj = 0; tj < 4; tj++) {
                int n0 = wc * 32 + tj * 8;
                uint32_t bf[2];
                uint32_t addr = (uint32_t)__cvta_generic_to_shared(
                    &Vs[(k0 + vlk) * AST + n0]);
                asm volatile("ldmatrix.sync.aligned.m8n8.x2.trans.shared.b16 {%0,%1}, [%2];"
                             : "=r"(bf[0]), "=r"(bf[1]) : "r"(addr));
                mma_f16(acc[tj], pf, bf);
            }
        }
    }

    float inv0 = 1.f / l0, inv1 = 1.f / l1;
    __half* Og = O + (size_t)b * TT * DIMD + (size_t)(qt * 64) * DIMD + (size_t)h * HD;
#pragma unroll
    for (int tj = 0; tj < 4; tj++) {
        int c0 = wc * 32 + tj * 8 + 2 * t;
        *(__half2*)&Og[(size_t)(r0)     * DIMD + c0] = __floats2half2_rn(acc[tj][0] * inv0, acc[tj][1] * inv0);
        *(__half2*)&Og[(size_t)(r0 + 8) * DIMD + c0] = __floats2half2_rn(acc[tj][2] * inv1, acc[tj][3] * inv1);
    }
}

// ------------------------------- launch --------------------------------------------
extern "C" void kernel_launch(void* const* d_in, const int* in_sizes, int n_in,
                              void* d_out, int out_size)
{
    const float* x       = (const float*)d_in[0];
    const float* actions = (const float*)d_in[1];
    const float* n1_w    = (const float*)d_in[2];
    const float* n2_w    = (const float*)d_in[3];
    const float* q_w     = (const float*)d_in[4];
    const float* q_b     = (const float*)d_in[5];
    const float* k_w     = (const float*)d_in[6];
    const float* k_b     = (const float*)d_in[7];
    const float* v_w     = (const float*)d_in[8];
    const float* v_b     = (const float*)d_in[9];
    const float* qn_w    = (const float*)d_in[10];
    const float* kn_w    = (const float*)d_in[11];
    const float* o_w     = (const float*)d_in[12];
    const float* o_b     = (const float*)d_in[13];
    const float* ae1_w   = (const float*)d_in[14];
    const float* ae1_b   = (const float*)d_in[15];
    const float* ae2_w   = (const float*)d_in[16];
    const float* ae2_b   = (const float*)d_in[17];
    const float* mod_w   = (const float*)d_in[18];
    const float* mod_b   = (const float*)d_in[19];
    const float* m1_w    = (const float*)d_in[20];
    const float* m1_b    = (const float*)d_in[21];
    const float* m2_w    = (const float*)d_in[22];
    const float* m2_b    = (const float*)d_in[23];
    float* out           = (float*)d_out;

    __half *h, *q, *k, *v, *ao, *ae, *hid;
    float *x1;
    __half *wq, *wk, *wv, *wo, *wae2, *wmod, *wm1, *wm2;
    cudaGetSymbolAddress((void**)&h,    g_h);
    cudaGetSymbolAddress((void**)&q,    g_q);
    cudaGetSymbolAddress((void**)&k,    g_k);
    cudaGetSymbolAddress((void**)&v,    g_v);
    cudaGetSymbolAddress((void**)&ao,   g_ao);
    cudaGetSymbolAddress((void**)&ae,   g_ae);
    cudaGetSymbolAddress((void**)&hid,  g_hid);
    cudaGetSymbolAddress((void**)&x1,   g_x1);
    cudaGetSymbolAddress((void**)&wq,   g_wq);
    cudaGetSymbolAddress((void**)&wk,   g_wk);
    cudaGetSymbolAddress((void**)&wv,   g_wv);
    cudaGetSymbolAddress((void**)&wo,   g_wo);
    cudaGetSymbolAddress((void**)&wae2, g_wae2);
    cudaGetSymbolAddress((void**)&wmod, g_wmod);
    cudaGetSymbolAddress((void**)&wm1,  g_wm1);
    cudaGetSymbolAddress((void**)&wm2,  g_wm2);

    static int attr_set = 0;
    if (!attr_set) {
        cudaFuncSetAttribute((const void*)hmma_kernel<EPI_NONE, 1>, cudaFuncAttributeMaxDynamicSharedMemorySize, HMMA_SMEM);
        cudaFuncSetAttribute((const void*)hmma_kernel<EPI_SILU, 1>, cudaFuncAttributeMaxDynamicSharedMemorySize, HMMA_SMEM);
        cudaFuncSetAttribute((const void*)hmma_kernel<EPI_GELU, 1>, cudaFuncAttributeMaxDynamicSharedMemorySize, HMMA_SMEM);
        cudaFuncSetAttribute((const void*)hmma_kernel<EPI_RES,  0>, cudaFuncAttributeMaxDynamicSharedMemorySize, HMMA_SMEM);
        cudaFuncSetAttribute((const void*)hmma_kernel<EPI_MOD,  0>, cudaFuncAttributeMaxDynamicSharedMemorySize, HMMA_SMEM);
        attr_set = 1;
    }

    // 0) transpose + fp16-round weights
    dim3 tb(32, 8);
    tr_half_kernel<<<dim3(32, 32),  tb>>>(q_w,   wq,   1024, 1024);
    tr_half_kernel<<<dim3(32, 32),  tb>>>(k_w,   wk,   1024, 1024);
    tr_half_kernel<<<dim3(32, 32),  tb>>>(v_w,   wv,   1024, 1024);
    tr_half_kernel<<<dim3(32, 32),  tb>>>(o_w,   wo,   1024, 1024);
    tr_half_kernel<<<dim3(32, 32),  tb>>>(ae2_w, wae2, 1024, 1024);
    tr_mod_kernel <<<dim3(64, 32),  tb>>>(mod_w, wmod);
    tr_half_kernel<<<dim3(128, 32), tb>>>(m1_w,  wm1,  4096, 1024);
    tr_half_kernel<<<dim3(32, 128), tb>>>(m2_w,  wm2,  1024, 4096);

    dim3 g1024(8, 32);
    dim3 g2048(16, 32);
    dim3 g4096(32, 32);

    // 1) h = rmsnorm(x, n1_w) -> half
    rmsnorm_kernel<<<BT, 256>>>(x, n1_w, h);
    // 2) q,k,v projections
    hmma_kernel<EPI_NONE, 1><<<g1024, 256, HMMA_SMEM>>>(h, wq, q_b, nullptr, q, BT, DIMD, DIMD);
    hmma_kernel<EPI_NONE, 1><<<g1024, 256, HMMA_SMEM>>>(h, wk, k_b, nullptr, k, BT, DIMD, DIMD);
    hmma_kernel<EPI_NONE, 1><<<g1024, 256, HMMA_SMEM>>>(h, wv, v_b, nullptr, v, BT, DIMD, DIMD);
    // 3) QK head norms (one launch; scale folded into q)
    headnorm_kernel<<<dim3((BT * NH) / 8, 2), 256>>>(q, k, qn_w, kn_w);
    // 4) attention
    attn_mma_kernel<<<dim3(TT / 64, 2 * NH), 256>>>(q, k, v, ao);
    // 5) x1 = x + ao @ o_w + o_b
    hmma_kernel<EPI_RES, 0><<<g1024, 256, HMMA_SMEM>>>(ao, wo, o_b, x, x1, BT, DIMD, DIMD);
    // 6) h = silu(actions @ ae1_w + ae1_b) -> half
    ae1_kernel<<<BT / 64, 256>>>(actions, ae1_w, ae1_b, h);
    // 7) ae = silu(h @ ae2_w + ae2_b) -> half
    hmma_kernel<EPI_SILU, 1><<<g1024, 256, HMMA_SMEM>>>(h, wae2, ae2_b, nullptr, ae, BT, DIMD, DIMD);
    // 8+9) fused: x1 = x1*(1+scale1)+shift1 via interleaved mod GEMM
    hmma_kernel<EPI_MOD, 0><<<g2048, 256, HMMA_SMEM>>>(ae, wmod, mod_b, x1, x1, BT, 2048, DIMD);
    // 10) h = rmsnorm(x1, n2_w) -> half
    rmsnorm_kernel<<<BT, 256>>>(x1, n2_w, h);
    // 11) hid = gelu(h @ m1_w + m1_b) -> half
    hmma_kernel<EPI_GELU, 1><<<g4096, 256, HMMA_SMEM>>>(h, wm1, m1_b, nullptr, hid, BT, MLPH, DIMD);
    // 12) out = x1 + hid @ m2_w + m2_b
    hmma_kernel<EPI_RES, 0><<<g1024, 256, HMMA_SMEM>>>(hid, wm2, m2_b, x1, out, BT, DIMD, MLPH);
}

// round 7
// speedup vs baseline: 4.8454x; 1.0561x over previous
#include <cuda_runtime.h>
#include <cuda_fp16.h>
#include <math.h>
#include <stdint.h>

#define BT    4096
#define DIMD  1024
#define NH    16
#define HD    64
#define TT    2048
#define MLPH  4096

// ---------------- scratch -------------------------------------------------------
__device__ __half g_h  [BT * DIMD];
__device__ __half g_a1 [BT * DIMD];      // ae1 output
__device__ __half g_q  [BT * DIMD];
__device__ __half g_k  [BT * DIMD];
__device__ __half g_v  [BT * DIMD];
__device__ __half g_ao [BT * DIMD];
__device__ __half g_ae [BT * DIMD];
__device__ __half g_hid[BT * MLPH];
__device__ float  g_x1 [BT * DIMD];
// transposed ([N][K]) fp16 weights
__device__ __half g_wq  [DIMD * DIMD];
__device__ __half g_wk  [DIMD * DIMD];
__device__ __half g_wv  [DIMD * DIMD];
__device__ __half g_wo  [DIMD * DIMD];
__device__ __half g_wae2[DIMD * DIMD];
__device__ __half g_wmod[2048 * DIMD];   // interleaved: row 2j=shift_j, 2j+1=scale_j
__device__ __half g_wm1 [MLPH * DIMD];
__device__ __half g_wm2 [DIMD * MLPH];

// ---------------- fused weight transpose+round (all 8 weights, one launch) -------
// jobs: [0,5120) five 1024x1024 squares; [5120,7168) mod; [7168,11264) m1; [11264,15360) m2
__global__ void tr_all_kernel(const float* __restrict__ q_w, const float* __restrict__ k_w,
                              const float* __restrict__ v_w, const float* __restrict__ o_w,
                              const float* __restrict__ ae2_w, const float* __restrict__ mod_w,
                              const float* __restrict__ m1_w, const float* __restrict__ m2_w)
{
    __shared__ float t[32][33];
    int id = blockIdx.x;
    const float* src;
    __half* dst;
    int ldsrc, Kd, n0, k0;
    bool modmap = false;

    if (id < 5120) {
        int j = id >> 10, tt = id & 1023;
        const float* sl[5] = {q_w, k_w, v_w, o_w, ae2_w};
        __half* dl[5] = {g_wq, g_wk, g_wv, g_wo, g_wae2};
        src = sl[j]; dst = dl[j];
        ldsrc = 1024; Kd = 1024;
        n0 = (tt & 31) * 32; k0 = (tt >> 5) * 32;
    } else if (id < 7168) {
        int tt = id - 5120;
        src = mod_w; dst = g_wmod;
        ldsrc = 4096; Kd = 1024;
        n0 = (tt & 63) * 32; k0 = (tt >> 6) * 32;
        modmap = true;
    } else if (id < 11264) {
        int tt = id - 7168;
        src = m1_w; dst = g_wm1;
        ldsrc = 4096; Kd = 1024;
        n0 = (tt & 127) * 32; k0 = (tt >> 7) * 32;
    } else {
        int tt = id - 11264;
        src = m2_w; dst = g_wm2;
        ldsrc = 1024; Kd = 4096;
        n0 = (tt & 31) * 32; k0 = (tt >> 5) * 32;
    }

    int tx = threadIdx.x, ty = threadIdx.y;
#pragma unroll
    for (int i = ty; i < 32; i += 8)
        t[i][tx] = src[(size_t)(k0 + i) * ldsrc + n0 + tx];
    __syncthreads();
#pragma unroll
    for (int i = ty; i < 32; i += 8) {
        int c = n0 + i;
        int n = modmap ? ((c < 1024) ? (2 * c) : (2 * (c - 1024) + 1)) : c;
        dst[(size_t)n * Kd + k0 + tx] = __float2half_rn(t[tx][i]);
    }
}

// ---------------- rmsnorm: float in -> half out ----------------------------------
__global__ void rmsnorm_kernel(const float* __restrict__ x,
                               const float* __restrict__ w,
                               __half* __restrict__ y)
{
    int row = blockIdx.x;
    const float* xr = x + (size_t)row * DIMD;
    float v[4];
    float s = 0.f;
#pragma unroll
    for (int i = 0; i < 4; i++) {
        v[i] = xr[threadIdx.x + i * 256];
        s += v[i] * v[i];
    }
#pragma unroll
    for (int o = 16; o > 0; o >>= 1) s += __shfl_xor_sync(0xffffffffu, s, o);
    __shared__ float red[8];
    if ((threadIdx.x & 31) == 0) red[threadIdx.x >> 5] = s;
    __syncthreads();
    if (threadIdx.x == 0) {
        float t = 0.f;
#pragma unroll
        for (int i = 0; i < 8; i++) t += red[i];
        red[0] = rsqrtf(t * (1.0f / DIMD) + 1e-6f);
    }
    __syncthreads();
    float r = red[0];
    __half* yr = y + (size_t)row * DIMD;
#pragma unroll
    for (int i = 0; i < 4; i++) {
        int c = threadIdx.x + i * 256;
        yr[c] = __float2half_rn(v[i] * r * w[c]);
    }
}

// ---------------- per-head rmsnorm on half (q and k in one launch) ----------------
__global__ void headnorm_kernel(__half* __restrict__ q, __half* __restrict__ k,
                                const float* __restrict__ qw, const float* __restrict__ kw)
{
    __half* base = blockIdx.y ? k : q;
    const float* w = blockIdx.y ? kw : qw;
    float scale = blockIdx.y ? 1.0f : 0.125f;
    int gw   = (blockIdx.x * blockDim.x + threadIdx.x) >> 5;
    int lane = threadIdx.x & 31;
    if (gw >= BT * NH) return;
    __half* p = base + (size_t)gw * HD;
    float a = __half2float(p[lane]);
    float b = __half2float(p[lane + 32]);
    float s = a * a + b * b;
#pragma unroll
    for (int o = 16; o > 0; o >>= 1) s += __shfl_xor_sync(0xffffffffu, s, o);
    float r = rsqrtf(s * (1.0f / HD) + 1e-6f) * scale;
    p[lane]      = __float2half_rn(a * r * w[lane]);
    p[lane + 32] = __float2half_rn(b * r * w[lane + 32]);
}

// ---------------- ae1 (K=16), fp32 compute, half out -------------------------------
__global__ void __launch_bounds__(256) ae1_kernel(
    const float* __restrict__ A, const float* __restrict__ W,
    const float* __restrict__ bias, __half* __restrict__ C)
{
    __shared__ float Ws[16 * 1024];
    __shared__ float As[64 * 16];
    int tid = threadIdx.x;
    for (int i = tid; i < 16 * 1024 / 4; i += 256)
        ((float4*)Ws)[i] = ((const float4*)W)[i];
    int brow = blockIdx.x * 64;
    for (int i = tid; i < 64 * 16 / 4; i += 256)
        ((float4*)As)[i] = *(const float4*)(A + (size_t)brow * 16 + i * 4);
    __syncthreads();
    int r = tid >> 2;
    int cb = (tid & 3) * 256;
    float a[16];
#pragma unroll
    for (int kk = 0; kk < 16; kk++) a[kk] = As[r * 16 + kk];
    __half* Cr = C + (size_t)(brow + r) * 1024;
    for (int cc = 0; cc < 256; cc += 4) {
        int col = cb + cc;
        float4 o = make_float4(bias[col], bias[col + 1], bias[col + 2], bias[col + 3]);
#pragma unroll
        for (int kk = 0; kk < 16; kk++) {
            float4 wv = *(float4*)&Ws[kk * 1024 + col];
            o.x += a[kk] * wv.x; o.y += a[kk] * wv.y;
            o.z += a[kk] * wv.z; o.w += a[kk] * wv.w;
        }
        o.x = o.x / (1.f + expf(-o.x));
        o.y = o.y / (1.f + expf(-o.y));
        o.z = o.z / (1.f + expf(-o.z));
        o.w = o.w / (1.f + expf(-o.w));
        *(__half2*)&Cr[col]     = __floats2half2_rn(o.x, o.y);
        *(__half2*)&Cr[col + 2] = __floats2half2_rn(o.z, o.w);
    }
}

// ================= fp16 tensor-core GEMM 128x128x32, 3-stage + ldmatrix ===========
#define EPI_NONE 0
#define EPI_SILU 1
#define EPI_GELU 2
#define EPI_RES  3
#define EPI_MOD  4

#define GBM 128
#define GBK 32
#define GSTR 40
#define HPS  (GBM * GSTR)
#define HMMA_SMEM (3 * 2 * HPS * 2)

__device__ __forceinline__ void cp16h(__half* s, const __half* g)
{
    uint32_t sa = (uint32_t)__cvta_generic_to_shared(s);
    asm volatile("cp.async.cg.shared.global [%0], [%1], 16;\n" :: "r"(sa), "l"(g));
}

__device__ __forceinline__ void mma_f16(float* c, const uint32_t* a, const uint32_t* b)
{
    asm volatile(
        "mma.sync.aligned.m16n8k16.row.col.f32.f16.f16.f32 "
        "{%0,%1,%2,%3},{%4,%5,%6,%7},{%8,%9},{%0,%1,%2,%3};"
        : "+f"(c[0]), "+f"(c[1]), "+f"(c[2]), "+f"(c[3])
        : "r"(a[0]), "r"(a[1]), "r"(a[2]), "r"(a[3]), "r"(b[0]), "r"(b[1]));
}

__device__ __forceinline__ void ldm_x4(uint32_t* r, const __half* p)
{
    uint32_t addr = (uint32_t)__cvta_generic_to_shared(p);
    asm volatile("ldmatrix.sync.aligned.m8n8.x4.shared.b16 {%0,%1,%2,%3}, [%4];"
                 : "=r"(r[0]), "=r"(r[1]), "=r"(r[2]), "=r"(r[3]) : "r"(addr));
}

__device__ __forceinline__ void ldm_x2(uint32_t* r, const __half* p)
{
    uint32_t addr = (uint32_t)__cvta_generic_to_shared(p);
    asm volatile("ldmatrix.sync.aligned.m8n8.x2.shared.b16 {%0,%1}, [%2];"
                 : "=r"(r[0]), "=r"(r[1]) : "r"(addr));
}

template<int EPI, int HOUT>
__global__ void __launch_bounds__(256, 2) hmma_kernel(
    const __half* __restrict__ A, const __half* __restrict__ Wt,
    const float* __restrict__ bias, const float* __restrict__ Res,
    void* __restrict__ Cv, int M, int N, int K)
{
    extern __shared__ __half hsm[];
    __half* Asm = hsm;
    __half* Bsm = hsm + 3 * HPS;

    int tid  = threadIdx.x;
    int brow = blockIdx.y * GBM;
    int bcol = blockIdx.x * GBM;
    int warp = tid >> 5, lane = tid & 31;
    int g = lane >> 2, t = lane & 3;
    int wr = warp & 1, wc = warp >> 1;

    int r0u = tid >> 2,        c0u = (tid & 3) << 3;
    int r1u = (tid >> 2) + 64;
    const __half* Ag0 = A  + (size_t)(brow + r0u) * K + c0u;
    const __half* Ag1 = A  + (size_t)(brow + r1u) * K + c0u;
    const __half* Bg0 = Wt + (size_t)(bcol + r0u) * K + c0u;
    const __half* Bg1 = Wt + (size_t)(bcol + r1u) * K + c0u;

    // ldmatrix per-lane source offsets (within a stage)
    // A x4: row = wr*64 + ti*16 + (lane&15), koff = ((lane>>4) ? 8 : 0)
    int a_row = wr * 64 + (lane & 15);
    int a_koff = (lane >> 4) << 3;
    // B x2: row = wc*32 + tj*8 + (lane&7), koff = (lane&15)>=8 ? 8 : 0  (lanes 16-31 ignored)
    int b_row = wc * 32 + (lane & 7);
    int b_koff = ((lane >> 3) & 1) << 3;

    float acc[4][4][4];
#pragma unroll
    for (int i = 0; i < 4; i++)
#pragma unroll
        for (int j = 0; j < 4; j++)
#pragma unroll
            for (int c = 0; c < 4; c++) acc[i][j][c] = 0.f;

    int nk = K / GBK;

#pragma unroll
    for (int p = 0; p < 2; p++) {
        int kc = p * GBK;
        cp16h(&Asm[p * HPS + r0u * GSTR + c0u], Ag0 + kc);
        cp16h(&Asm[p * HPS + r1u * GSTR + c0u], Ag1 + kc);
        cp16h(&Bsm[p * HPS + r0u * GSTR + c0u], Bg0 + kc);
        cp16h(&Bsm[p * HPS + r1u * GSTR + c0u], Bg1 + kc);
        asm volatile("cp.async.commit_group;");
    }

    int st = 0;
    for (int i = 0; i < nk; i++) {
        asm volatile("cp.async.wait_group 1;" ::: "memory");
        __syncthreads();

        if (i + 2 < nk) {
            int kc = (i + 2) * GBK;
            int s2 = st + 2; if (s2 >= 3) s2 -= 3;
            cp16h(&Asm[s2 * HPS + r0u * GSTR + c0u], Ag0 + kc);
            cp16h(&Asm[s2 * HPS + r1u * GSTR + c0u], Ag1 + kc);
            cp16h(&Bsm[s2 * HPS + r0u * GSTR + c0u], Bg0 + kc);
            cp16h(&Bsm[s2 * HPS + r1u * GSTR + c0u], Bg1 + kc);
        }
        asm volatile("cp.async.commit_group;");

        const __half* Sb = &Asm[st * HPS];
        const __half* Tb = &Bsm[st * HPS];
#pragma unroll
        for (int ks = 0; ks < 2; ks++) {
            int k0 = ks * 16;
            uint32_t af[4][4], bf[4][2];
#pragma unroll
            for (int ti = 0; ti < 4; ti++)
                ldm_x4(af[ti], Sb + (a_row + ti * 16) * GSTR + k0 + a_koff);
#pragma unroll
            for (int tj = 0; tj < 4; tj++)
                ldm_x2(bf[tj], Tb + (b_row + tj * 8) * GSTR + k0 + b_koff);
#pragma unroll
            for (int ti = 0; ti < 4; ti++)
#pragma unroll
                for (int tj = 0; tj < 4; tj++)
                    mma_f16(acc[ti][tj], af[ti], bf[tj]);
        }
        if (++st == 3) st = 0;
    }

#pragma unroll
    for (int ti = 0; ti < 4; ti++) {
        int r0 = brow + wr * 64 + ti * 16 + g;
#pragma unroll
        for (int tj = 0; tj < 4; tj++) {
            int c0 = bcol + wc * 32 + tj * 8 + 2 * t;
#pragma unroll
            for (int half_i = 0; half_i < 2; half_i++) {
                int row = r0 + half_i * 8;
                float vx = acc[ti][tj][half_i * 2 + 0];
                float vy = acc[ti][tj][half_i * 2 + 1];
                if (EPI == EPI_MOD) {
                    int j = c0 >> 1;
                    float shift = vx + bias[j];
                    float scale = vy + bias[1024 + j];
                    float res = Res[(size_t)row * (N >> 1) + j];
                    ((float*)Cv)[(size_t)row * (N >> 1) + j] = res * (1.f + scale) + shift;
                    continue;
                }
                vx += bias[c0]; vy += bias[c0 + 1];
                if (EPI == EPI_SILU) {
                    vx = vx / (1.f + expf(-vx));
                    vy = vy / (1.f + expf(-vy));
                } else if (EPI == EPI_GELU) {
                    const float cst = 0.70710678118654752f;
                    vx = 0.5f * vx * (1.f + erff(vx * cst));
                    vy = 0.5f * vy * (1.f + erff(vy * cst));
                } else if (EPI == EPI_RES) {
                    float2 rv = *(const float2*)&Res[(size_t)row * N + c0];
                    vx += rv.x; vy += rv.y;
                }
                if (HOUT) {
                    *(__half2*)((__half*)Cv + (size_t)row * N + c0) = __floats2half2_rn(vx, vy);
                } else {
                    *(float2*)((float*)Cv + (size_t)row * N + c0) = make_float2(vx, vy);
                }
            }
        }
    }
}

// ---------------- fp16 flash attention, 64x64 tiles, cp.async double-buffered -----
#define AST 72
#define ATT_SMEM ((6 * 64 * AST) * 2 + 1024)   // Qs + 2*Ks + 2*Vs + Ps (halves) + red

__global__ void __launch_bounds__(256) attn_mma_kernel(
    const __half* __restrict__ Q, const __half* __restrict__ K,
    const __half* __restrict__ V, __half* __restrict__ O)
{
    extern __shared__ __half asm_[];
    __half* Qs = asm_;                  // [64][AST]
    __half* Ks = Qs + 64 * AST;         // [2][64][AST] natural [c][d]
    __half* Vs = Ks + 2 * 64 * AST;     // [2][64][AST] natural [c][d]
    __half* Ps = Vs + 2 * 64 * AST;     // [64][AST]
    float* redM = (float*)(Ps + 64 * AST);   // [2][64]
    float* redL = redM + 128;                // [2][64]

    int tid = threadIdx.x, warp = tid >> 5, lane = tid & 31;
    int g = lane >> 2, t = lane & 3;
    int wr = warp & 3, wc = warp >> 2;
    int qt = (TT / 64 - 1) - blockIdx.x;
    int bh = blockIdx.y, b = bh >> 4, h = bh & 15;

    const __half* Qg = Q + (size_t)b * TT * DIMD + (size_t)h * HD;
    const __half* Kg = K + (size_t)b * TT * DIMD + (size_t)h * HD;
    const __half* Vg = V + (size_t)b * TT * DIMD + (size_t)h * HD;

    int lrow = tid >> 2;
    int ld16 = (tid & 3) << 4;

    {
        const __half* src = Qg + (size_t)(qt * 64 + lrow) * DIMD + ld16;
        *(uint4*)&Qs[lrow * AST + ld16]     = *(const uint4*)(src);
        *(uint4*)&Qs[lrow * AST + ld16 + 8] = *(const uint4*)(src + 8);
    }

    // prologue: cp.async K/V tile kt=0 into stage 0
    {
        const __half* kp = Kg + (size_t)(0 * 64 + lrow) * DIMD + ld16;
        const __half* vp = Vg + (size_t)(0 * 64 + lrow) * DIMD + ld16;
        cp16h(&Ks[lrow * AST + ld16],     kp);
        cp16h(&Ks[lrow * AST + ld16 + 8], kp + 8);
        cp16h(&Vs[lrow * AST + ld16],     vp);
        cp16h(&Vs[lrow * AST + ld16 + 8], vp + 8);
        asm volatile("cp.async.commit_group;");
    }
    __syncthreads();   // Qs visible

    int r0 = wr * 16 + g;
    uint32_t qf[4][4];
#pragma unroll
    for (int ks = 0; ks < 4; ks++) {
        int k0 = ks * 16;
        qf[ks][0] = *(const uint32_t*)&Qs[(r0)     * AST + k0 + 2 * t];
        qf[ks][1] = *(const uint32_t*)&Qs[(r0 + 8) * AST + k0 + 2 * t];
        qf[ks][2] = *(const uint32_t*)&Qs[(r0)     * AST + k0 + 2 * t + 8];
        qf[ks][3] = *(const uint32_t*)&Qs[(r0 + 8) * AST + k0 + 2 * t + 8];
    }

    int kln = lane & 7, klk = ((lane >> 3) & 1) * 8;
    int vlk = lane & 15;

    float m0 = -1e30f, m1 = -1e30f, l0 = 0.f, l1 = 0.f;
    float acc[4][4];
#pragma unroll
    for (int tj = 0; tj < 4; tj++)
#pragma unroll
        for (int c = 0; c < 4; c++) acc[tj][c] = 0.f;

    for (int kt = 0; kt <= qt; kt++) {
        int cur = kt & 1;
        asm volatile("cp.async.wait_group 0;" ::: "memory");
        __syncthreads();   // stage cur ready; all warps done with prev iter

        // prefetch kt+1 into other stage (overlaps with this iter's compute)
        if (kt + 1 <= qt) {
            int nxt = cur ^ 1;
            const __half* kp = Kg + (size_t)((kt + 1) * 64 + lrow) * DIMD + ld16;
            const __half* vp = Vg + (size_t)((kt + 1) * 64 + lrow) * DIMD + ld16;
            cp16h(&Ks[nxt * 64 * AST + lrow * AST + ld16],     kp);
            cp16h(&Ks[nxt * 64 * AST + lrow * AST + ld16 + 8], kp + 8);
            cp16h(&Vs[nxt * 64 * AST + lrow * AST + ld16],     vp);
            cp16h(&Vs[nxt * 64 * AST + lrow * AST + ld16 + 8], vp + 8);
        }
        asm volatile("cp.async.commit_group;");

        const __half* Kc = Ks + cur * 64 * AST;
        const __half* Vc = Vs + cur * 64 * AST;

        // S = Q @ K^T
        float s[4][4];
#pragma unroll
        for (int tj = 0; tj < 4; tj++)
#pragma unroll
            for (int c = 0; c < 4; c++) s[tj][c] = 0.f;
#pragma unroll
        for (int ks = 0; ks < 4; ks++) {
            int k0 = ks * 16;
#pragma unroll
            for (int tj = 0; tj < 4; tj++) {
                int n0 = wc * 32 + tj * 8;
                uint32_t bf[2];
                ldm_x2(bf, Kc + (n0 + kln) * AST + k0 + klk);
                mma_f16(s[tj], qf[ks], bf);
            }
        }

        if (kt == qt) {
#pragma unroll
            for (int tj = 0; tj < 4; tj++) {
                int c0 = wc * 32 + tj * 8 + 2 * t;
                if (c0     > r0)     s[tj][0] = -1e30f;
                if (c0 + 1 > r0)     s[tj][1] = -1e30f;
                if (c0     > r0 + 8) s[tj][2] = -1e30f;
                if (c0 + 1 > r0 + 8) s[tj][3] = -1e30f;
            }
        }

        float rm0 = -1e30f, rm1 = -1e30f;
#pragma unroll
        for (int tj = 0; tj < 4; tj++) {
            rm0 = fmaxf(rm0, fmaxf(s[tj][0], s[tj][1]));
            rm1 = fmaxf(rm1, fmaxf(s[tj][2], s[tj][3]));
        }
#pragma unroll
        for (int o = 1; o < 4; o <<= 1) {
            rm0 = fmaxf(rm0, __shfl_xor_sync(0xffffffffu, rm0, o));
            rm1 = fmaxf(rm1, __shfl_xor_sync(0xffffffffu, rm1, o));
        }
        if (t == 0) {
            redM[wc * 64 + r0]     = rm0;
            redM[wc * 64 + r0 + 8] = rm1;
        }
        __syncthreads();
        float nm0 = fmaxf(m0, fmaxf(redM[r0],     redM[64 + r0]));
        float nm1 = fmaxf(m1, fmaxf(redM[r0 + 8], redM[64 + r0 + 8]));
        float a0 = __expf(m0 - nm0), a1 = __expf(m1 - nm1);
        m0 = nm0; m1 = nm1;

        float ls0 = 0.f, ls1 = 0.f;
#pragma unroll
        for (int tj = 0; tj < 4; tj++) {
            s[tj][0] = __expf(s[tj][0] - nm0);
            s[tj][1] = __expf(s[tj][1] - nm0);
            s[tj][2] = __expf(s[tj][2] - nm1);
            s[tj][3] = __expf(s[tj][3] - nm1);
            ls0 += s[tj][0] + s[tj][1];
            ls1 += s[tj][2] + s[tj][3];
        }
#pragma unroll
        for (int o = 1; o < 4; o <<= 1) {
            ls0 += __shfl_xor_sync(0xffffffffu, ls0, o);
            ls1 += __shfl_xor_sync(0xffffffffu, ls1, o);
        }
        if (t == 0) {
            redL[wc * 64 + r0]     = ls0;
            redL[wc * 64 + r0 + 8] = ls1;
        }
#pragma unroll
        for (int tj = 0; tj < 4; tj++) {
            int c0 = wc * 32 + tj * 8 + 2 * t;
            *(__half2*)&Ps[(r0)     * AST + c0] = __floats2half2_rn(s[tj][0], s[tj][1]);
            *(__half2*)&Ps[(r0 + 8) * AST + c0] = __floats2half2_rn(s[tj][2], s[tj][3]);
        }
        __syncthreads();

        l0 = l0 * a0 + redL[r0]     + redL[64 + r0];
        l1 = l1 * a1 + redL[r0 + 8] + redL[64 + r0 + 8];
#pragma unroll
        for (int tj = 0; tj < 4; tj++) {
            acc[tj][0] *= a0; acc[tj][1] *= a0;
            acc[tj][2] *= a1; acc[tj][3] *= a1;
        }

        // O += P @ V
#pragma unroll
        for (int ks = 0; ks < 4; ks++) {
            int k0 = ks * 16;
            uint32_t pf[4];
            pf[0] = *(const uint32_t*)&Ps[(r0)     * AST + k0 + 2 * t];
            pf[1] = *(const uint32_t*)&Ps[(r0 + 8) * AST + k0 + 2 * t];
            pf[2] = *(const uint32_t*)&Ps[(r0)     * AST + k0 + 2 * t + 8];
            pf[3] = *(const uint32_t*)&Ps[(r0 + 8) * AST + k0 + 2 * t + 8];
#pragma unroll
            for (int tj = 0; tj < 4; tj++) {
                int n0 = wc * 32 + tj * 8;
                uint32_t bf[2];
                uint32_t addr = (uint32_t)__cvta_generic_to_shared(
                    &Vc[(k0 + vlk) * AST + n0]);
                asm volatile("ldmatrix.sync.aligned.m8n8.x2.trans.shared.b16 {%0,%1}, [%2];"
                             : "=r"(bf[0]), "=r"(bf[1]) : "r"(addr));
                mma_f16(acc[tj], pf, bf);
            }
        }
    }

    float inv0 = 1.f / l0, inv1 = 1.f / l1;
    __half* Og = O + (size_t)b * TT * DIMD + (size_t)(qt * 64) * DIMD + (size_t)h * HD;
#pragma unroll
    for (int tj = 0; tj < 4; tj++) {
        int c0 = wc * 32 + tj * 8 + 2 * t;
        *(__half2*)&Og[(size_t)(r0)     * DIMD + c0] = __floats2half2_rn(acc[tj][0] * inv0, acc[tj][1] * inv0);
        *(__half2*)&Og[(size_t)(r0 + 8) * DIMD + c0] = __floats2half2_rn(acc[tj][2] * inv1, acc[tj][3] * inv1);
    }
}

// ------------------------------- launch --------------------------------------------
extern "C" void kernel_launch(void* const* d_in, const int* in_sizes, int n_in,
                              void* d_out, int out_size)
{
    const float* x       = (const float*)d_in[0];
    const float* actions = (const float*)d_in[1];
    const float* n1_w    = (const float*)d_in[2];
    const float* n2_w    = (const float*)d_in[3];
    const float* q_w     = (const float*)d_in[4];
    const float* q_b     = (const float*)d_in[5];
    const float* k_w     = (const float*)d_in[6];
    const float* k_b     = (const float*)d_in[7];
    const float* v_w     = (const float*)d_in[8];
    const float* v_b     = (const float*)d_in[9];
    const float* qn_w    = (const float*)d_in[10];
    const float* kn_w    = (const float*)d_in[11];
    const float* o_w     = (const float*)d_in[12];
    const float* o_b     = (const float*)d_in[13];
    const float* ae1_w   = (const float*)d_in[14];
    const float* ae1_b   = (const float*)d_in[15];
    const float* ae2_w   = (const float*)d_in[16];
    const float* ae2_b   = (const float*)d_in[17];
    const float* mod_w   = (const float*)d_in[18];
    const float* mod_b   = (const float*)d_in[19];
    const float* m1_w    = (const float*)d_in[20];
    const float* m1_b    = (const float*)d_in[21];
    const float* m2_w    = (const float*)d_in[22];
    const float* m2_b    = (const float*)d_in[23];
    float* out           = (float*)d_out;

    __half *h, *a1, *q, *k, *v, *ao, *ae, *hid;
    float *x1;
    __half *wq, *wk, *wv, *wo, *wae2, *wmod, *wm1, *wm2;
    cudaGetSymbolAddress((void**)&h,    g_h);
    cudaGetSymbolAddress((void**)&a1,   g_a1);
    cudaGetSymbolAddress((void**)&q,    g_q);
    cudaGetSymbolAddress((void**)&k,    g_k);
    cudaGetSymbolAddress((void**)&v,    g_v);
    cudaGetSymbolAddress((void**)&ao,   g_ao);
    cudaGetSymbolAddress((void**)&ae,   g_ae);
    cudaGetSymbolAddress((void**)&hid,  g_hid);
    cudaGetSymbolAddress((void**)&x1,   g_x1);
    cudaGetSymbolAddress((void**)&wq,   g_wq);
    cudaGetSymbolAddress((void**)&wk,   g_wk);
    cudaGetSymbolAddress((void**)&wv,   g_wv);
    cudaGetSymbolAddress((void**)&wo,   g_wo);
    cudaGetSymbolAddress((void**)&wae2, g_wae2);
    cudaGetSymbolAddress((void**)&wmod, g_wmod);
    cudaGetSymbolAddress((void**)&wm1,  g_wm1);
    cudaGetSymbolAddress((void**)&wm2,  g_wm2);

    static int attr_set = 0;
    if (!attr_set) {
        cudaFuncSetAttribute((const void*)hmma_kernel<EPI_NONE, 1>, cudaFuncAttributeMaxDynamicSharedMemorySize, HMMA_SMEM);
        cudaFuncSetAttribute((const void*)hmma_kernel<EPI_SILU, 1>, cudaFuncAttributeMaxDynamicSharedMemorySize, HMMA_SMEM);
        cudaFuncSetAttribute((const void*)hmma_kernel<EPI_GELU, 1>, cudaFuncAttributeMaxDynamicSharedMemorySize, HMMA_SMEM);
        cudaFuncSetAttribute((const void*)hmma_kernel<EPI_RES,  0>, cudaFuncAttributeMaxDynamicSharedMemorySize, HMMA_SMEM);
        cudaFuncSetAttribute((const void*)hmma_kernel<EPI_MOD,  0>, cudaFuncAttributeMaxDynamicSharedMemorySize, HMMA_SMEM);
        cudaFuncSetAttribute((const void*)attn_mma_kernel, cudaFuncAttributeMaxDynamicSharedMemorySize, ATT_SMEM);
        attr_set = 1;
    }

    dim3 g1024(8, 32);
    dim3 g2048(16, 32);
    dim3 g4096(32, 32);

    // 1) all weight transposes, one launch
    tr_all_kernel<<<15360, dim3(32, 8)>>>(q_w, k_w, v_w, o_w, ae2_w, mod_w, m1_w, m2_w);
    // 2) h = rmsnorm(x, n1_w)
    rmsnorm_kernel<<<BT, 256>>>(x, n1_w, h);
    // 3) a1 = silu(actions @ ae1_w + ae1_b)
    ae1_kernel<<<BT / 64, 256>>>(actions, ae1_w, ae1_b, a1);
    // 4-6) v,k,q projections (launch #6 = q -> visible in ncu -s 5 -c 1)
    hmma_kernel<EPI_NONE, 1><<<g1024, 256, HMMA_SMEM>>>(h, wv, v_b, nullptr, v, BT, DIMD, DIMD);
    hmma_kernel<EPI_NONE, 1><<<g1024, 256, HMMA_SMEM>>>(h, wk, k_b, nullptr, k, BT, DIMD, DIMD);
    hmma_kernel<EPI_NONE, 1><<<g1024, 256, HMMA_SMEM>>>(h, wq, q_b, nullptr, q, BT, DIMD, DIMD);
    // 7) QK head norms
    headnorm_kernel<<<dim3((BT * NH) / 8, 2), 256>>>(q, k, qn_w, kn_w);
    // 8) attention
    attn_mma_kernel<<<dim3(TT / 64, 2 * NH), 256, ATT_SMEM>>>(q, k, v, ao);
    // 9) x1 = x + ao @ o_w + o_b
    hmma_kernel<EPI_RES, 0><<<g1024, 256, HMMA_SMEM>>>(ao, wo, o_b, x, x1, BT, DIMD, DIMD);
    // 10) ae = silu(a1 @ ae2_w + ae2_b)
    hmma_kernel<EPI_SILU, 1><<<g1024, 256, HMMA_SMEM>>>(a1, wae2, ae2_b, nullptr, ae, BT, DIMD, DIMD);
    // 11) fused modulate GEMM
    hmma_kernel<EPI_MOD, 0><<<g2048, 256, HMMA_SMEM>>>(ae, wmod, mod_b, x1, x1, BT, 2048, DIMD);
    // 12) h = rmsnorm(x1, n2_w)
    rmsnorm_kernel<<<BT, 256>>>(x1, n2_w, h);
    // 13) hid = gelu(h @ m1_w + m1_b)
    hmma_kernel<EPI_GELU, 1><<<g4096, 256, HMMA_SMEM>>>(h, wm1, m1_b, nullptr, hid, BT, MLPH, DIMD);
    // 14) out = x1 + hid @ m2_w + m2_b
    hmma_kernel<EPI_RES, 0><<<g1024, 256, HMMA_SMEM>>>(hid, wm2, m2_b, x1, out, BT, DIMD, MLPH);
}

// round 8
// speedup vs baseline: 5.3641x; 1.1070x over previous
#include <cuda_runtime.h>
#include <cuda_fp16.h>
#include <math.h>
#include <stdint.h>

#define BT    4096
#define DIMD  1024
#define NH    16
#define HD    64
#define TT    2048
#define MLPH  4096
#define QSTR  3072

// ---------------- scratch -------------------------------------------------------
__device__ __half g_h  [BT * DIMD];
__device__ __half g_a1 [BT * DIMD];
__device__ __half g_qkv[BT * QSTR];      // q | k | v interleaved per row
__device__ __half g_ao [BT * DIMD];
__device__ __half g_ae [BT * DIMD];
__device__ __half g_hid[BT * MLPH];
__device__ float  g_x1 [BT * DIMD];
__device__ float  g_bqkv[QSTR];
// transposed ([N][K]) fp16 weights
__device__ __half g_wqkv[QSTR * DIMD];   // q rows 0-1023, k 1024-2047, v 2048-3071
__device__ __half g_wo  [DIMD * DIMD];
__device__ __half g_wae2[DIMD * DIMD];
__device__ __half g_wmod[2048 * DIMD];   // interleaved: row 2j=shift_j, 2j+1=scale_j
__device__ __half g_wm1 [MLPH * DIMD];
__device__ __half g_wm2 [DIMD * MLPH];

// ---------------- qkv bias pack ----------------------------------------------------
__global__ void bias_pack_kernel(const float* __restrict__ qb, const float* __restrict__ kb,
                                 const float* __restrict__ vb)
{
    int i = blockIdx.x * 256 + threadIdx.x;
    float v = (i < 1024) ? qb[i] : ((i < 2048) ? kb[i - 1024] : vb[i - 2048]);
    g_bqkv[i] = v;
}

// ---------------- fused weight transpose+round (all weights, one launch) -----------
// jobs: [0,3072) q/k/v->wqkv; [3072,5120) o,ae2; [5120,7168) mod; [7168,11264) m1;
//       [11264,15360) m2
__global__ void tr_all_kernel(const float* __restrict__ q_w, const float* __restrict__ k_w,
                              const float* __restrict__ v_w, const float* __restrict__ o_w,
                              const float* __restrict__ ae2_w, const float* __restrict__ mod_w,
                              const float* __restrict__ m1_w, const float* __restrict__ m2_w)
{
    __shared__ float t[32][33];
    int id = blockIdx.x;
    const float* src;
    __half* dst;
    int ldsrc, Kd, n0, k0, noff = 0;
    bool modmap = false;

    if (id < 3072) {
        int j = id >> 10, tt = id & 1023;
        const float* sl[3] = {q_w, k_w, v_w};
        src = sl[j]; dst = g_wqkv; noff = j * 1024;
        ldsrc = 1024; Kd = 1024;
        n0 = (tt & 31) * 32; k0 = (tt >> 5) * 32;
    } else if (id < 5120) {
        int j = (id - 3072) >> 10, tt = id & 1023;
        src = j ? ae2_w : o_w; dst = j ? g_wae2 : g_wo;
        ldsrc = 1024; Kd = 1024;
        n0 = (tt & 31) * 32; k0 = (tt >> 5) * 32;
    } else if (id < 7168) {
        int tt = id - 5120;
        src = mod_w; dst = g_wmod;
        ldsrc = 4096; Kd = 1024;
        n0 = (tt & 63) * 32; k0 = (tt >> 6) * 32;
        modmap = true;
    } else if (id < 11264) {
        int tt = id - 7168;
        src = m1_w; dst = g_wm1;
        ldsrc = 4096; Kd = 1024;
        n0 = (tt & 127) * 32; k0 = (tt >> 7) * 32;
    } else {
        int tt = id - 11264;
        src = m2_w; dst = g_wm2;
        ldsrc = 1024; Kd = 4096;
        n0 = (tt & 31) * 32; k0 = (tt >> 5) * 32;
    }

    int tx = threadIdx.x, ty = threadIdx.y;
#pragma unroll
    for (int i = ty; i < 32; i += 8)
        t[i][tx] = src[(size_t)(k0 + i) * ldsrc + n0 + tx];
    __syncthreads();
#pragma unroll
    for (int i = ty; i < 32; i += 8) {
        int c = n0 + i;
        int n = modmap ? ((c < 1024) ? (2 * c) : (2 * (c - 1024) + 1)) : (noff + c);
        dst[(size_t)n * Kd + k0 + tx] = __float2half_rn(t[tx][i]);
    }
}

// ---------------- rmsnorm: float in -> half out ----------------------------------
__global__ void rmsnorm_kernel(const float* __restrict__ x,
                               const float* __restrict__ w,
                               __half* __restrict__ y)
{
    int row = blockIdx.x;
    const float* xr = x + (size_t)row * DIMD;
    float v[4];
    float s = 0.f;
#pragma unroll
    for (int i = 0; i < 4; i++) {
        v[i] = xr[threadIdx.x + i * 256];
        s += v[i] * v[i];
    }
#pragma unroll
    for (int o = 16; o > 0; o >>= 1) s += __shfl_xor_sync(0xffffffffu, s, o);
    __shared__ float red[8];
    if ((threadIdx.x & 31) == 0) red[threadIdx.x >> 5] = s;
    __syncthreads();
    if (threadIdx.x == 0) {
        float t = 0.f;
#pragma unroll
        for (int i = 0; i < 8; i++) t += red[i];
        red[0] = rsqrtf(t * (1.0f / DIMD) + 1e-6f);
    }
    __syncthreads();
    float r = red[0];
    __half* yr = y + (size_t)row * DIMD;
#pragma unroll
    for (int i = 0; i < 4; i++) {
        int c = threadIdx.x + i * 256;
        yr[c] = __float2half_rn(v[i] * r * w[c]);
    }
}

// ---------------- per-head rmsnorm on qkv buffer (q and k in one launch) -----------
__global__ void headnorm_kernel(__half* __restrict__ qkv,
                                const float* __restrict__ qw, const float* __restrict__ kw)
{
    int sel = blockIdx.y;
    const float* w = sel ? kw : qw;
    float scale = sel ? 1.0f : 0.125f;
    int gw   = (blockIdx.x * blockDim.x + threadIdx.x) >> 5;
    int lane = threadIdx.x & 31;
    if (gw >= BT * NH) return;
    int token = gw >> 4, head = gw & 15;
    __half* p = qkv + (size_t)token * QSTR + sel * 1024 + head * 64;
    float a = __half2float(p[lane]);
    float b = __half2float(p[lane + 32]);
    float s = a * a + b * b;
#pragma unroll
    for (int o = 16; o > 0; o >>= 1) s += __shfl_xor_sync(0xffffffffu, s, o);
    float r = rsqrtf(s * (1.0f / HD) + 1e-6f) * scale;
    p[lane]      = __float2half_rn(a * r * w[lane]);
    p[lane + 32] = __float2half_rn(b * r * w[lane + 32]);
}

// ---------------- ae1 (K=16), fp32 compute, half out -------------------------------
__global__ void __launch_bounds__(256) ae1_kernel(
    const float* __restrict__ A, const float* __restrict__ W,
    const float* __restrict__ bias, __half* __restrict__ C)
{
    __shared__ float Ws[16 * 1024];
    __shared__ float As[64 * 16];
    int tid = threadIdx.x;
    for (int i = tid; i < 16 * 1024 / 4; i += 256)
        ((float4*)Ws)[i] = ((const float4*)W)[i];
    int brow = blockIdx.x * 64;
    for (int i = tid; i < 64 * 16 / 4; i += 256)
        ((float4*)As)[i] = *(const float4*)(A + (size_t)brow * 16 + i * 4);
    __syncthreads();
    int r = tid >> 2;
    int cb = (tid & 3) * 256;
    float a[16];
#pragma unroll
    for (int kk = 0; kk < 16; kk++) a[kk] = As[r * 16 + kk];
    __half* Cr = C + (size_t)(brow + r) * 1024;
    for (int cc = 0; cc < 256; cc += 4) {
        int col = cb + cc;
        float4 o = make_float4(bias[col], bias[col + 1], bias[col + 2], bias[col + 3]);
#pragma unroll
        for (int kk = 0; kk < 16; kk++) {
            float4 wv = *(float4*)&Ws[kk * 1024 + col];
            o.x += a[kk] * wv.x; o.y += a[kk] * wv.y;
            o.z += a[kk] * wv.z; o.w += a[kk] * wv.w;
        }
        o.x = o.x / (1.f + expf(-o.x));
        o.y = o.y / (1.f + expf(-o.y));
        o.z = o.z / (1.f + expf(-o.z));
        o.w = o.w / (1.f + expf(-o.w));
        *(__half2*)&Cr[col]     = __floats2half2_rn(o.x, o.y);
        *(__half2*)&Cr[col + 2] = __floats2half2_rn(o.z, o.w);
    }
}

// ================= fp16 tensor-core GEMM 128x128x64, 3-stage + ldmatrix.x4 =========
#define EPI_NONE 0
#define EPI_SILU 1
#define EPI_GELU 2
#define EPI_RES  3
#define EPI_MOD  4

#define GBK 64
#define GSTR 72
#define HPS  (128 * GSTR)                     // halves per stage per matrix
#define HMMA_SMEM (3 * 2 * HPS * 2)           // 110592 B

__device__ __forceinline__ void cp16h(__half* s, const __half* g)
{
    uint32_t sa = (uint32_t)__cvta_generic_to_shared(s);
    asm volatile("cp.async.cg.shared.global [%0], [%1], 16;\n" :: "r"(sa), "l"(g));
}

__device__ __forceinline__ void mma_f16(float* c, const uint32_t* a, const uint32_t* b)
{
    asm volatile(
        "mma.sync.aligned.m16n8k16.row.col.f32.f16.f16.f32 "
        "{%0,%1,%2,%3},{%4,%5,%6,%7},{%8,%9},{%0,%1,%2,%3};"
        : "+f"(c[0]), "+f"(c[1]), "+f"(c[2]), "+f"(c[3])
        : "r"(a[0]), "r"(a[1]), "r"(a[2]), "r"(a[3]), "r"(b[0]), "r"(b[1]));
}

__device__ __forceinline__ void ldm_x4(uint32_t* r, const __half* p)
{
    uint32_t addr = (uint32_t)__cvta_generic_to_shared(p);
    asm volatile("ldmatrix.sync.aligned.m8n8.x4.shared.b16 {%0,%1,%2,%3}, [%4];"
                 : "=r"(r[0]), "=r"(r[1]), "=r"(r[2]), "=r"(r[3]) : "r"(addr));
}

__device__ __forceinline__ void ldm_x2(uint32_t* r, const __half* p)
{
    uint32_t addr = (uint32_t)__cvta_generic_to_shared(p);
    asm volatile("ldmatrix.sync.aligned.m8n8.x2.shared.b16 {%0,%1}, [%2];"
                 : "=r"(r[0]), "=r"(r[1]) : "r"(addr));
}

template<int EPI, int HOUT>
__global__ void __launch_bounds__(256, 2) hmma_kernel(
    const __half* __restrict__ A, const __half* __restrict__ Wt,
    const float* __restrict__ bias, const float* __restrict__ Res,
    void* __restrict__ Cv, int M, int N, int K)
{
    extern __shared__ __half hsm[];
    __half* Asm = hsm;
    __half* Bsm = hsm + 3 * HPS;

    int tid  = threadIdx.x;
    int brow = blockIdx.y * 128;
    int bcol = blockIdx.x * 128;
    int warp = tid >> 5, lane = tid & 31;
    int g = lane >> 2, t = lane & 3;
    int wr = warp & 1, wc = warp >> 1;

    // loader: thread -> row tid>>3 (+32 per pass), col8 (tid&7)*8
    int r0u = tid >> 3, c0u = (tid & 7) << 3;
    const __half* Agb = A  + (size_t)(brow + r0u) * K + c0u;
    const __half* Bgb = Wt + (size_t)(bcol + r0u) * K + c0u;

    // ldmatrix lane offsets
    int a_row  = wr * 64 + (lane & 15);
    int a_koff = (lane >> 4) << 3;
    int b_row  = wc * 32 + ((lane >> 4) << 3) + (lane & 7);
    int b_koff = ((lane >> 3) & 1) << 3;

    float acc[4][4][4];
#pragma unroll
    for (int i = 0; i < 4; i++)
#pragma unroll
        for (int j = 0; j < 4; j++)
#pragma unroll
            for (int c = 0; c < 4; c++) acc[i][j][c] = 0.f;

    int nk = K / GBK;

#pragma unroll
    for (int s = 0; s < 2; s++) {
        int kc = s * GBK;
#pragma unroll
        for (int p = 0; p < 4; p++) {
            cp16h(&Asm[s * HPS + (r0u + 32 * p) * GSTR + c0u], Agb + (size_t)32 * p * K + kc);
            cp16h(&Bsm[s * HPS + (r0u + 32 * p) * GSTR + c0u], Bgb + (size_t)32 * p * K + kc);
        }
        asm volatile("cp.async.commit_group;");
    }

    int st = 0;
    for (int i = 0; i < nk; i++) {
        asm volatile("cp.async.wait_group 1;" ::: "memory");
        __syncthreads();

        if (i + 2 < nk) {
            int kc = (i + 2) * GBK;
            int s2 = st + 2; if (s2 >= 3) s2 -= 3;
#pragma unroll
            for (int p = 0; p < 4; p++) {
                cp16h(&Asm[s2 * HPS + (r0u + 32 * p) * GSTR + c0u], Agb + (size_t)32 * p * K + kc);
                cp16h(&Bsm[s2 * HPS + (r0u + 32 * p) * GSTR + c0u], Bgb + (size_t)32 * p * K + kc);
            }
        }
        asm volatile("cp.async.commit_group;");

        const __half* Sb = &Asm[st * HPS];
        const __half* Tb = &Bsm[st * HPS];
#pragma unroll
        for (int ks = 0; ks < 4; ks++) {
            int k0 = ks * 16;
            uint32_t af[4][4], bf[4][2];
#pragma unroll
            for (int ti = 0; ti < 4; ti++)
                ldm_x4(af[ti], Sb + (a_row + ti * 16) * GSTR + k0 + a_koff);
#pragma unroll
            for (int tp = 0; tp < 2; tp++)
                ldm_x4(&bf[2 * tp][0], Tb + (b_row + tp * 16) * GSTR + k0 + b_koff);
#pragma unroll
            for (int ti = 0; ti < 4; ti++)
#pragma unroll
                for (int tj = 0; tj < 4; tj++)
                    mma_f16(acc[ti][tj], af[ti], bf[tj]);
        }
        if (++st == 3) st = 0;
    }

#pragma unroll
    for (int ti = 0; ti < 4; ti++) {
        int r0 = brow + wr * 64 + ti * 16 + g;
#pragma unroll
        for (int tj = 0; tj < 4; tj++) {
            int c0 = bcol + wc * 32 + tj * 8 + 2 * t;
#pragma unroll
            for (int half_i = 0; half_i < 2; half_i++) {
                int row = r0 + half_i * 8;
                float vx = acc[ti][tj][half_i * 2 + 0];
                float vy = acc[ti][tj][half_i * 2 + 1];
                if (EPI == EPI_MOD) {
                    int j = c0 >> 1;
                    float shift = vx + bias[j];
                    float scale = vy + bias[1024 + j];
                    float res = Res[(size_t)row * (N >> 1) + j];
                    ((float*)Cv)[(size_t)row * (N >> 1) + j] = res * (1.f + scale) + shift;
                    continue;
                }
                vx += bias[c0]; vy += bias[c0 + 1];
                if (EPI == EPI_SILU) {
                    vx = vx / (1.f + expf(-vx));
                    vy = vy / (1.f + expf(-vy));
                } else if (EPI == EPI_GELU) {
                    const float cst = 0.70710678118654752f;
                    vx = 0.5f * vx * (1.f + erff(vx * cst));
                    vy = 0.5f * vy * (1.f + erff(vy * cst));
                } else if (EPI == EPI_RES) {
                    float2 rv = *(const float2*)&Res[(size_t)row * N + c0];
                    vx += rv.x; vy += rv.y;
                }
                if (HOUT) {
                    *(__half2*)((__half*)Cv + (size_t)row * N + c0) = __floats2half2_rn(vx, vy);
                } else {
                    *(float2*)((float*)Cv + (size_t)row * N + c0) = make_float2(vx, vy);
                }
            }
        }
    }
}

// ---------------- fp16 flash attention, 64x64 tiles, cp.async double-buffered -----
#define AST 72
#define ATT_SMEM ((6 * 64 * AST) * 2 + 1024)

__global__ void __launch_bounds__(256) attn_mma_kernel(
    const __half* __restrict__ QKV, __half* __restrict__ O)
{
    extern __shared__ __half asm_[];
    __half* Qs = asm_;
    __half* Ks = Qs + 64 * AST;
    __half* Vs = Ks + 2 * 64 * AST;
    __half* Ps = Vs + 2 * 64 * AST;
    float* redM = (float*)(Ps + 64 * AST);
    float* redL = redM + 128;

    int tid = threadIdx.x, warp = tid >> 5, lane = tid & 31;
    int g = lane >> 2, t = lane & 3;
    int wr = warp & 3, wc = warp >> 2;
    int qt = (TT / 64 - 1) - blockIdx.x;
    int bh = blockIdx.y, b = bh >> 4, h = bh & 15;

    const __half* Qg = QKV + (size_t)b * TT * QSTR + (size_t)h * HD;
    const __half* Kg = Qg + 1024;
    const __half* Vg = Qg + 2048;

    int lrow = tid >> 2;
    int ld16 = (tid & 3) << 4;

    {
        const __half* src = Qg + (size_t)(qt * 64 + lrow) * QSTR + ld16;
        *(uint4*)&Qs[lrow * AST + ld16]     = *(const uint4*)(src);
        *(uint4*)&Qs[lrow * AST + ld16 + 8] = *(const uint4*)(src + 8);
    }

    {
        const __half* kp = Kg + (size_t)lrow * QSTR + ld16;
        const __half* vp = Vg + (size_t)lrow * QSTR + ld16;
        cp16h(&Ks[lrow * AST + ld16],     kp);
        cp16h(&Ks[lrow * AST + ld16 + 8], kp + 8);
        cp16h(&Vs[lrow * AST + ld16],     vp);
        cp16h(&Vs[lrow * AST + ld16 + 8], vp + 8);
        asm volatile("cp.async.commit_group;");
    }
    __syncthreads();

    int r0 = wr * 16 + g;
    uint32_t qf[4][4];
#pragma unroll
    for (int ks = 0; ks < 4; ks++) {
        int k0 = ks * 16;
        qf[ks][0] = *(const uint32_t*)&Qs[(r0)     * AST + k0 + 2 * t];
        qf[ks][1] = *(const uint32_t*)&Qs[(r0 + 8) * AST + k0 + 2 * t];
        qf[ks][2] = *(const uint32_t*)&Qs[(r0)     * AST + k0 + 2 * t + 8];
        qf[ks][3] = *(const uint32_t*)&Qs[(r0 + 8) * AST + k0 + 2 * t + 8];
    }

    int kln = lane & 7, klk = ((lane >> 3) & 1) * 8;
    int vlk = lane & 15;

    float m0 = -1e30f, m1 = -1e30f, l0 = 0.f, l1 = 0.f;
    float acc[4][4];
#pragma unroll
    for (int tj = 0; tj < 4; tj++)
#pragma unroll
        for (int c = 0; c < 4; c++) acc[tj][c] = 0.f;

    for (int kt = 0; kt <= qt; kt++) {
        int cur = kt & 1;
        asm volatile("cp.async.wait_group 0;" ::: "memory");
        __syncthreads();

        if (kt + 1 <= qt) {
            int nxt = cur ^ 1;
            const __half* kp = Kg + (size_t)((kt + 1) * 64 + lrow) * QSTR + ld16;
            const __half* vp = Vg + (size_t)((kt + 1) * 64 + lrow) * QSTR + ld16;
            cp16h(&Ks[nxt * 64 * AST + lrow * AST + ld16],     kp);
            cp16h(&Ks[nxt * 64 * AST + lrow * AST + ld16 + 8], kp + 8);
            cp16h(&Vs[nxt * 64 * AST + lrow * AST + ld16],     vp);
            cp16h(&Vs[nxt * 64 * AST + lrow * AST + ld16 + 8], vp + 8);
        }
        asm volatile("cp.async.commit_group;");

        const __half* Kc = Ks + cur * 64 * AST;
        const __half* Vc = Vs + cur * 64 * AST;

        float s[4][4];
#pragma unroll
        for (int tj = 0; tj < 4; tj++)
#pragma unroll
            for (int c = 0; c < 4; c++) s[tj][c] = 0.f;
#pragma unroll
        for (int ks = 0; ks < 4; ks++) {
            int k0 = ks * 16;
#pragma unroll
            for (int tj = 0; tj < 4; tj++) {
                int n0 = wc * 32 + tj * 8;
                uint32_t bf[2];
                ldm_x2(bf, Kc + (n0 + kln) * AST + k0 + klk);
                mma_f16(s[tj], qf[ks], bf);
            }
        }

        if (kt == qt) {
#pragma unroll
            for (int tj = 0; tj < 4; tj++) {
                int c0 = wc * 32 + tj * 8 + 2 * t;
                if (c0     > r0)     s[tj][0] = -1e30f;
                if (c0 + 1 > r0)     s[tj][1] = -1e30f;
                if (c0     > r0 + 8) s[tj][2] = -1e30f;
                if (c0 + 1 > r0 + 8) s[tj][3] = -1e30f;
            }
        }

        float rm0 = -1e30f, rm1 = -1e30f;
#pragma unroll
        for (int tj = 0; tj < 4; tj++) {
            rm0 = fmaxf(rm0, fmaxf(s[tj][0], s[tj][1]));
            rm1 = fmaxf(rm1, fmaxf(s[tj][2], s[tj][3]));
        }
#pragma unroll
        for (int o = 1; o < 4; o <<= 1) {
            rm0 = fmaxf(rm0, __shfl_xor_sync(0xffffffffu, rm0, o));
            rm1 = fmaxf(rm1, __shfl_xor_sync(0xffffffffu, rm1, o));
        }
        if (t == 0) {
            redM[wc * 64 + r0]     = rm0;
            redM[wc * 64 + r0 + 8] = rm1;
        }
        __syncthreads();
        float nm0 = fmaxf(m0, fmaxf(redM[r0],     redM[64 + r0]));
        float nm1 = fmaxf(m1, fmaxf(redM[r0 + 8], redM[64 + r0 + 8]));
        float a0 = __expf(m0 - nm0), a1 = __expf(m1 - nm1);
        m0 = nm0; m1 = nm1;

        float ls0 = 0.f, ls1 = 0.f;
#pragma unroll
        for (int tj = 0; tj < 4; tj++) {
            s[tj][0] = __expf(s[tj][0] - nm0);
            s[tj][1] = __expf(s[tj][1] - nm0);
            s[tj][2] = __expf(s[tj][2] - nm1);
            s[tj][3] = __expf(s[tj][3] - nm1);
            ls0 += s[tj][0] + s[tj][1];
            ls1 += s[tj][2] + s[tj][3];
        }
#pragma unroll
        for (int o = 1; o < 4; o <<= 1) {
            ls0 += __shfl_xor_sync(0xffffffffu, ls0, o);
            ls1 += __shfl_xor_sync(0xffffffffu, ls1, o);
        }
        if (t == 0) {
            redL[wc * 64 + r0]     = ls0;
            redL[wc * 64 + r0 + 8] = ls1;
        }
#pragma unroll
        for (int tj = 0; tj < 4; tj++) {
            int c0 = wc * 32 + tj * 8 + 2 * t;
            *(__half2*)&Ps[(r0)     * AST + c0] = __floats2half2_rn(s[tj][0], s[tj][1]);
            *(__half2*)&Ps[(r0 + 8) * AST + c0] = __floats2half2_rn(s[tj][2], s[tj][3]);
        }
        __syncthreads();

        l0 = l0 * a0 + redL[r0]     + redL[64 + r0];
        l1 = l1 * a1 + redL[r0 + 8] + redL[64 + r0 + 8];
#pragma unroll
        for (int tj = 0; tj < 4; tj++) {
            acc[tj][0] *= a0; acc[tj][1] *= a0;
            acc[tj][2] *= a1; acc[tj][3] *= a1;
        }

#pragma unroll
        for (int ks = 0; ks < 4; ks++) {
            int k0 = ks * 16;
            uint32_t pf[4];
            pf[0] = *(const uint32_t*)&Ps[(r0)     * AST + k0 + 2 * t];
            pf[1] = *(const uint32_t*)&Ps[(r0 + 8) * AST + k0 + 2 * t];
            pf[2] = *(const uint32_t*)&Ps[(r0)     * AST + k0 + 2 * t + 8];
            pf[3] = *(const uint32_t*)&Ps[(r0 + 8) * AST + k0 + 2 * t + 8];
#pragma unroll
            for (int tj = 0; tj < 4; tj++) {
                int n0 = wc * 32 + tj * 8;
                uint32_t bf[2];
                uint32_t addr = (uint32_t)__cvta_generic_to_shared(
                    &Vc[(k0 + vlk) * AST + n0]);
                asm volatile("ldmatrix.sync.aligned.m8n8.x2.trans.shared.b16 {%0,%1}, [%2];"
                             : "=r"(bf[0]), "=r"(bf[1]) : "r"(addr));
                mma_f16(acc[tj], pf, bf);
            }
        }
    }

    float inv0 = 1.f / l0, inv1 = 1.f / l1;
    __half* Og = O + (size_t)b * TT * DIMD + (size_t)(qt * 64) * DIMD + (size_t)h * HD;
#pragma unroll
    for (int tj = 0; tj < 4; tj++) {
        int c0 = wc * 32 + tj * 8 + 2 * t;
        *(__half2*)&Og[(size_t)(r0)     * DIMD + c0] = __floats2half2_rn(acc[tj][0] * inv0, acc[tj][1] * inv0);
        *(__half2*)&Og[(size_t)(r0 + 8) * DIMD + c0] = __floats2half2_rn(acc[tj][2] * inv1, acc[tj][3] * inv1);
    }
}

// ------------------------------- launch --------------------------------------------
extern "C" void kernel_launch(void* const* d_in, const int* in_sizes, int n_in,
                              void* d_out, int out_size)
{
    const float* x       = (const float*)d_in[0];
    const float* actions = (const float*)d_in[1];
    const float* n1_w    = (const float*)d_in[2];
    const float* n2_w    = (const float*)d_in[3];
    const float* q_w     = (const float*)d_in[4];
    const float* q_b     = (const float*)d_in[5];
    const float* k_w     = (const float*)d_in[6];
    const float* k_b     = (const float*)d_in[7];
    const float* v_w     = (const float*)d_in[8];
    const float* v_b     = (const float*)d_in[9];
    const float* qn_w    = (const float*)d_in[10];
    const float* kn_w    = (const float*)d_in[11];
    const float* o_w     = (const float*)d_in[12];
    const float* o_b     = (const float*)d_in[13];
    const float* ae1_w   = (const float*)d_in[14];
    const float* ae1_b   = (const float*)d_in[15];
    const float* ae2_w   = (const float*)d_in[16];
    const float* ae2_b   = (const float*)d_in[17];
    const float* mod_w   = (const float*)d_in[18];
    const float* mod_b   = (const float*)d_in[19];
    const float* m1_w    = (const float*)d_in[20];
    const float* m1_b    = (const float*)d_in[21];
    const float* m2_w    = (const float*)d_in[22];
    const float* m2_b    = (const float*)d_in[23];
    float* out           = (float*)d_out;

    __half *h, *a1, *qkv, *ao, *ae, *hid;
    float *x1, *bqkv;
    __half *wqkv, *wo, *wae2, *wmod, *wm1, *wm2;
    cudaGetSymbolAddress((void**)&h,    g_h);
    cudaGetSymbolAddress((void**)&a1,   g_a1);
    cudaGetSymbolAddress((void**)&qkv,  g_qkv);
    cudaGetSymbolAddress((void**)&ao,   g_ao);
    cudaGetSymbolAddress((void**)&ae,   g_ae);
    cudaGetSymbolAddress((void**)&hid,  g_hid);
    cudaGetSymbolAddress((void**)&x1,   g_x1);
    cudaGetSymbolAddress((void**)&bqkv, g_bqkv);
    cudaGetSymbolAddress((void**)&wqkv, g_wqkv);
    cudaGetSymbolAddress((void**)&wo,   g_wo);
    cudaGetSymbolAddress((void**)&wae2, g_wae2);
    cudaGetSymbolAddress((void**)&wmod, g_wmod);
    cudaGetSymbolAddress((void**)&wm1,  g_wm1);
    cudaGetSymbolAddress((void**)&wm2,  g_wm2);

    static int attr_set = 0;
    if (!attr_set) {
        cudaFuncSetAttribute((const void*)hmma_kernel<EPI_NONE, 1>, cudaFuncAttributeMaxDynamicSharedMemorySize, HMMA_SMEM);
        cudaFuncSetAttribute((const void*)hmma_kernel<EPI_SILU, 1>, cudaFuncAttributeMaxDynamicSharedMemorySize, HMMA_SMEM);
        cudaFuncSetAttribute((const void*)hmma_kernel<EPI_GELU, 1>, cudaFuncAttributeMaxDynamicSharedMemorySize, HMMA_SMEM);
        cudaFuncSetAttribute((const void*)hmma_kernel<EPI_RES,  0>, cudaFuncAttributeMaxDynamicSharedMemorySize, HMMA_SMEM);
        cudaFuncSetAttribute((const void*)hmma_kernel<EPI_MOD,  0>, cudaFuncAttributeMaxDynamicSharedMemorySize, HMMA_SMEM);
        cudaFuncSetAttribute((const void*)attn_mma_kernel, cudaFuncAttributeMaxDynamicSharedMemorySize, ATT_SMEM);
        attr_set = 1;
    }

    dim3 g1024(8, 32);
    dim3 g2048(16, 32);
    dim3 g3072(24, 32);
    dim3 g4096(32, 32);

    // 1) pack qkv bias
    bias_pack_kernel<<<12, 256>>>(q_b, k_b, v_b);
    // 2) all weight transposes, one launch
    tr_all_kernel<<<15360, dim3(32, 8)>>>(q_w, k_w, v_w, o_w, ae2_w, mod_w, m1_w, m2_w);
    // 3) h = rmsnorm(x, n1_w)
    rmsnorm_kernel<<<BT, 256>>>(x, n1_w, h);
    // 4) a1 = silu(actions @ ae1_w + ae1_b)
    ae1_kernel<<<BT / 64, 256>>>(actions, ae1_w, ae1_b, a1);
    // 5) ae = silu(a1 @ ae2_w + ae2_b)
    hmma_kernel<EPI_SILU, 1><<<g1024, 256, HMMA_SMEM>>>(a1, wae2, ae2_b, nullptr, ae, BT, DIMD, DIMD);
    // 6) fused qkv projection (profiled by ncu -s 5 -c 1)
    hmma_kernel<EPI_NONE, 1><<<g3072, 256, HMMA_SMEM>>>(h, wqkv, bqkv, nullptr, qkv, BT, QSTR, DIMD);
    // 7) QK head norms
    headnorm_kernel<<<dim3((BT * NH) / 8, 2), 256>>>(qkv, qn_w, kn_w);
    // 8) attention
    attn_mma_kernel<<<dim3(TT / 64, 2 * NH), 256, ATT_SMEM>>>(qkv, ao);
    // 9) x1 = x + ao @ o_w + o_b
    hmma_kernel<EPI_RES, 0><<<g1024, 256, HMMA_SMEM>>>(ao, wo, o_b, x, x1, BT, DIMD, DIMD);
    // 10) fused modulate GEMM
    hmma_kernel<EPI_MOD, 0><<<g2048, 256, HMMA_SMEM>>>(ae, wmod, mod_b, x1, x1, BT, 2048, DIMD);
    // 11) h = rmsnorm(x1, n2_w)
    rmsnorm_kernel<<<BT, 256>>>(x1, n2_w, h);
    // 12) hid = gelu(h @ m1_w + m1_b)
    hmma_kernel<EPI_GELU, 1><<<g4096, 256, HMMA_SMEM>>>(h, wm1, m1_b, nullptr, hid, BT, MLPH, DIMD);
    // 13) out = x1 + hid @ m2_w + m2_b
    hmma_kernel<EPI_RES, 0><<<g1024, 256, HMMA_SMEM>>>(hid, wm2, m2_b, x1, out, BT, DIMD, MLPH);
}

// round 9
// speedup vs baseline: 5.9312x; 1.1057x over previous
#include <cuda_runtime.h>
#include <cuda_fp16.h>
#include <math.h>
#include <stdint.h>

#define BT    4096
#define DIMD  1024
#define NH    16
#define HD    64
#define TT    2048
#define MLPH  4096
#define QSTR  3072

// ---------------- scratch -------------------------------------------------------
__device__ __half g_h  [BT * DIMD];
__device__ __half g_a1 [BT * DIMD];
__device__ __half g_qkv[BT * QSTR];      // q | k | v interleaved per row
__device__ __half g_ao [BT * DIMD];
__device__ __half g_ae [BT * DIMD];
__device__ __half g_hid[BT * MLPH];
__device__ float  g_x1 [BT * DIMD];
__device__ float  g_bqkv[QSTR];
// transposed ([N][K]) fp16 weights
__device__ __half g_wqkv[QSTR * DIMD];   // q rows 0-1023, k 1024-2047, v 2048-3071
__device__ __half g_wo  [DIMD * DIMD];
__device__ __half g_wae2[DIMD * DIMD];
__device__ __half g_wmod[2048 * DIMD];   // interleaved: row 2j=shift_j, 2j+1=scale_j
__device__ __half g_wm1 [MLPH * DIMD];
__device__ __half g_wm2 [DIMD * MLPH];

// ---------------- qkv bias pack ----------------------------------------------------
__global__ void bias_pack_kernel(const float* __restrict__ qb, const float* __restrict__ kb,
                                 const float* __restrict__ vb)
{
    int i = blockIdx.x * 256 + threadIdx.x;
    float v = (i < 1024) ? qb[i] : ((i < 2048) ? kb[i - 1024] : vb[i - 2048]);
    g_bqkv[i] = v;
}

// ---------------- fused weight transpose+round (all weights, one launch) -----------
__global__ void tr_all_kernel(const float* __restrict__ q_w, const float* __restrict__ k_w,
                              const float* __restrict__ v_w, const float* __restrict__ o_w,
                              const float* __restrict__ ae2_w, const float* __restrict__ mod_w,
                              const float* __restrict__ m1_w, const float* __restrict__ m2_w)
{
    __shared__ float t[32][33];
    int id = blockIdx.x;
    const float* src;
    __half* dst;
    int ldsrc, Kd, n0, k0, noff = 0;
    bool modmap = false;

    if (id < 3072) {
        int j = id >> 10, tt = id & 1023;
        const float* sl[3] = {q_w, k_w, v_w};
        src = sl[j]; dst = g_wqkv; noff = j * 1024;
        ldsrc = 1024; Kd = 1024;
        n0 = (tt & 31) * 32; k0 = (tt >> 5) * 32;
    } else if (id < 5120) {
        int j = (id - 3072) >> 10, tt = id & 1023;
        src = j ? ae2_w : o_w; dst = j ? g_wae2 : g_wo;
        ldsrc = 1024; Kd = 1024;
        n0 = (tt & 31) * 32; k0 = (tt >> 5) * 32;
    } else if (id < 7168) {
        int tt = id - 5120;
        src = mod_w; dst = g_wmod;
        ldsrc = 4096; Kd = 1024;
        n0 = (tt & 63) * 32; k0 = (tt >> 6) * 32;
        modmap = true;
    } else if (id < 11264) {
        int tt = id - 7168;
        src = m1_w; dst = g_wm1;
        ldsrc = 4096; Kd = 1024;
        n0 = (tt & 127) * 32; k0 = (tt >> 7) * 32;
    } else {
        int tt = id - 11264;
        src = m2_w; dst = g_wm2;
        ldsrc = 1024; Kd = 4096;
        n0 = (tt & 31) * 32; k0 = (tt >> 5) * 32;
    }

    int tx = threadIdx.x, ty = threadIdx.y;
#pragma unroll
    for (int i = ty; i < 32; i += 8)
        t[i][tx] = src[(size_t)(k0 + i) * ldsrc + n0 + tx];
    __syncthreads();
#pragma unroll
    for (int i = ty; i < 32; i += 8) {
        int c = n0 + i;
        int n = modmap ? ((c < 1024) ? (2 * c) : (2 * (c - 1024) + 1)) : (noff + c);
        dst[(size_t)n * Kd + k0 + tx] = __float2half_rn(t[tx][i]);
    }
}

// ---------------- rmsnorm: float in -> half out ----------------------------------
__global__ void rmsnorm_kernel(const float* __restrict__ x,
                               const float* __restrict__ w,
                               __half* __restrict__ y)
{
    int row = blockIdx.x;
    const float* xr = x + (size_t)row * DIMD;
    float v[4];
    float s = 0.f;
#pragma unroll
    for (int i = 0; i < 4; i++) {
        v[i] = xr[threadIdx.x + i * 256];
        s += v[i] * v[i];
    }
#pragma unroll
    for (int o = 16; o > 0; o >>= 1) s += __shfl_xor_sync(0xffffffffu, s, o);
    __shared__ float red[8];
    if ((threadIdx.x & 31) == 0) red[threadIdx.x >> 5] = s;
    __syncthreads();
    if (threadIdx.x == 0) {
        float t = 0.f;
#pragma unroll
        for (int i = 0; i < 8; i++) t += red[i];
        red[0] = rsqrtf(t * (1.0f / DIMD) + 1e-6f);
    }
    __syncthreads();
    float r = red[0];
    __half* yr = y + (size_t)row * DIMD;
#pragma unroll
    for (int i = 0; i < 4; i++) {
        int c = threadIdx.x + i * 256;
        yr[c] = __float2half_rn(v[i] * r * w[c]);
    }
}

// ---------------- per-head rmsnorm on qkv buffer (q and k in one launch) -----------
__global__ void headnorm_kernel(__half* __restrict__ qkv,
                                const float* __restrict__ qw, const float* __restrict__ kw)
{
    int sel = blockIdx.y;
    const float* w = sel ? kw : qw;
    float scale = sel ? 1.0f : 0.125f;
    int gw   = (blockIdx.x * blockDim.x + threadIdx.x) >> 5;
    int lane = threadIdx.x & 31;
    if (gw >= BT * NH) return;
    int token = gw >> 4, head = gw & 15;
    __half* p = qkv + (size_t)token * QSTR + sel * 1024 + head * 64;
    float a = __half2float(p[lane]);
    float b = __half2float(p[lane + 32]);
    float s = a * a + b * b;
#pragma unroll
    for (int o = 16; o > 0; o >>= 1) s += __shfl_xor_sync(0xffffffffu, s, o);
    float r = rsqrtf(s * (1.0f / HD) + 1e-6f) * scale;
    p[lane]      = __float2half_rn(a * r * w[lane]);
    p[lane + 32] = __float2half_rn(b * r * w[lane + 32]);
}

// ---------------- ae1 (K=16): 8 rows/block, conflict-free lanes --------------------
__global__ void __launch_bounds__(256) ae1_kernel(
    const float* __restrict__ A, const float* __restrict__ W,
    const float* __restrict__ bias, __half* __restrict__ C)
{
    __shared__ float Ws[16 * 1024];
    __shared__ float As[8 * 16];
    int tid = threadIdx.x;
    for (int i = tid; i < 16 * 1024 / 4; i += 256)
        ((float4*)Ws)[i] = ((const float4*)W)[i];
    int brow = blockIdx.x * 8;
    if (tid < 32)
        ((float4*)As)[tid] = ((const float4*)(A + (size_t)brow * 16))[tid];
    __syncthreads();

    int r    = tid >> 5;          // 0..7 (row within block)
    int lane = tid & 31;
    float a[16];
#pragma unroll
    for (int kk = 0; kk < 16; kk++) a[kk] = As[r * 16 + kk];
    __half* Cr = C + (size_t)(brow + r) * 1024;

#pragma unroll
    for (int j = 0; j < 8; j++) {
        int col = lane * 4 + j * 128;     // lanes read consecutive float4s: no conflicts
        float4 o = make_float4(bias[col], bias[col + 1], bias[col + 2], bias[col + 3]);
#pragma unroll
        for (int kk = 0; kk < 16; kk++) {
            float4 wv = *(float4*)&Ws[kk * 1024 + col];
            o.x += a[kk] * wv.x; o.y += a[kk] * wv.y;
            o.z += a[kk] * wv.z; o.w += a[kk] * wv.w;
        }
        o.x = o.x / (1.f + expf(-o.x));
        o.y = o.y / (1.f + expf(-o.y));
        o.z = o.z / (1.f + expf(-o.z));
        o.w = o.w / (1.f + expf(-o.w));
        *(__half2*)&Cr[col]     = __floats2half2_rn(o.x, o.y);
        *(__half2*)&Cr[col + 2] = __floats2half2_rn(o.z, o.w);
    }
}

// ================= fp16 tensor-core GEMM 128x128x64, 3-stage + ldmatrix.x4 =========
#define EPI_NONE 0
#define EPI_SILU 1
#define EPI_GELU 2
#define EPI_RES  3
#define EPI_MOD  4

#define GBK 64
#define GSTR 72
#define HPS  (128 * GSTR)
#define HMMA_SMEM (3 * 2 * HPS * 2)           // 110592 B

__device__ __forceinline__ void cp16h(__half* s, const __half* g)
{
    uint32_t sa = (uint32_t)__cvta_generic_to_shared(s);
    asm volatile("cp.async.cg.shared.global [%0], [%1], 16;\n" :: "r"(sa), "l"(g));
}

__device__ __forceinline__ void mma_f16(float* c, const uint32_t* a, const uint32_t* b)
{
    asm volatile(
        "mma.sync.aligned.m16n8k16.row.col.f32.f16.f16.f32 "
        "{%0,%1,%2,%3},{%4,%5,%6,%7},{%8,%9},{%0,%1,%2,%3};"
        : "+f"(c[0]), "+f"(c[1]), "+f"(c[2]), "+f"(c[3])
        : "r"(a[0]), "r"(a[1]), "r"(a[2]), "r"(a[3]), "r"(b[0]), "r"(b[1]));
}

__device__ __forceinline__ void ldm_x4(uint32_t* r, const __half* p)
{
    uint32_t addr = (uint32_t)__cvta_generic_to_shared(p);
    asm volatile("ldmatrix.sync.aligned.m8n8.x4.shared.b16 {%0,%1,%2,%3}, [%4];"
                 : "=r"(r[0]), "=r"(r[1]), "=r"(r[2]), "=r"(r[3]) : "r"(addr));
}

__device__ __forceinline__ void ldm_x2(uint32_t* r, const __half* p)
{
    uint32_t addr = (uint32_t)__cvta_generic_to_shared(p);
    asm volatile("ldmatrix.sync.aligned.m8n8.x2.shared.b16 {%0,%1}, [%2];"
                 : "=r"(r[0]), "=r"(r[1]) : "r"(addr));
}

template<int EPI, int HOUT>
__global__ void __launch_bounds__(256, 2) hmma_kernel(
    const __half* __restrict__ A, const __half* __restrict__ Wt,
    const float* __restrict__ bias, const float* __restrict__ Res,
    void* __restrict__ Cv, int M, int N, int K)
{
    extern __shared__ __half hsm[];
    __half* Asm = hsm;
    __half* Bsm = hsm + 3 * HPS;

    int tid  = threadIdx.x;
    int brow = blockIdx.y * 128;
    int bcol = blockIdx.x * 128;
    int warp = tid >> 5, lane = tid & 31;
    int g = lane >> 2, t = lane & 3;
    int wr = warp & 1, wc = warp >> 1;

    int r0u = tid >> 3, c0u = (tid & 7) << 3;
    const __half* Agb = A  + (size_t)(brow + r0u) * K + c0u;
    const __half* Bgb = Wt + (size_t)(bcol + r0u) * K + c0u;

    int a_row  = wr * 64 + (lane & 15);
    int a_koff = (lane >> 4) << 3;
    int b_row  = wc * 32 + ((lane >> 4) << 3) + (lane & 7);
    int b_koff = ((lane >> 3) & 1) << 3;

    float acc[4][4][4];
#pragma unroll
    for (int i = 0; i < 4; i++)
#pragma unroll
        for (int j = 0; j < 4; j++)
#pragma unroll
            for (int c = 0; c < 4; c++) acc[i][j][c] = 0.f;

    int nk = K / GBK;

#pragma unroll
    for (int s = 0; s < 2; s++) {
        int kc = s * GBK;
#pragma unroll
        for (int p = 0; p < 4; p++) {
            cp16h(&Asm[s * HPS + (r0u + 32 * p) * GSTR + c0u], Agb + (size_t)32 * p * K + kc);
            cp16h(&Bsm[s * HPS + (r0u + 32 * p) * GSTR + c0u], Bgb + (size_t)32 * p * K + kc);
        }
        asm volatile("cp.async.commit_group;");
    }

    int st = 0;
    for (int i = 0; i < nk; i++) {
        asm volatile("cp.async.wait_group 1;" ::: "memory");
        __syncthreads();

        if (i + 2 < nk) {
            int kc = (i + 2) * GBK;
            int s2 = st + 2; if (s2 >= 3) s2 -= 3;
#pragma unroll
            for (int p = 0; p < 4; p++) {
                cp16h(&Asm[s2 * HPS + (r0u + 32 * p) * GSTR + c0u], Agb + (size_t)32 * p * K + kc);
                cp16h(&Bsm[s2 * HPS + (r0u + 32 * p) * GSTR + c0u], Bgb + (size_t)32 * p * K + kc);
            }
        }
        asm volatile("cp.async.commit_group;");

        const __half* Sb = &Asm[st * HPS];
        const __half* Tb = &Bsm[st * HPS];
#pragma unroll
        for (int ks = 0; ks < 4; ks++) {
            int k0 = ks * 16;
            uint32_t af[4][4], bf[4][2];
#pragma unroll
            for (int ti = 0; ti < 4; ti++)
                ldm_x4(af[ti], Sb + (a_row + ti * 16) * GSTR + k0 + a_koff);
#pragma unroll
            for (int tp = 0; tp < 2; tp++)
                ldm_x4(&bf[2 * tp][0], Tb + (b_row + tp * 16) * GSTR + k0 + b_koff);
#pragma unroll
            for (int ti = 0; ti < 4; ti++)
#pragma unroll
                for (int tj = 0; tj < 4; tj++)
                    mma_f16(acc[ti][tj], af[ti], bf[tj]);
        }
        if (++st == 3) st = 0;
    }

#pragma unroll
    for (int ti = 0; ti < 4; ti++) {
        int r0 = brow + wr * 64 + ti * 16 + g;
#pragma unroll
        for (int tj = 0; tj < 4; tj++) {
            int c0 = bcol + wc * 32 + tj * 8 + 2 * t;
#pragma unroll
            for (int half_i = 0; half_i < 2; half_i++) {
                int row = r0 + half_i * 8;
                float vx = acc[ti][tj][half_i * 2 + 0];
                float vy = acc[ti][tj][half_i * 2 + 1];
                if (EPI == EPI_MOD) {
                    int j = c0 >> 1;
                    float shift = vx + bias[j];
                    float scale = vy + bias[1024 + j];
                    float res = Res[(size_t)row * (N >> 1) + j];
                    ((float*)Cv)[(size_t)row * (N >> 1) + j] = res * (1.f + scale) + shift;
                    continue;
                }
                vx += bias[c0]; vy += bias[c0 + 1];
                if (EPI == EPI_SILU) {
                    vx = vx / (1.f + expf(-vx));
                    vy = vy / (1.f + expf(-vy));
                } else if (EPI == EPI_GELU) {
                    const float cst = 0.70710678118654752f;
                    vx = 0.5f * vx * (1.f + erff(vx * cst));
                    vy = 0.5f * vy * (1.f + erff(vy * cst));
                } else if (EPI == EPI_RES) {
                    float2 rv = *(const float2*)&Res[(size_t)row * N + c0];
                    vx += rv.x; vy += rv.y;
                }
                if (HOUT) {
                    *(__half2*)((__half*)Cv + (size_t)row * N + c0) = __floats2half2_rn(vx, vy);
                } else {
                    *(float2*)((float*)Cv + (size_t)row * N + c0) = make_float2(vx, vy);
                }
            }
        }
    }
}

// ---------------- fp16 flash attention, 64x64 tiles, cp.async double-buffered -----
#define AST 72
#define ATT_SMEM ((6 * 64 * AST) * 2 + 1024)

__global__ void __launch_bounds__(256) attn_mma_kernel(
    const __half* __restrict__ QKV, __half* __restrict__ O)
{
    extern __shared__ __half asm_[];
    __half* Qs = asm_;
    __half* Ks = Qs + 64 * AST;
    __half* Vs = Ks + 2 * 64 * AST;
    __half* Ps = Vs + 2 * 64 * AST;
    float* redM = (float*)(Ps + 64 * AST);
    float* redL = redM + 128;

    int tid = threadIdx.x, warp = tid >> 5, lane = tid & 31;
    int g = lane >> 2, t = lane & 3;
    int wr = warp & 3, wc = warp >> 2;
    int qt = (TT / 64 - 1) - blockIdx.x;
    int bh = blockIdx.y, b = bh >> 4, h = bh & 15;

    const __half* Qg = QKV + (size_t)b * TT * QSTR + (size_t)h * HD;
    const __half* Kg = Qg + 1024;
    const __half* Vg = Qg + 2048;

    int lrow = tid >> 2;
    int ld16 = (tid & 3) << 4;

    {
        const __half* src = Qg + (size_t)(qt * 64 + lrow) * QSTR + ld16;
        *(uint4*)&Qs[lrow * AST + ld16]     = *(const uint4*)(src);
        *(uint4*)&Qs[lrow * AST + ld16 + 8] = *(const uint4*)(src + 8);
    }

    {
        const __half* kp = Kg + (size_t)lrow * QSTR + ld16;
        const __half* vp = Vg + (size_t)lrow * QSTR + ld16;
        cp16h(&Ks[lrow * AST + ld16],     kp);
        cp16h(&Ks[lrow * AST + ld16 + 8], kp + 8);
        cp16h(&Vs[lrow * AST + ld16],     vp);
        cp16h(&Vs[lrow * AST + ld16 + 8], vp + 8);
        asm volatile("cp.async.commit_group;");
    }
    __syncthreads();

    int r0 = wr * 16 + g;
    uint32_t qf[4][4];
#pragma unroll
    for (int ks = 0; ks < 4; ks++) {
        int k0 = ks * 16;
        qf[ks][0] = *(const uint32_t*)&Qs[(r0)     * AST + k0 + 2 * t];
        qf[ks][1] = *(const uint32_t*)&Qs[(r0 + 8) * AST + k0 + 2 * t];
        qf[ks][2] = *(const uint32_t*)&Qs[(r0)     * AST + k0 + 2 * t + 8];
        qf[ks][3] = *(const uint32_t*)&Qs[(r0 + 8) * AST + k0 + 2 * t + 8];
    }

    int kln = lane & 7, klk = ((lane >> 3) & 1) * 8;
    int vlk = lane & 15;

    float m0 = -1e30f, m1 = -1e30f, l0 = 0.f, l1 = 0.f;
    float acc[4][4];
#pragma unroll
    for (int tj = 0; tj < 4; tj++)
#pragma unroll
        for (int c = 0; c < 4; c++) acc[tj][c] = 0.f;

    for (int kt = 0; kt <= qt; kt++) {
        int cur = kt & 1;
        asm volatile("cp.async.wait_group 0;" ::: "memory");
        __syncthreads();

        if (kt + 1 <= qt) {
            int nxt = cur ^ 1;
            const __half* kp = Kg + (size_t)((kt + 1) * 64 + lrow) * QSTR + ld16;
            const __half* vp = Vg + (size_t)((kt + 1) * 64 + lrow) * QSTR + ld16;
            cp16h(&Ks[nxt * 64 * AST + lrow * AST + ld16],     kp);
            cp16h(&Ks[nxt * 64 * AST + lrow * AST + ld16 + 8], kp + 8);
            cp16h(&Vs[nxt * 64 * AST + lrow * AST + ld16],     vp);
            cp16h(&Vs[nxt * 64 * AST + lrow * AST + ld16 + 8], vp + 8);
        }
        asm volatile("cp.async.commit_group;");

        const __half* Kc = Ks + cur * 64 * AST;
        const __half* Vc = Vs + cur * 64 * AST;

        float s[4][4];
#pragma unroll
        for (int tj = 0; tj < 4; tj++)
#pragma unroll
            for (int c = 0; c < 4; c++) s[tj][c] = 0.f;
#pragma unroll
        for (int ks = 0; ks < 4; ks++) {
            int k0 = ks * 16;
#pragma unroll
            for (int tj = 0; tj < 4; tj++) {
                int n0 = wc * 32 + tj * 8;
                uint32_t bf[2];
                ldm_x2(bf, Kc + (n0 + kln) * AST + k0 + klk);
                mma_f16(s[tj], qf[ks], bf);
            }
        }

        if (kt == qt) {
#pragma unroll
            for (int tj = 0; tj < 4; tj++) {
                int c0 = wc * 32 + tj * 8 + 2 * t;
                if (c0     > r0)     s[tj][0] = -1e30f;
                if (c0 + 1 > r0)     s[tj][1] = -1e30f;
                if (c0     > r0 + 8) s[tj][2] = -1e30f;
                if (c0 + 1 > r0 + 8) s[tj][3] = -1e30f;
            }
        }

        float rm0 = -1e30f, rm1 = -1e30f;
#pragma unroll
        for (int tj = 0; tj < 4; tj++) {
            rm0 = fmaxf(rm0, fmaxf(s[tj][0], s[tj][1]));
            rm1 = fmaxf(rm1, fmaxf(s[tj][2], s[tj][3]));
        }
#pragma unroll
        for (int o = 1; o < 4; o <<= 1) {
            rm0 = fmaxf(rm0, __shfl_xor_sync(0xffffffffu, rm0, o));
            rm1 = fmaxf(rm1, __shfl_xor_sync(0xffffffffu, rm1, o));
        }
        if (t == 0) {
            redM[wc * 64 + r0]     = rm0;
            redM[wc * 64 + r0 + 8] = rm1;
        }
        __syncthreads();
        float nm0 = fmaxf(m0, fmaxf(redM[r0],     redM[64 + r0]));
        float nm1 = fmaxf(m1, fmaxf(redM[r0 + 8], redM[64 + r0 + 8]));
        float a0 = __expf(m0 - nm0), a1 = __expf(m1 - nm1);
        m0 = nm0; m1 = nm1;

        float ls0 = 0.f, ls1 = 0.f;
#pragma unroll
        for (int tj = 0; tj < 4; tj++) {
            s[tj][0] = __expf(s[tj][0] - nm0);
            s[tj][1] = __expf(s[tj][1] - nm0);
            s[tj][2] = __expf(s[tj][2] - nm1);
            s[tj][3] = __expf(s[tj][3] - nm1);
            ls0 += s[tj][0] + s[tj][1];
            ls1 += s[tj][2] + s[tj][3];
        }
#pragma unroll
        for (int o = 1; o < 4; o <<= 1) {
            ls0 += __shfl_xor_sync(0xffffffffu, ls0, o);
            ls1 += __shfl_xor_sync(0xffffffffu, ls1, o);
        }
        if (t == 0) {
            redL[wc * 64 + r0]     = ls0;
            redL[wc * 64 + r0 + 8] = ls1;
        }
#pragma unroll
        for (int tj = 0; tj < 4; tj++) {
            int c0 = wc * 32 + tj * 8 + 2 * t;
            *(__half2*)&Ps[(r0)     * AST + c0] = __floats2half2_rn(s[tj][0], s[tj][1]);
            *(__half2*)&Ps[(r0 + 8) * AST + c0] = __floats2half2_rn(s[tj][2], s[tj][3]);
        }
        __syncthreads();

        l0 = l0 * a0 + redL[r0]     + redL[64 + r0];
        l1 = l1 * a1 + redL[r0 + 8] + redL[64 + r0 + 8];
#pragma unroll
        for (int tj = 0; tj < 4; tj++) {
            acc[tj][0] *= a0; acc[tj][1] *= a0;
            acc[tj][2] *= a1; acc[tj][3] *= a1;
        }

#pragma unroll
        for (int ks = 0; ks < 4; ks++) {
            int k0 = ks * 16;
            uint32_t pf[4];
            pf[0] = *(const uint32_t*)&Ps[(r0)     * AST + k0 + 2 * t];
            pf[1] = *(const uint32_t*)&Ps[(r0 + 8) * AST + k0 + 2 * t];
            pf[2] = *(const uint32_t*)&Ps[(r0)     * AST + k0 + 2 * t + 8];
            pf[3] = *(const uint32_t*)&Ps[(r0 + 8) * AST + k0 + 2 * t + 8];
#pragma unroll
            for (int tj = 0; tj < 4; tj++) {
                int n0 = wc * 32 + tj * 8;
                uint32_t bf[2];
                uint32_t addr = (uint32_t)__cvta_generic_to_shared(
                    &Vc[(k0 + vlk) * AST + n0]);
                asm volatile("ldmatrix.sync.aligned.m8n8.x2.trans.shared.b16 {%0,%1}, [%2];"
                             : "=r"(bf[0]), "=r"(bf[1]) : "r"(addr));
                mma_f16(acc[tj], pf, bf);
            }
        }
    }

    float inv0 = 1.f / l0, inv1 = 1.f / l1;
    __half* Og = O + (size_t)b * TT * DIMD + (size_t)(qt * 64) * DIMD + (size_t)h * HD;
#pragma unroll
    for (int tj = 0; tj < 4; tj++) {
        int c0 = wc * 32 + tj * 8 + 2 * t;
        *(__half2*)&Og[(size_t)(r0)     * DIMD + c0] = __floats2half2_rn(acc[tj][0] * inv0, acc[tj][1] * inv0);
        *(__half2*)&Og[(size_t)(r0 + 8) * DIMD + c0] = __floats2half2_rn(acc[tj][2] * inv1, acc[tj][3] * inv1);
    }
}

// ------------------------------- launch --------------------------------------------
extern "C" void kernel_launch(void* const* d_in, const int* in_sizes, int n_in,
                              void* d_out, int out_size)
{
    const float* x       = (const float*)d_in[0];
    const float* actions = (const float*)d_in[1];
    const float* n1_w    = (const float*)d_in[2];
    const float* n2_w    = (const float*)d_in[3];
    const float* q_w     = (const float*)d_in[4];
    const float* q_b     = (const float*)d_in[5];
    const float* k_w     = (const float*)d_in[6];
    const float* k_b     = (const float*)d_in[7];
    const float* v_w     = (const float*)d_in[8];
    const float* v_b     = (const float*)d_in[9];
    const float* qn_w    = (const float*)d_in[10];
    const float* kn_w    = (const float*)d_in[11];
    const float* o_w     = (const float*)d_in[12];
    const float* o_b     = (const float*)d_in[13];
    const float* ae1_w   = (const float*)d_in[14];
    const float* ae1_b   = (const float*)d_in[15];
    const float* ae2_w   = (const float*)d_in[16];
    const float* ae2_b   = (const float*)d_in[17];
    const float* mod_w   = (const float*)d_in[18];
    const float* mod_b   = (const float*)d_in[19];
    const float* m1_w    = (const float*)d_in[20];
    const float* m1_b    = (const float*)d_in[21];
    const float* m2_w    = (const float*)d_in[22];
    const float* m2_b    = (const float*)d_in[23];
    float* out           = (float*)d_out;

    __half *h, *a1, *qkv, *ao, *ae, *hid;
    float *x1, *bqkv;
    __half *wqkv, *wo, *wae2, *wmod, *wm1, *wm2;
    cudaGetSymbolAddress((void**)&h,    g_h);
    cudaGetSymbolAddress((void**)&a1,   g_a1);
    cudaGetSymbolAddress((void**)&qkv,  g_qkv);
    cudaGetSymbolAddress((void**)&ao,   g_ao);
    cudaGetSymbolAddress((void**)&ae,   g_ae);
    cudaGetSymbolAddress((void**)&hid,  g_hid);
    cudaGetSymbolAddress((void**)&x1,   g_x1);
    cudaGetSymbolAddress((void**)&bqkv, g_bqkv);
    cudaGetSymbolAddress((void**)&wqkv, g_wqkv);
    cudaGetSymbolAddress((void**)&wo,   g_wo);
    cudaGetSymbolAddress((void**)&wae2, g_wae2);
    cudaGetSymbolAddress((void**)&wmod, g_wmod);
    cudaGetSymbolAddress((void**)&wm1,  g_wm1);
    cudaGetSymbolAddress((void**)&wm2,  g_wm2);

    static int attr_set = 0;
    if (!attr_set) {
        cudaFuncSetAttribute((const void*)hmma_kernel<EPI_NONE, 1>, cudaFuncAttributeMaxDynamicSharedMemorySize, HMMA_SMEM);
        cudaFuncSetAttribute((const void*)hmma_kernel<EPI_SILU, 1>, cudaFuncAttributeMaxDynamicSharedMemorySize, HMMA_SMEM);
        cudaFuncSetAttribute((const void*)hmma_kernel<EPI_GELU, 1>, cudaFuncAttributeMaxDynamicSharedMemorySize, HMMA_SMEM);
        cudaFuncSetAttribute((const void*)hmma_kernel<EPI_RES,  0>, cudaFuncAttributeMaxDynamicSharedMemorySize, HMMA_SMEM);
        cudaFuncSetAttribute((const void*)hmma_kernel<EPI_MOD,  0>, cudaFuncAttributeMaxDynamicSharedMemorySize, HMMA_SMEM);
        cudaFuncSetAttribute((const void*)attn_mma_kernel, cudaFuncAttributeMaxDynamicSharedMemorySize, ATT_SMEM);
        attr_set = 1;
    }

    dim3 g1024(8, 32);
    dim3 g2048(16, 32);
    dim3 g3072(24, 32);
    dim3 g4096(32, 32);

    // 1) pack qkv bias
    bias_pack_kernel<<<12, 256>>>(q_b, k_b, v_b);
    // 2) all weight transposes, one launch
    tr_all_kernel<<<15360, dim3(32, 8)>>>(q_w, k_w, v_w, o_w, ae2_w, mod_w, m1_w, m2_w);
    // 3) h = rmsnorm(x, n1_w)
    rmsnorm_kernel<<<BT, 256>>>(x, n1_w, h);
    // 4) a1 = silu(actions @ ae1_w + ae1_b)  (parallelized: 512 blocks)
    ae1_kernel<<<BT / 8, 256>>>(actions, ae1_w, ae1_b, a1);
    // 5) ae = silu(a1 @ ae2_w + ae2_b)
    hmma_kernel<EPI_SILU, 1><<<g1024, 256, HMMA_SMEM>>>(a1, wae2, ae2_b, nullptr, ae, BT, DIMD, DIMD);
    // 6) fused qkv projection
    hmma_kernel<EPI_NONE, 1><<<g3072, 256, HMMA_SMEM>>>(h, wqkv, bqkv, nullptr, qkv, BT, QSTR, DIMD);
    // 7) QK head norms
    headnorm_kernel<<<dim3((BT * NH) / 8, 2), 256>>>(qkv, qn_w, kn_w);
    // 8) attention
    attn_mma_kernel<<<dim3(TT / 64, 2 * NH), 256, ATT_SMEM>>>(qkv, ao);
    // 9) x1 = x + ao @ o_w + o_b
    hmma_kernel<EPI_RES, 0><<<g1024, 256, HMMA_SMEM>>>(ao, wo, o_b, x, x1, BT, DIMD, DIMD);
    // 10) fused modulate GEMM
    hmma_kernel<EPI_MOD, 0><<<g2048, 256, HMMA_SMEM>>>(ae, wmod, mod_b, x1, x1, BT, 2048, DIMD);
    // 11) h = rmsnorm(x1, n2_w)
    rmsnorm_kernel<<<BT, 256>>>(x1, n2_w, h);
    // 12) hid = gelu(h @ m1_w + m1_b)
    hmma_kernel<EPI_GELU, 1><<<g4096, 256, HMMA_SMEM>>>(h, wm1, m1_b, nullptr, hid, BT, MLPH, DIMD);
    // 13) out = x1 + hid @ m2_w + m2_b
    hmma_kernel<EPI_RES, 0><<<g1024, 256, HMMA_SMEM>>>(hid, wm2, m2_b, x1, out, BT, DIMD, MLPH);
}

// round 11
// speedup vs baseline: 6.0619x; 1.0220x over previous
#include <cuda_runtime.h>
#include <cuda_fp16.h>
#include <math.h>
#include <stdint.h>

#define BT    4096
#define DIMD  1024
#define NH    16
#define HD    64
#define TT    2048
#define MLPH  4096
#define QSTR  3072

// ---------------- scratch -------------------------------------------------------
__device__ __half g_h  [BT * DIMD];
__device__ __half g_a1 [BT * DIMD];
__device__ __half g_qkv[BT * QSTR];
__device__ __half g_ao [BT * DIMD];
__device__ __half g_ae [BT * DIMD];
__device__ __half g_hid[BT * MLPH];
__device__ float  g_x1 [BT * DIMD];
__device__ float  g_bqkv[QSTR];
// transposed ([N][K]) fp16 weights
__device__ __half g_wqkv[QSTR * DIMD];
__device__ __half g_wo  [DIMD * DIMD];
__device__ __half g_wae2[DIMD * DIMD];
__device__ __half g_wmod[2048 * DIMD];
__device__ __half g_wm1 [MLPH * DIMD];
__device__ __half g_wm2 [DIMD * MLPH];

// ---------------- qkv bias pack ----------------------------------------------------
__global__ void bias_pack_kernel(const float* __restrict__ qb, const float* __restrict__ kb,
                                 const float* __restrict__ vb)
{
    int i = blockIdx.x * 256 + threadIdx.x;
    float v = (i < 1024) ? qb[i] : ((i < 2048) ? kb[i - 1024] : vb[i - 2048]);
    g_bqkv[i] = v;
}

// ---------------- fused weight transpose+round (all weights, one launch) -----------
__global__ void tr_all_kernel(const float* __restrict__ q_w, const float* __restrict__ k_w,
                              const float* __restrict__ v_w, const float* __restrict__ o_w,
                              const float* __restrict__ ae2_w, const float* __restrict__ mod_w,
                              const float* __restrict__ m1_w, const float* __restrict__ m2_w)
{
    __shared__ float t[32][33];
    int id = blockIdx.x;
    const float* src;
    __half* dst;
    int ldsrc, Kd, n0, k0, noff = 0;
    bool modmap = false;

    if (id < 3072) {
        int j = id >> 10, tt = id & 1023;
        const float* sl[3] = {q_w, k_w, v_w};
        src = sl[j]; dst = g_wqkv; noff = j * 1024;
        ldsrc = 1024; Kd = 1024;
        n0 = (tt & 31) * 32; k0 = (tt >> 5) * 32;
    } else if (id < 5120) {
        int j = (id - 3072) >> 10, tt = id & 1023;
        src = j ? ae2_w : o_w; dst = j ? g_wae2 : g_wo;
        ldsrc = 1024; Kd = 1024;
        n0 = (tt & 31) * 32; k0 = (tt >> 5) * 32;
    } else if (id < 7168) {
        int tt = id - 5120;
        src = mod_w; dst = g_wmod;
        ldsrc = 4096; Kd = 1024;
        n0 = (tt & 63) * 32; k0 = (tt >> 6) * 32;
        modmap = true;
    } else if (id < 11264) {
        int tt = id - 7168;
        src = m1_w; dst = g_wm1;
        ldsrc = 4096; Kd = 1024;
        n0 = (tt & 127) * 32; k0 = (tt >> 7) * 32;
    } else {
        int tt = id - 11264;
        src = m2_w; dst = g_wm2;
        ldsrc = 1024; Kd = 4096;
        n0 = (tt & 31) * 32; k0 = (tt >> 5) * 32;
    }

    int tx = threadIdx.x, ty = threadIdx.y;
#pragma unroll
    for (int i = ty; i < 32; i += 8)
        t[i][tx] = src[(size_t)(k0 + i) * ldsrc + n0 + tx];
    __syncthreads();
#pragma unroll
    for (int i = ty; i < 32; i += 8) {
        int c = n0 + i;
        int n = modmap ? ((c < 1024) ? (2 * c) : (2 * (c - 1024) + 1)) : (noff + c);
        dst[(size_t)n * Kd + k0 + tx] = __float2half_rn(t[tx][i]);
    }
}

// ---------------- rmsnorm: float in -> half out ----------------------------------
__global__ void rmsnorm_kernel(const float* __restrict__ x,
                               const float* __restrict__ w,
                               __half* __restrict__ y)
{
    int row = blockIdx.x;
    const float* xr = x + (size_t)row * DIMD;
    float v[4];
    float s = 0.f;
#pragma unroll
    for (int i = 0; i < 4; i++) {
        v[i] = xr[threadIdx.x + i * 256];
        s += v[i] * v[i];
    }
#pragma unroll
    for (int o = 16; o > 0; o >>= 1) s += __shfl_xor_sync(0xffffffffu, s, o);
    __shared__ float red[8];
    if ((threadIdx.x & 31) == 0) red[threadIdx.x >> 5] = s;
    __syncthreads();
    if (threadIdx.x == 0) {
        float t = 0.f;
#pragma unroll
        for (int i = 0; i < 8; i++) t += red[i];
        red[0] = rsqrtf(t * (1.0f / DIMD) + 1e-6f);
    }
    __syncthreads();
    float r = red[0];
    __half* yr = y + (size_t)row * DIMD;
#pragma unroll
    for (int i = 0; i < 4; i++) {
        int c = threadIdx.x + i * 256;
        yr[c] = __float2half_rn(v[i] * r * w[c]);
    }
}

// ---------------- per-head rmsnorm on qkv buffer ------------------------------------
__global__ void headnorm_kernel(__half* __restrict__ qkv,
                                const float* __restrict__ qw, const float* __restrict__ kw)
{
    int sel = blockIdx.y;
    const float* w = sel ? kw : qw;
    float scale = sel ? 1.0f : 0.125f;
    int gw   = (blockIdx.x * blockDim.x + threadIdx.x) >> 5;
    int lane = threadIdx.x & 31;
    if (gw >= BT * NH) return;
    int token = gw >> 4, head = gw & 15;
    __half* p = qkv + (size_t)token * QSTR + sel * 1024 + head * 64;
    float a = __half2float(p[lane]);
    float b = __half2float(p[lane + 32]);
    float s = a * a + b * b;
#pragma unroll
    for (int o = 16; o > 0; o >>= 1) s += __shfl_xor_sync(0xffffffffu, s, o);
    float r = rsqrtf(s * (1.0f / HD) + 1e-6f) * scale;
    p[lane]      = __float2half_rn(a * r * w[lane]);
    p[lane + 32] = __float2half_rn(b * r * w[lane + 32]);
}

// ---------------- ae1 (K=16): 32 rows x 256 cols per block --------------------------
__global__ void __launch_bounds__(256) ae1_kernel(
    const float* __restrict__ A, const float* __restrict__ W,
    const float* __restrict__ bias, __half* __restrict__ C)
{
    __shared__ float Ws[16 * 256];
    __shared__ float As[32 * 16];
    int tid = threadIdx.x;
    int colbase = blockIdx.y * 256;
    for (int i = tid; i < 1024; i += 256) {
        int row = i >> 6, c4 = (i & 63) << 2;
        *(float4*)&Ws[row * 256 + c4] = *(const float4*)&W[(size_t)row * 1024 + colbase + c4];
    }
    int brow = blockIdx.x * 32;
    if (tid < 128)
        ((float4*)As)[tid] = ((const float4*)(A + (size_t)brow * 16))[tid];
    __syncthreads();

    int r = tid >> 3, lane8 = tid & 7;
    float a[16];
#pragma unroll
    for (int kk = 0; kk < 16; kk++) a[kk] = As[r * 16 + kk];
    __half* Cr = C + (size_t)(brow + r) * 1024 + colbase;

#pragma unroll
    for (int j = 0; j < 8; j++) {                 // FIX: 8 iterations x 32-col stride = 256 cols
        int col = lane8 * 4 + j * 32;
        float4 o = make_float4(bias[colbase + col],     bias[colbase + col + 1],
                               bias[colbase + col + 2], bias[colbase + col + 3]);
#pragma unroll
        for (int kk = 0; kk < 16; kk++) {
            float4 wv = *(float4*)&Ws[kk * 256 + col];
            o.x += a[kk] * wv.x; o.y += a[kk] * wv.y;
            o.z += a[kk] * wv.z; o.w += a[kk] * wv.w;
        }
        o.x = o.x / (1.f + expf(-o.x));
        o.y = o.y / (1.f + expf(-o.y));
        o.z = o.z / (1.f + expf(-o.z));
        o.w = o.w / (1.f + expf(-o.w));
        *(__half2*)&Cr[col]     = __floats2half2_rn(o.x, o.y);
        *(__half2*)&Cr[col + 2] = __floats2half2_rn(o.z, o.w);
    }
}

// ================= fp16 tensor-core GEMM 128x128x64 (unchanged, known good) ========
#define EPI_NONE 0
#define EPI_SILU 1
#define EPI_GELU 2
#define EPI_RES  3
#define EPI_MOD  4

#define GBK 64
#define GSTR 72
#define HPS  (128 * GSTR)
#define HMMA_SMEM (3 * 2 * HPS * 2)

__device__ __forceinline__ void cp16h(__half* s, const __half* g)
{
    uint32_t sa = (uint32_t)__cvta_generic_to_shared(s);
    asm volatile("cp.async.cg.shared.global [%0], [%1], 16;\n" :: "r"(sa), "l"(g));
}

__device__ __forceinline__ void mma_f16(float* c, const uint32_t* a, const uint32_t* b)
{
    asm volatile(
        "mma.sync.aligned.m16n8k16.row.col.f32.f16.f16.f32 "
        "{%0,%1,%2,%3},{%4,%5,%6,%7},{%8,%9},{%0,%1,%2,%3};"
        : "+f"(c[0]), "+f"(c[1]), "+f"(c[2]), "+f"(c[3])
        : "r"(a[0]), "r"(a[1]), "r"(a[2]), "r"(a[3]), "r"(b[0]), "r"(b[1]));
}

__device__ __forceinline__ void ldm_x4(uint32_t* r, const __half* p)
{
    uint32_t addr = (uint32_t)__cvta_generic_to_shared(p);
    asm volatile("ldmatrix.sync.aligned.m8n8.x4.shared.b16 {%0,%1,%2,%3}, [%4];"
                 : "=r"(r[0]), "=r"(r[1]), "=r"(r[2]), "=r"(r[3]) : "r"(addr));
}

__device__ __forceinline__ void ldm_x4t(uint32_t* r, const __half* p)
{
    uint32_t addr = (uint32_t)__cvta_generic_to_shared(p);
    asm volatile("ldmatrix.sync.aligned.m8n8.x4.trans.shared.b16 {%0,%1,%2,%3}, [%4];"
                 : "=r"(r[0]), "=r"(r[1]), "=r"(r[2]), "=r"(r[3]) : "r"(addr));
}

template<int EPI, int HOUT>
__global__ void __launch_bounds__(256, 2) hmma_kernel(
    const __half* __restrict__ A, const __half* __restrict__ Wt,
    const float* __restrict__ bias, const float* __restrict__ Res,
    void* __restrict__ Cv, int M, int N, int K)
{
    extern __shared__ __half hsm[];
    __half* Asm = hsm;
    __half* Bsm = hsm + 3 * HPS;

    int tid  = threadIdx.x;
    int brow = blockIdx.y * 128;
    int bcol = blockIdx.x * 128;
    int warp = tid >> 5, lane = tid & 31;
    int g = lane >> 2, t = lane & 3;
    int wr = warp & 1, wc = warp >> 1;

    int r0u = tid >> 3, c0u = (tid & 7) << 3;
    const __half* Agb = A  + (size_t)(brow + r0u) * K + c0u;
    const __half* Bgb = Wt + (size_t)(bcol + r0u) * K + c0u;

    int a_row  = wr * 64 + (lane & 15);
    int a_koff = (lane >> 4) << 3;
    int b_row  = wc * 32 + ((lane >> 4) << 3) + (lane & 7);
    int b_koff = ((lane >> 3) & 1) << 3;

    float acc[4][4][4];
#pragma unroll
    for (int i = 0; i < 4; i++)
#pragma unroll
        for (int j = 0; j < 4; j++)
#pragma unroll
            for (int c = 0; c < 4; c++) acc[i][j][c] = 0.f;

    int nk = K / GBK;

#pragma unroll
    for (int s = 0; s < 2; s++) {
        int kc = s * GBK;
#pragma unroll
        for (int p = 0; p < 4; p++) {
            cp16h(&Asm[s * HPS + (r0u + 32 * p) * GSTR + c0u], Agb + (size_t)32 * p * K + kc);
            cp16h(&Bsm[s * HPS + (r0u + 32 * p) * GSTR + c0u], Bgb + (size_t)32 * p * K + kc);
        }
        asm volatile("cp.async.commit_group;");
    }

    int st = 0;
    for (int i = 0; i < nk; i++) {
        asm volatile("cp.async.wait_group 1;" ::: "memory");
        __syncthreads();

        if (i + 2 < nk) {
            int kc = (i + 2) * GBK;
            int s2 = st + 2; if (s2 >= 3) s2 -= 3;
#pragma unroll
            for (int p = 0; p < 4; p++) {
                cp16h(&Asm[s2 * HPS + (r0u + 32 * p) * GSTR + c0u], Agb + (size_t)32 * p * K + kc);
                cp16h(&Bsm[s2 * HPS + (r0u + 32 * p) * GSTR + c0u], Bgb + (size_t)32 * p * K + kc);
            }
        }
        asm volatile("cp.async.commit_group;");

        const __half* Sb = &Asm[st * HPS];
        const __half* Tb = &Bsm[st * HPS];
#pragma unroll
        for (int ks = 0; ks < 4; ks++) {
            int k0 = ks * 16;
            uint32_t af[4][4], bf[4][2];
#pragma unroll
            for (int ti = 0; ti < 4; ti++)
                ldm_x4(af[ti], Sb + (a_row + ti * 16) * GSTR + k0 + a_koff);
#pragma unroll
            for (int tp = 0; tp < 2; tp++)
                ldm_x4(&bf[2 * tp][0], Tb + (b_row + tp * 16) * GSTR + k0 + b_koff);
#pragma unroll
            for (int ti = 0; ti < 4; ti++)
#pragma unroll
                for (int tj = 0; tj < 4; tj++)
                    mma_f16(acc[ti][tj], af[ti], bf[tj]);
        }
        if (++st == 3) st = 0;
    }

#pragma unroll
    for (int ti = 0; ti < 4; ti++) {
        int r0 = brow + wr * 64 + ti * 16 + g;
#pragma unroll
        for (int tj = 0; tj < 4; tj++) {
            int c0 = bcol + wc * 32 + tj * 8 + 2 * t;
#pragma unroll
            for (int half_i = 0; half_i < 2; half_i++) {
                int row = r0 + half_i * 8;
                float vx = acc[ti][tj][half_i * 2 + 0];
                float vy = acc[ti][tj][half_i * 2 + 1];
                if (EPI == EPI_MOD) {
                    int j = c0 >> 1;
                    float shift = vx + bias[j];
                    float scale = vy + bias[1024 + j];
                    float res = Res[(size_t)row * (N >> 1) + j];
                    ((float*)Cv)[(size_t)row * (N >> 1) + j] = res * (1.f + scale) + shift;
                    continue;
                }
                vx += bias[c0]; vy += bias[c0 + 1];
                if (EPI == EPI_SILU) {
                    vx = vx / (1.f + expf(-vx));
                    vy = vy / (1.f + expf(-vy));
                } else if (EPI == EPI_GELU) {
                    const float cst = 0.70710678118654752f;
                    vx = 0.5f * vx * (1.f + erff(vx * cst));
                    vy = 0.5f * vy * (1.f + erff(vy * cst));
                } else if (EPI == EPI_RES) {
                    float2 rv = *(const float2*)&Res[(size_t)row * N + c0];
                    vx += rv.x; vy += rv.y;
                }
                if (HOUT) {
                    *(__half2*)((__half*)Cv + (size_t)row * N + c0) = __floats2half2_rn(vx, vy);
                } else {
                    *(float2*)((float*)Cv + (size_t)row * N + c0) = make_float2(vx, vy);
                }
            }
        }
    }
}

// ---------------- fp16 flash attention, 128x64 tiles, warp-owned rows ---------------
#define AST 72
#define ATT_SMEM ((128 * AST + 4 * 64 * AST) * 2)   // 55296 B

__global__ void __launch_bounds__(256) attn_mma_kernel(
    const __half* __restrict__ QKV, __half* __restrict__ O)
{
    extern __shared__ __half asm_[];
    __half* Qs = asm_;                  // [128][AST]; becomes Ps after qf preload
    __half* Ks = Qs + 128 * AST;        // [2][64][AST]
    __half* Vs = Ks + 2 * 64 * AST;     // [2][64][AST]
    __half* Ps = Qs;                    // overlay (warp-private 16-row slices)

    int tid = threadIdx.x, warp = tid >> 5, lane = tid & 31;
    int g = lane >> 2, t = lane & 3;
    int qt = (TT / 128 - 1) - blockIdx.x;
    int bh = blockIdx.y, b = bh >> 4, h = bh & 15;

    const __half* Qg = QKV + (size_t)b * TT * QSTR + (size_t)h * HD;
    const __half* Kg = Qg + 1024;
    const __half* Vg = Qg + 2048;

    {
        int lrow = tid >> 1, ld32 = (tid & 1) << 5;
        const __half* src = Qg + (size_t)(qt * 128 + lrow) * QSTR + ld32;
        __half* dst = Qs + lrow * AST + ld32;
        *(uint4*)(dst)      = *(const uint4*)(src);
        *(uint4*)(dst + 8)  = *(const uint4*)(src + 8);
        *(uint4*)(dst + 16) = *(const uint4*)(src + 16);
        *(uint4*)(dst + 24) = *(const uint4*)(src + 24);
    }
    int lrow = tid >> 2, ld16 = (tid & 3) << 4;
    {
        const __half* kp = Kg + (size_t)lrow * QSTR + ld16;
        const __half* vp = Vg + (size_t)lrow * QSTR + ld16;
        cp16h(&Ks[lrow * AST + ld16],     kp);
        cp16h(&Ks[lrow * AST + ld16 + 8], kp + 8);
        cp16h(&Vs[lrow * AST + ld16],     vp);
        cp16h(&Vs[lrow * AST + ld16 + 8], vp + 8);
        asm volatile("cp.async.commit_group;");
    }
    __syncthreads();

    int r0 = warp * 16 + g;
    uint32_t qf[4][4];
#pragma unroll
    for (int ks = 0; ks < 4; ks++) {
        int k0 = ks * 16;
        qf[ks][0] = *(const uint32_t*)&Qs[(r0)     * AST + k0 + 2 * t];
        qf[ks][1] = *(const uint32_t*)&Qs[(r0 + 8) * AST + k0 + 2 * t];
        qf[ks][2] = *(const uint32_t*)&Qs[(r0)     * AST + k0 + 2 * t + 8];
        qf[ks][3] = *(const uint32_t*)&Qs[(r0 + 8) * AST + k0 + 2 * t + 8];
    }
    __half* Pw = Ps + warp * 16 * AST;

    int kb_row  = ((lane >> 4) << 3) + (lane & 7);
    int kb_koff = ((lane >> 3) & 1) << 3;
    int vb_row  = lane;

    float m0 = -1e30f, m1 = -1e30f, l0 = 0.f, l1 = 0.f;
    float acc[8][4];
#pragma unroll
    for (int tj = 0; tj < 8; tj++)
#pragma unroll
        for (int c = 0; c < 4; c++) acc[tj][c] = 0.f;

    int nkt = 2 * qt + 2;
    for (int kt = 0; kt < nkt; kt++) {
        int cur = kt & 1;
        asm volatile("cp.async.wait_group 0;" ::: "memory");
        __syncthreads();

        if (kt + 1 < nkt) {
            int nxt = cur ^ 1;
            const __half* kp = Kg + (size_t)((kt + 1) * 64 + lrow) * QSTR + ld16;
            const __half* vp = Vg + (size_t)((kt + 1) * 64 + lrow) * QSTR + ld16;
            cp16h(&Ks[nxt * 64 * AST + lrow * AST + ld16],     kp);
            cp16h(&Ks[nxt * 64 * AST + lrow * AST + ld16 + 8], kp + 8);
            cp16h(&Vs[nxt * 64 * AST + lrow * AST + ld16],     vp);
            cp16h(&Vs[nxt * 64 * AST + lrow * AST + ld16 + 8], vp + 8);
        }
        asm volatile("cp.async.commit_group;");

        const __half* Kc = Ks + cur * 64 * AST;
        const __half* Vc = Vs + cur * 64 * AST;

        float s[8][4];
#pragma unroll
        for (int tj = 0; tj < 8; tj++)
#pragma unroll
            for (int c = 0; c < 4; c++) s[tj][c] = 0.f;
#pragma unroll
        for (int ks = 0; ks < 4; ks++) {
            int k0 = ks * 16;
#pragma unroll
            for (int tp = 0; tp < 4; tp++) {
                uint32_t bf4[4];
                ldm_x4(bf4, Kc + (tp * 16 + kb_row) * AST + k0 + kb_koff);
                mma_f16(s[2 * tp],     qf[ks], bf4);
                mma_f16(s[2 * tp + 1], qf[ks], bf4 + 2);
            }
        }

        if (kt >= 2 * qt) {
            int cgb = kt * 64;
            int rg0 = qt * 128 + r0, rg1 = rg0 + 8;
#pragma unroll
            for (int tj = 0; tj < 8; tj++) {
                int c0 = cgb + tj * 8 + 2 * t;
                if (c0     > rg0) s[tj][0] = -1e30f;
                if (c0 + 1 > rg0) s[tj][1] = -1e30f;
                if (c0     > rg1) s[tj][2] = -1e30f;
                if (c0 + 1 > rg1) s[tj][3] = -1e30f;
            }
        }

        float rm0 = -1e30f, rm1 = -1e30f;
#pragma unroll
        for (int tj = 0; tj < 8; tj++) {
            rm0 = fmaxf(rm0, fmaxf(s[tj][0], s[tj][1]));
            rm1 = fmaxf(rm1, fmaxf(s[tj][2], s[tj][3]));
        }
#pragma unroll
        for (int o = 1; o < 4; o <<= 1) {
            rm0 = fmaxf(rm0, __shfl_xor_sync(0xffffffffu, rm0, o));
            rm1 = fmaxf(rm1, __shfl_xor_sync(0xffffffffu, rm1, o));
        }
        float nm0 = fmaxf(m0, rm0), nm1 = fmaxf(m1, rm1);
        float a0 = __expf(m0 - nm0), a1 = __expf(m1 - nm1);
        m0 = nm0; m1 = nm1;

        float ls0 = 0.f, ls1 = 0.f;
#pragma unroll
        for (int tj = 0; tj < 8; tj++) {
            s[tj][0] = __expf(s[tj][0] - nm0);
            s[tj][1] = __expf(s[tj][1] - nm0);
            s[tj][2] = __expf(s[tj][2] - nm1);
            s[tj][3] = __expf(s[tj][3] - nm1);
            ls0 += s[tj][0] + s[tj][1];
            ls1 += s[tj][2] + s[tj][3];
        }
#pragma unroll
        for (int o = 1; o < 4; o <<= 1) {
            ls0 += __shfl_xor_sync(0xffffffffu, ls0, o);
            ls1 += __shfl_xor_sync(0xffffffffu, ls1, o);
        }
        l0 = l0 * a0 + ls0;
        l1 = l1 * a1 + ls1;

#pragma unroll
        for (int tj = 0; tj < 8; tj++) {
            int c0 = tj * 8 + 2 * t;
            *(__half2*)&Pw[(g)     * AST + c0] = __floats2half2_rn(s[tj][0], s[tj][1]);
            *(__half2*)&Pw[(g + 8) * AST + c0] = __floats2half2_rn(s[tj][2], s[tj][3]);
        }
        __syncwarp();

#pragma unroll
        for (int tj = 0; tj < 8; tj++) {
            acc[tj][0] *= a0; acc[tj][1] *= a0;
            acc[tj][2] *= a1; acc[tj][3] *= a1;
        }

#pragma unroll
        for (int kp2 = 0; kp2 < 2; kp2++) {
            int k0 = kp2 * 32;
            uint32_t pf0[4], pf1[4];
            pf0[0] = *(const uint32_t*)&Pw[(g)     * AST + k0 + 2 * t];
            pf0[1] = *(const uint32_t*)&Pw[(g + 8) * AST + k0 + 2 * t];
            pf0[2] = *(const uint32_t*)&Pw[(g)     * AST + k0 + 2 * t + 8];
            pf0[3] = *(const uint32_t*)&Pw[(g + 8) * AST + k0 + 2 * t + 8];
            pf1[0] = *(const uint32_t*)&Pw[(g)     * AST + k0 + 16 + 2 * t];
            pf1[1] = *(const uint32_t*)&Pw[(g + 8) * AST + k0 + 16 + 2 * t];
            pf1[2] = *(const uint32_t*)&Pw[(g)     * AST + k0 + 16 + 2 * t + 8];
            pf1[3] = *(const uint32_t*)&Pw[(g + 8) * AST + k0 + 16 + 2 * t + 8];
#pragma unroll
            for (int tj = 0; tj < 8; tj++) {
                uint32_t vb[4];
                ldm_x4t(vb, Vc + (k0 + vb_row) * AST + tj * 8);
                mma_f16(acc[tj], pf0, vb);
                mma_f16(acc[tj], pf1, vb + 2);
            }
        }
    }

    float inv0 = 1.f / l0, inv1 = 1.f / l1;
    __half* Og = O + (size_t)b * TT * DIMD + (size_t)(qt * 128) * DIMD + (size_t)h * HD;
#pragma unroll
    for (int tj = 0; tj < 8; tj++) {
        int c0 = tj * 8 + 2 * t;
        *(__half2*)&Og[(size_t)(r0)     * DIMD + c0] = __floats2half2_rn(acc[tj][0] * inv0, acc[tj][1] * inv0);
        *(__half2*)&Og[(size_t)(r0 + 8) * DIMD + c0] = __floats2half2_rn(acc[tj][2] * inv1, acc[tj][3] * inv1);
    }
}

// ------------------------------- launch --------------------------------------------
extern "C" void kernel_launch(void* const* d_in, const int* in_sizes, int n_in,
                              void* d_out, int out_size)
{
    const float* x       = (const float*)d_in[0];
    const float* actions = (const float*)d_in[1];
    const float* n1_w    = (const float*)d_in[2];
    const float* n2_w    = (const float*)d_in[3];
    const float* q_w     = (const float*)d_in[4];
    const float* q_b     = (const float*)d_in[5];
    const float* k_w     = (const float*)d_in[6];
    const float* k_b     = (const float*)d_in[7];
    const float* v_w     = (const float*)d_in[8];
    const float* v_b     = (const float*)d_in[9];
    const float* qn_w    = (const float*)d_in[10];
    const float* kn_w    = (const float*)d_in[11];
    const float* o_w     = (const float*)d_in[12];
    const float* o_b     = (const float*)d_in[13];
    const float* ae1_w   = (const float*)d_in[14];
    const float* ae1_b   = (const float*)d_in[15];
    const float* ae2_w   = (const float*)d_in[16];
    const float* ae2_b   = (const float*)d_in[17];
    const float* mod_w   = (const float*)d_in[18];
    const float* mod_b   = (const float*)d_in[19];
    const float* m1_w    = (const float*)d_in[20];
    const float* m1_b    = (const float*)d_in[21];
    const float* m2_w    = (const float*)d_in[22];
    const float* m2_b    = (const float*)d_in[23];
    float* out           = (float*)d_out;

    __half *h, *a1, *qkv, *ao, *ae, *hid;
    float *x1, *bqkv;
    __half *wqkv, *wo, *wae2, *wmod, *wm1, *wm2;
    cudaGetSymbolAddress((void**)&h,    g_h);
    cudaGetSymbolAddress((void**)&a1,   g_a1);
    cudaGetSymbolAddress((void**)&qkv,  g_qkv);
    cudaGetSymbolAddress((void**)&ao,   g_ao);
    cudaGetSymbolAddress((void**)&ae,   g_ae);
    cudaGetSymbolAddress((void**)&hid,  g_hid);
    cudaGetSymbolAddress((void**)&x1,   g_x1);
    cudaGetSymbolAddress((void**)&bqkv, g_bqkv);
    cudaGetSymbolAddress((void**)&wqkv, g_wqkv);
    cudaGetSymbolAddress((void**)&wo,   g_wo);
    cudaGetSymbolAddress((void**)&wae2, g_wae2);
    cudaGetSymbolAddress((void**)&wmod, g_wmod);
    cudaGetSymbolAddress((void**)&wm1,  g_wm1);
    cudaGetSymbolAddress((void**)&wm2,  g_wm2);

    static int attr_set = 0;
    if (!attr_set) {
        cudaFuncSetAttribute((const void*)hmma_kernel<EPI_NONE, 1>, cudaFuncAttributeMaxDynamicSharedMemorySize, HMMA_SMEM);
        cudaFuncSetAttribute((const void*)hmma_kernel<EPI_SILU, 1>, cudaFuncAttributeMaxDynamicSharedMemorySize, HMMA_SMEM);
        cudaFuncSetAttribute((const void*)hmma_kernel<EPI_GELU, 1>, cudaFuncAttributeMaxDynamicSharedMemorySize, HMMA_SMEM);
        cudaFuncSetAttribute((const void*)hmma_kernel<EPI_RES,  0>, cudaFuncAttributeMaxDynamicSharedMemorySize, HMMA_SMEM);
        cudaFuncSetAttribute((const void*)hmma_kernel<EPI_MOD,  0>, cudaFuncAttributeMaxDynamicSharedMemorySize, HMMA_SMEM);
        cudaFuncSetAttribute((const void*)attn_mma_kernel, cudaFuncAttributeMaxDynamicSharedMemorySize, ATT_SMEM);
        attr_set = 1;
    }

    dim3 g1024(8, 32);
    dim3 g2048(16, 32);
    dim3 g3072(24, 32);
    dim3 g4096(32, 32);

    // 1) pack qkv bias
    bias_pack_kernel<<<12, 256>>>(q_b, k_b, v_b);
    // 2) all weight transposes
    tr_all_kernel<<<15360, dim3(32, 8)>>>(q_w, k_w, v_w, o_w, ae2_w, mod_w, m1_w, m2_w);
    // 3) h = rmsnorm(x, n1_w)
    rmsnorm_kernel<<<BT, 256>>>(x, n1_w, h);
    // 4) a1 = silu(actions @ ae1_w + ae1_b)
    ae1_kernel<<<dim3(BT / 32, 4), 256>>>(actions, ae1_w, ae1_b, a1);
    // 5) ae = silu(a1 @ ae2_w + ae2_b)
    hmma_kernel<EPI_SILU, 1><<<g1024, 256, HMMA_SMEM>>>(a1, wae2, ae2_b, nullptr, ae, BT, DIMD, DIMD);
    // 6) fused qkv projection
    hmma_kernel<EPI_NONE, 1><<<g3072, 256, HMMA_SMEM>>>(h, wqkv, bqkv, nullptr, qkv, BT, QSTR, DIMD);
    // 7) QK head norms
    headnorm_kernel<<<dim3((BT * NH) / 8, 2), 256>>>(qkv, qn_w, kn_w);
    // 8) attention (128-row tiles)
    attn_mma_kernel<<<dim3(TT / 128, 2 * NH), 256, ATT_SMEM>>>(qkv, ao);
    // 9) x1 = x + ao @ o_w + o_b
    hmma_kernel<EPI_RES, 0><<<g1024, 256, HMMA_SMEM>>>(ao, wo, o_b, x, x1, BT, DIMD, DIMD);
    // 10) fused modulate GEMM
    hmma_kernel<EPI_MOD, 0><<<g2048, 256, HMMA_SMEM>>>(ae, wmod, mod_b, x1, x1, BT, 2048, DIMD);
    // 11) h = rmsnorm(x1, n2_w)
    rmsnorm_kernel<<<BT, 256>>>(x1, n2_w, h);
    // 12) hid = gelu(h @ m1_w + m1_b)
    hmma_kernel<EPI_GELU, 1><<<g4096, 256, HMMA_SMEM>>>(h, wm1, m1_b, nullptr, hid, BT, MLPH, DIMD);
    // 13) out = x1 + hid @ m2_w + m2_b
    hmma_kernel<EPI_RES, 0><<<g1024, 256, HMMA_SMEM>>>(hid, wm2, m2_b, x1, out, BT, DIMD, MLPH);
}

// round 13
// speedup vs baseline: 6.1168x; 1.0091x over previous
#include <cuda_runtime.h>
#include <cuda_fp16.h>
#include <math.h>
#include <stdint.h>

#define BT    4096
#define DIMD  1024
#define NH    16
#define HD    64
#define TT    2048
#define MLPH  4096
#define QSTR  3072

// ---------------- scratch -------------------------------------------------------
__device__ __half g_h  [BT * DIMD];
__device__ __half g_a1 [BT * DIMD];
__device__ __half g_qkv[BT * QSTR];
__device__ __half g_ao [BT * DIMD];
__device__ __half g_ae [BT * DIMD];
__device__ __half g_hid[BT * MLPH];
__device__ float  g_x1 [BT * DIMD];
__device__ float  g_bqkv[QSTR];
// NATURAL layout ([K][N]) fp16 weights
__device__ __half g_wqkv[DIMD * QSTR];     // [k][0..1023]=q, [1024..2047]=k, [2048..3071]=v
__device__ __half g_wo  [DIMD * DIMD];
__device__ __half g_wae2[DIMD * DIMD];
__device__ __half g_wmod[DIMD * 2048];     // col 2j=shift_j, 2j+1=scale_j
__device__ __half g_wm1 [DIMD * MLPH];
__device__ __half g_wm2 [MLPH * DIMD];

// ---------------- fused weight convert (fp32->fp16, coalesced, one launch) ---------
#define U_QKV  786432
#define U_O    1048576
#define U_AE2  1310720
#define U_M1   2359296
#define U_M2   3407872
#define U_MOD  3670016
#define U_TOT  3670784

__global__ void conv_all_kernel(const float* __restrict__ q_w, const float* __restrict__ k_w,
                                const float* __restrict__ v_w, const float* __restrict__ o_w,
                                const float* __restrict__ ae2_w, const float* __restrict__ mod_w,
                                const float* __restrict__ m1_w, const float* __restrict__ m2_w,
                                const float* __restrict__ q_b, const float* __restrict__ k_b,
                                const float* __restrict__ v_b)
{
    int u = blockIdx.x * 256 + threadIdx.x;
    if (u < U_QKV) {
        int j = u >> 18, r = u & 262143;
        int k = r >> 8, n4 = (r & 255) << 2;
        const float* s = (j == 0) ? q_w : ((j == 1) ? k_w : v_w);
        float4 v = *(const float4*)&s[(size_t)k * 1024 + n4];
        uint2 o;
        ((__half2*)&o)[0] = __floats2half2_rn(v.x, v.y);
        ((__half2*)&o)[1] = __floats2half2_rn(v.z, v.w);
        *(uint2*)&g_wqkv[(size_t)k * QSTR + j * 1024 + n4] = o;
    } else if (u < U_O) {
        int e4 = (u - U_QKV) << 2;
        float4 v = *(const float4*)&o_w[e4];
        uint2 o;
        ((__half2*)&o)[0] = __floats2half2_rn(v.x, v.y);
        ((__half2*)&o)[1] = __floats2half2_rn(v.z, v.w);
        *(uint2*)&g_wo[e4] = o;
    } else if (u < U_AE2) {
        int e4 = (u - U_O) << 2;
        float4 v = *(const float4*)&ae2_w[e4];
        uint2 o;
        ((__half2*)&o)[0] = __floats2half2_rn(v.x, v.y);
        ((__half2*)&o)[1] = __floats2half2_rn(v.z, v.w);
        *(uint2*)&g_wae2[e4] = o;
    } else if (u < U_M1) {
        int e4 = (u - U_AE2) << 2;
        float4 v = *(const float4*)&m1_w[e4];
        uint2 o;
        ((__half2*)&o)[0] = __floats2half2_rn(v.x, v.y);
        ((__half2*)&o)[1] = __floats2half2_rn(v.z, v.w);
        *(uint2*)&g_wm1[e4] = o;
    } else if (u < U_M2) {
        int e4 = (u - U_M1) << 2;
        float4 v = *(const float4*)&m2_w[e4];
        uint2 o;
        ((__half2*)&o)[0] = __floats2half2_rn(v.x, v.y);
        ((__half2*)&o)[1] = __floats2half2_rn(v.z, v.w);
        *(uint2*)&g_wm2[e4] = o;
    } else if (u < U_MOD) {
        int r = u - U_M2;
        int k = r >> 8, j4 = (r & 255) << 2;
        float4 sh = *(const float4*)&mod_w[(size_t)k * 4096 + j4];
        float4 sc = *(const float4*)&mod_w[(size_t)k * 4096 + 1024 + j4];
        uint4 o;
        ((__half2*)&o)[0] = __floats2half2_rn(sh.x, sc.x);
        ((__half2*)&o)[1] = __floats2half2_rn(sh.y, sc.y);
        ((__half2*)&o)[2] = __floats2half2_rn(sh.z, sc.z);
        ((__half2*)&o)[3] = __floats2half2_rn(sh.w, sc.w);
        *(uint4*)&g_wmod[(size_t)k * 2048 + 2 * j4] = o;
    } else {
        int r = u - U_MOD;
        int i = r << 2;
        float4 v;
        if (i < 1024)      v = *(const float4*)&q_b[i];
        else if (i < 2048) v = *(const float4*)&k_b[i - 1024];
        else               v = *(const float4*)&v_b[i - 2048];
        *(float4*)&g_bqkv[i] = v;
    }
}

// ---------------- rmsnorm: float in -> half out ----------------------------------
__global__ void rmsnorm_kernel(const float* __restrict__ x,
                               const float* __restrict__ w,
                               __half* __restrict__ y)
{
    int row = blockIdx.x;
    const float* xr = x + (size_t)row * DIMD;
    float v[4];
    float s = 0.f;
#pragma unroll
    for (int i = 0; i < 4; i++) {
        v[i] = xr[threadIdx.x + i * 256];
        s += v[i] * v[i];
    }
#pragma unroll
    for (int o = 16; o > 0; o >>= 1) s += __shfl_xor_sync(0xffffffffu, s, o);
    __shared__ float red[8];
    if ((threadIdx.x & 31) == 0) red[threadIdx.x >> 5] = s;
    __syncthreads();
    if (threadIdx.x == 0) {
        float t = 0.f;
#pragma unroll
        for (int i = 0; i < 8; i++) t += red[i];
        red[0] = rsqrtf(t * (1.0f / DIMD) + 1e-6f);
    }
    __syncthreads();
    float r = red[0];
    __half* yr = y + (size_t)row * DIMD;
#pragma unroll
    for (int i = 0; i < 4; i++) {
        int c = threadIdx.x + i * 256;
        yr[c] = __float2half_rn(v[i] * r * w[c]);
    }
}

// ---------------- per-head rmsnorm on qkv buffer ------------------------------------
__global__ void headnorm_kernel(__half* __restrict__ qkv,
                                const float* __restrict__ qw, const float* __restrict__ kw)
{
    int sel = blockIdx.y;
    const float* w = sel ? kw : qw;
    float scale = sel ? 1.0f : 0.125f;
    int gw   = (blockIdx.x * blockDim.x + threadIdx.x) >> 5;
    int lane = threadIdx.x & 31;
    if (gw >= BT * NH) return;
    int token = gw >> 4, head = gw & 15;
    __half* p = qkv + (size_t)token * QSTR + sel * 1024 + head * 64;
    float a = __half2float(p[lane]);
    float b = __half2float(p[lane + 32]);
    float s = a * a + b * b;
#pragma unroll
    for (int o = 16; o > 0; o >>= 1) s += __shfl_xor_sync(0xffffffffu, s, o);
    float r = rsqrtf(s * (1.0f / HD) + 1e-6f) * scale;
    p[lane]      = __float2half_rn(a * r * w[lane]);
    p[lane + 32] = __float2half_rn(b * r * w[lane + 32]);
}

// ---------------- ae1 (K=16): 32 rows x 256 cols per block --------------------------
__global__ void __launch_bounds__(256) ae1_kernel(
    const float* __restrict__ A, const float* __restrict__ W,
    const float* __restrict__ bias, __half* __restrict__ C)
{
    __shared__ float Ws[16 * 256];
    __shared__ float As[32 * 16];
    int tid = threadIdx.x;
    int colbase = blockIdx.y * 256;
    for (int i = tid; i < 1024; i += 256) {
        int row = i >> 6, c4 = (i & 63) << 2;
        *(float4*)&Ws[row * 256 + c4] = *(const float4*)&W[(size_t)row * 1024 + colbase + c4];
    }
    int brow = blockIdx.x * 32;
    if (tid < 128)
        ((float4*)As)[tid] = ((const float4*)(A + (size_t)brow * 16))[tid];
    __syncthreads();

    int r = tid >> 3, lane8 = tid & 7;
    float a[16];
#pragma unroll
    for (int kk = 0; kk < 16; kk++) a[kk] = As[r * 16 + kk];
    __half* Cr = C + (size_t)(brow + r) * 1024 + colbase;

#pragma unroll
    for (int j = 0; j < 8; j++) {
        int col = lane8 * 4 + j * 32;
        float4 o = make_float4(bias[colbase + col],     bias[colbase + col + 1],
                               bias[colbase + col + 2], bias[colbase + col + 3]);
#pragma unroll
        for (int kk = 0; kk < 16; kk++) {
            float4 wv = *(float4*)&Ws[kk * 256 + col];
            o.x += a[kk] * wv.x; o.y += a[kk] * wv.y;
            o.z += a[kk] * wv.z; o.w += a[kk] * wv.w;
        }
        o.x = o.x / (1.f + expf(-o.x));
        o.y = o.y / (1.f + expf(-o.y));
        o.z = o.z / (1.f + expf(-o.z));
        o.w = o.w / (1.f + expf(-o.w));
        *(__half2*)&Cr[col]     = __floats2half2_rn(o.x, o.y);
        *(__half2*)&Cr[col + 2] = __floats2half2_rn(o.z, o.w);
    }
}

// ============ fp16 GEMM 128x128x64, 3-stage, natural-layout B via ldmatrix.trans ====
#define EPI_NONE 0
#define EPI_SILU 1
#define EPI_GELU 2
#define EPI_RES  3
#define EPI_MOD  4

#define GBK 64
#define GSTR 72          // A tile stride (halves)
#define BSTR 136         // B tile stride (halves)
#define APS  (128 * GSTR)
#define BPS  (64 * BSTR)
#define HMMA_SMEM (3 * (APS + BPS) * 2)     // 107520 B

__device__ __forceinline__ void cp16h(__half* s, const __half* g)
{
    uint32_t sa = (uint32_t)__cvta_generic_to_shared(s);
    asm volatile("cp.async.cg.shared.global [%0], [%1], 16;\n" :: "r"(sa), "l"(g));
}

__device__ __forceinline__ void mma_f16(float* c, const uint32_t* a, const uint32_t* b)
{
    asm volatile(
        "mma.sync.aligned.m16n8k16.row.col.f32.f16.f16.f32 "
        "{%0,%1,%2,%3},{%4,%5,%6,%7},{%8,%9},{%0,%1,%2,%3};"
        : "+f"(c[0]), "+f"(c[1]), "+f"(c[2]), "+f"(c[3])
        : "r"(a[0]), "r"(a[1]), "r"(a[2]), "r"(a[3]), "r"(b[0]), "r"(b[1]));
}

__device__ __forceinline__ void ldm_x4(uint32_t* r, const __half* p)
{
    uint32_t addr = (uint32_t)__cvta_generic_to_shared(p);
    asm volatile("ldmatrix.sync.aligned.m8n8.x4.shared.b16 {%0,%1,%2,%3}, [%4];"
                 : "=r"(r[0]), "=r"(r[1]), "=r"(r[2]), "=r"(r[3]) : "r"(addr));
}

__device__ __forceinline__ void ldm_x4t(uint32_t* r, const __half* p)
{
    uint32_t addr = (uint32_t)__cvta_generic_to_shared(p);
    asm volatile("ldmatrix.sync.aligned.m8n8.x4.trans.shared.b16 {%0,%1,%2,%3}, [%4];"
                 : "=r"(r[0]), "=r"(r[1]), "=r"(r[2]), "=r"(r[3]) : "r"(addr));
}

template<int EPI, int HOUT>
__global__ void __launch_bounds__(256, 2) hmma_kernel(
    const __half* __restrict__ A, const __half* __restrict__ Wn,   // Wn: [K][N] natural
    const float* __restrict__ bias, const float* __restrict__ Res,
    void* __restrict__ Cv, int M, int N, int K)
{
    extern __shared__ __half hsm[];
    __half* Asm = hsm;
    __half* Bsm = hsm + 3 * APS;

    int tid  = threadIdx.x;
    int brow = blockIdx.y * 128;
    int bcol = blockIdx.x * 128;
    int warp = tid >> 5, lane = tid & 31;
    int g = lane >> 2, t = lane & 3;
    int wr = warp & 1, wc = warp >> 1;

    int ar = tid >> 3, ac = (tid & 7) << 3;
    const __half* Agb = A + (size_t)(brow + ar) * K + ac;
    int br = tid >> 4, bc = (tid & 15) << 3;
    const __half* Bgb = Wn + (size_t)br * N + bcol + bc;

    int a_row  = wr * 64 + (lane & 15);
    int a_koff = (lane >> 4) << 3;

    float acc[4][4][4];
#pragma unroll
    for (int i = 0; i < 4; i++)
#pragma unroll
        for (int j = 0; j < 4; j++)
#pragma unroll
            for (int c = 0; c < 4; c++) acc[i][j][c] = 0.f;

    int nk = K / GBK;

#pragma unroll
    for (int s = 0; s < 2; s++) {
        int kc = s * GBK;
#pragma unroll
        for (int p = 0; p < 4; p++)
            cp16h(&Asm[s * APS + (ar + 32 * p) * GSTR + ac], Agb + (size_t)32 * p * K + kc);
#pragma unroll
        for (int p = 0; p < 4; p++)
            cp16h(&Bsm[s * BPS + (br + 16 * p) * BSTR + bc], Bgb + (size_t)(kc + 16 * p) * N);
        asm volatile("cp.async.commit_group;");
    }

    int st = 0;
    for (int i = 0; i < nk; i++) {
        asm volatile("cp.async.wait_group 1;" ::: "memory");
        __syncthreads();

        if (i + 2 < nk) {
            int kc = (i + 2) * GBK;
            int s2 = st + 2; if (s2 >= 3) s2 -= 3;
#pragma unroll
            for (int p = 0; p < 4; p++)
                cp16h(&Asm[s2 * APS + (ar + 32 * p) * GSTR + ac], Agb + (size_t)32 * p * K + kc);
#pragma unroll
            for (int p = 0; p < 4; p++)
                cp16h(&Bsm[s2 * BPS + (br + 16 * p) * BSTR + bc], Bgb + (size_t)(kc + 16 * p) * N);
        }
        asm volatile("cp.async.commit_group;");

        const __half* Sb = &Asm[st * APS];
        const __half* Tb = &Bsm[st * BPS];
#pragma unroll
        for (int kp2 = 0; kp2 < 2; kp2++) {
            int k0 = kp2 * 32;
            uint32_t af[2][4][4];
#pragma unroll
            for (int ti = 0; ti < 4; ti++) {
                ldm_x4(af[0][ti], Sb + (a_row + ti * 16) * GSTR + k0 + a_koff);
                ldm_x4(af[1][ti], Sb + (a_row + ti * 16) * GSTR + k0 + 16 + a_koff);
            }
#pragma unroll
            for (int tj = 0; tj < 4; tj++) {
                uint32_t vb[4];
                ldm_x4t(vb, Tb + (size_t)(k0 + lane) * BSTR + wc * 32 + tj * 8);
#pragma unroll
                for (int ti = 0; ti < 4; ti++) {
                    mma_f16(acc[ti][tj], af[0][ti], vb);
                    mma_f16(acc[ti][tj], af[1][ti], vb + 2);
                }
            }
        }
        if (++st == 3) st = 0;
    }

#pragma unroll
    for (int ti = 0; ti < 4; ti++) {
        int r0 = brow + wr * 64 + ti * 16 + g;
#pragma unroll
        for (int tj = 0; tj < 4; tj++) {
            int c0 = bcol + wc * 32 + tj * 8 + 2 * t;
#pragma unroll
            for (int half_i = 0; half_i < 2; half_i++) {
                int row = r0 + half_i * 8;
                float vx = acc[ti][tj][half_i * 2 + 0];
                float vy = acc[ti][tj][half_i * 2 + 1];
                if (EPI == EPI_MOD) {
                    int j = c0 >> 1;
                    float shift = vx + bias[j];
                    float scale = vy + bias[1024 + j];
                    float res = Res[(size_t)row * (N >> 1) + j];
                    ((float*)Cv)[(size_t)row * (N >> 1) + j] = res * (1.f + scale) + shift;
                    continue;
                }
                vx += bias[c0]; vy += bias[c0 + 1];
                if (EPI == EPI_SILU) {
                    vx = vx / (1.f + expf(-vx));
                    vy = vy / (1.f + expf(-vy));
                } else if (EPI == EPI_GELU) {
                    const float cst = 0.70710678118654752f;
                    vx = 0.5f * vx * (1.f + erff(vx * cst));
                    vy = 0.5f * vy * (1.f + erff(vy * cst));
                } else if (EPI == EPI_RES) {
                    float2 rv = *(const float2*)&Res[(size_t)row * N + c0];
                    vx += rv.x; vy += rv.y;
                }
                if (HOUT) {
                    *(__half2*)((__half*)Cv + (size_t)row * N + c0) = __floats2half2_rn(vx, vy);
                } else {
                    *(float2*)((float*)Cv + (size_t)row * N + c0) = make_float2(vx, vy);
                }
            }
        }
    }
}

// ---------------- fp16 flash attention, 128x64 tiles (unchanged, known good) --------
#define AST 72
#define ATT_SMEM ((128 * AST + 4 * 64 * AST) * 2)

__global__ void __launch_bounds__(256) attn_mma_kernel(
    const __half* __restrict__ QKV, __half* __restrict__ O)
{
    extern __shared__ __half asm_[];
    __half* Qs = asm_;
    __half* Ks = Qs + 128 * AST;
    __half* Vs = Ks + 2 * 64 * AST;
    __half* Ps = Qs;

    int tid = threadIdx.x, warp = tid >> 5, lane = tid & 31;
    int g = lane >> 2, t = lane & 3;
    int qt = (TT / 128 - 1) - blockIdx.x;
    int bh = blockIdx.y, b = bh >> 4, h = bh & 15;

    const __half* Qg = QKV + (size_t)b * TT * QSTR + (size_t)h * HD;
    const __half* Kg = Qg + 1024;
    const __half* Vg = Qg + 2048;

    {
        int lrow = tid >> 1, ld32 = (tid & 1) << 5;
        const __half* src = Qg + (size_t)(qt * 128 + lrow) * QSTR + ld32;
        __half* dst = Qs + lrow * AST + ld32;
        *(uint4*)(dst)      = *(const uint4*)(src);
        *(uint4*)(dst + 8)  = *(const uint4*)(src + 8);
        *(uint4*)(dst + 16) = *(const uint4*)(src + 16);
        *(uint4*)(dst + 24) = *(const uint4*)(src + 24);
    }
    int lrow = tid >> 2, ld16 = (tid & 3) << 4;
    {
        const __half* kp = Kg + (size_t)lrow * QSTR + ld16;
        const __half* vp = Vg + (size_t)lrow * QSTR + ld16;
        cp16h(&Ks[lrow * AST + ld16],     kp);
        cp16h(&Ks[lrow * AST + ld16 + 8], kp + 8);
        cp16h(&Vs[lrow * AST + ld16],     vp);
        cp16h(&Vs[lrow * AST + ld16 + 8], vp + 8);
        asm volatile("cp.async.commit_group;");
    }
    __syncthreads();

    int r0 = warp * 16 + g;
    uint32_t qf[4][4];
#pragma unroll
    for (int ks = 0; ks < 4; ks++) {
        int k0 = ks * 16;
        qf[ks][0] = *(const uint32_t*)&Qs[(r0)     * AST + k0 + 2 * t];
        qf[ks][1] = *(const uint32_t*)&Qs[(r0 + 8) * AST + k0 + 2 * t];
        qf[ks][2] = *(const uint32_t*)&Qs[(r0)     * AST + k0 + 2 * t + 8];
        qf[ks][3] = *(const uint32_t*)&Qs[(r0 + 8) * AST + k0 + 2 * t + 8];
    }
    __half* Pw = Ps + warp * 16 * AST;

    int kb_row  = ((lane >> 4) << 3) + (lane & 7);
    int kb_koff = ((lane >> 3) & 1) << 3;
    int vb_row  = lane;

    float m0 = -1e30f, m1 = -1e30f, l0 = 0.f, l1 = 0.f;
    float acc[8][4];
#pragma unroll
    for (int tj = 0; tj < 8; tj++)
#pragma unroll
        for (int c = 0; c < 4; c++) acc[tj][c] = 0.f;

    int nkt = 2 * qt + 2;
    for (int kt = 0; kt < nkt; kt++) {
        int cur = kt & 1;
        asm volatile("cp.async.wait_group 0;" ::: "memory");
        __syncthreads();

        if (kt + 1 < nkt) {
            int nxt = cur ^ 1;
            const __half* kp = Kg + (size_t)((kt + 1) * 64 + lrow) * QSTR + ld16;
            const __half* vp = Vg + (size_t)((kt + 1) * 64 + lrow) * QSTR + ld16;
            cp16h(&Ks[nxt * 64 * AST + lrow * AST + ld16],     kp);
            cp16h(&Ks[nxt * 64 * AST + lrow * AST + ld16 + 8], kp + 8);
            cp16h(&Vs[nxt * 64 * AST + lrow * AST + ld16],     vp);
            cp16h(&Vs[nxt * 64 * AST + lrow * AST + ld16 + 8], vp + 8);
        }
        asm volatile("cp.async.commit_group;");

        const __half* Kc = Ks + cur * 64 * AST;
        const __half* Vc = Vs + cur * 64 * AST;

        float s[8][4];
#pragma unroll
        for (int tj = 0; tj < 8; tj++)
#pragma unroll
            for (int c = 0; c < 4; c++) s[tj][c] = 0.f;
#pragma unroll
        for (int ks = 0; ks < 4; ks++) {
            int k0 = ks * 16;
#pragma unroll
            for (int tp = 0; tp < 4; tp++) {
                uint32_t bf4[4];
                ldm_x4(bf4, Kc + (tp * 16 + kb_row) * AST + k0 + kb_koff);
                mma_f16(s[2 * tp],     qf[ks], bf4);
                mma_f16(s[2 * tp + 1], qf[ks], bf4 + 2);
            }
        }

        if (kt >= 2 * qt) {
            int cgb = kt * 64;
            int rg0 = qt * 128 + r0, rg1 = rg0 + 8;
#pragma unroll
            for (int tj = 0; tj < 8; tj++) {
                int c0 = cgb + tj * 8 + 2 * t;
                if (c0     > rg0) s[tj][0] = -1e30f;
                if (c0 + 1 > rg0) s[tj][1] = -1e30f;
                if (c0     > rg1) s[tj][2] = -1e30f;
                if (c0 + 1 > rg1) s[tj][3] = -1e30f;
            }
        }

        float rm0 = -1e30f, rm1 = -1e30f;
#pragma unroll
        for (int tj = 0; tj < 8; tj++) {
            rm0 = fmaxf(rm0, fmaxf(s[tj][0], s[tj][1]));
            rm1 = fmaxf(rm1, fmaxf(s[tj][2], s[tj][3]));
        }
#pragma unroll
        for (int o = 1; o < 4; o <<= 1) {
            rm0 = fmaxf(rm0, __shfl_xor_sync(0xffffffffu, rm0, o));
            rm1 = fmaxf(rm1, __shfl_xor_sync(0xffffffffu, rm1, o));
        }
        float nm0 = fmaxf(m0, rm0), nm1 = fmaxf(m1, rm1);
        float a0 = __expf(m0 - nm0), a1 = __expf(m1 - nm1);
        m0 = nm0; m1 = nm1;

        float ls0 = 0.f, ls1 = 0.f;
#pragma unroll
        for (int tj = 0; tj < 8; tj++) {
            s[tj][0] = __expf(s[tj][0] - nm0);
            s[tj][1] = __expf(s[tj][1] - nm0);
            s[tj][2] = __expf(s[tj][2] - nm1);
            s[tj][3] = __expf(s[tj][3] - nm1);
            ls0 += s[tj][0] + s[tj][1];
            ls1 += s[tj][2] + s[tj][3];
        }
#pragma unroll
        for (int o = 1; o < 4; o <<= 1) {
            ls0 += __shfl_xor_sync(0xffffffffu, ls0, o);
            ls1 += __shfl_xor_sync(0xffffffffu, ls1, o);
        }
        l0 = l0 * a0 + ls0;
        l1 = l1 * a1 + ls1;

#pragma unroll
        for (int tj = 0; tj < 8; tj++) {
            int c0 = tj * 8 + 2 * t;
            *(__half2*)&Pw[(g)     * AST + c0] = __floats2half2_rn(s[tj][0], s[tj][1]);
            *(__half2*)&Pw[(g + 8) * AST + c0] = __floats2half2_rn(s[tj][2], s[tj][3]);
        }
        __syncwarp();

#pragma unroll
        for (int tj = 0; tj < 8; tj++) {
            acc[tj][0] *= a0; acc[tj][1] *= a0;
            acc[tj][2] *= a1; acc[tj][3] *= a1;
        }

#pragma unroll
        for (int kp2 = 0; kp2 < 2; kp2++) {
            int k0 = kp2 * 32;
            uint32_t pf0[4], pf1[4];
            pf0[0] = *(const uint32_t*)&Pw[(g)     * AST + k0 + 2 * t];
            pf0[1] = *(const uint32_t*)&Pw[(g + 8) * AST + k0 + 2 * t];
            pf0[2] = *(const uint32_t*)&Pw[(g)     * AST + k0 + 2 * t + 8];
            pf0[3] = *(const uint32_t*)&Pw[(g + 8) * AST + k0 + 2 * t + 8];
            pf1[0] = *(const uint32_t*)&Pw[(g)     * AST + k0 + 16 + 2 * t];
            pf1[1] = *(const uint32_t*)&Pw[(g + 8) * AST + k0 + 16 + 2 * t];
            pf1[2] = *(const uint32_t*)&Pw[(g)     * AST + k0 + 16 + 2 * t + 8];
            pf1[3] = *(const uint32_t*)&Pw[(g + 8) * AST + k0 + 16 + 2 * t + 8];
#pragma unroll
            for (int tj = 0; tj < 8; tj++) {
                uint32_t vb[4];
                ldm_x4t(vb, Vc + (k0 + vb_row) * AST + tj * 8);
                mma_f16(acc[tj], pf0, vb);
                mma_f16(acc[tj], pf1, vb + 2);
            }
        }
    }

    float inv0 = 1.f / l0, inv1 = 1.f / l1;
    __half* Og = O + (size_t)b * TT * DIMD + (size_t)(qt * 128) * DIMD + (size_t)h * HD;
#pragma unroll
    for (int tj = 0; tj < 8; tj++) {
        int c0 = tj * 8 + 2 * t;
        *(__half2*)&Og[(size_t)(r0)     * DIMD + c0] = __floats2half2_rn(acc[tj][0] * inv0, acc[tj][1] * inv0);
        *(__half2*)&Og[(size_t)(r0 + 8) * DIMD + c0] = __floats2half2_rn(acc[tj][2] * inv1, acc[tj][3] * inv1);
    }
}

// ------------------------------- launch --------------------------------------------
extern "C" void kernel_launch(void* const* d_in, const int* in_sizes, int n_in,
                              void* d_out, int out_size)
{
    const float* x       = (const float*)d_in[0];
    const float* actions = (const float*)d_in[1];
    const float* n1_w    = (const float*)d_in[2];
    const float* n2_w    = (const float*)d_in[3];
    const float* q_w     = (const float*)d_in[4];
    const float* q_b     = (const float*)d_in[5];
    const float* k_w     = (const float*)d_in[6];
    const float* k_b     = (const float*)d_in[7];
    const float* v_w     = (const float*)d_in[8];
    const float* v_b     = (const float*)d_in[9];
    const float* qn_w    = (const float*)d_in[10];
    const float* kn_w    = (const float*)d_in[11];
    const float* o_w     = (const float*)d_in[12];
    const float* o_b     = (const float*)d_in[13];
    const float* ae1_w   = (const float*)d_in[14];
    const float* ae1_b   = (const float*)d_in[15];
    const float* ae2_w   = (const float*)d_in[16];
    const float* ae2_b   = (const float*)d_in[17];
    const float* mod_w   = (const float*)d_in[18];
    const float* mod_b   = (const float*)d_in[19];
    const float* m1_w    = (const float*)d_in[20];
    const float* m1_b    = (const float*)d_in[21];
    const float* m2_w    = (const float*)d_in[22];
    const float* m2_b    = (const float*)d_in[23];
    float* out           = (float*)d_out;

    __half *h, *a1, *qkv, *ao, *ae, *hid;
    float *x1, *bqkv;
    __half *wqkv, *wo, *wae2, *wmod, *wm1, *wm2;
    cudaGetSymbolAddress((void**)&h,    g_h);
    cudaGetSymbolAddress((void**)&a1,   g_a1);
    cudaGetSymbolAddress((void**)&qkv,  g_qkv);
    cudaGetSymbolAddress((void**)&ao,   g_ao);
    cudaGetSymbolAddress((void**)&ae,   g_ae);
    cudaGetSymbolAddress((void**)&hid,  g_hid);
    cudaGetSymbolAddress((void**)&x1,   g_x1);
    cudaGetSymbolAddress((void**)&bqkv, g_bqkv);
    cudaGetSymbolAddress((void**)&wqkv, g_wqkv);
    cudaGetSymbolAddress((void**)&wo,   g_wo);
    cudaGetSymbolAddress((void**)&wae2, g_wae2);
    cudaGetSymbolAddress((void**)&wmod, g_wmod);
    cudaGetSymbolAddress((void**)&wm1,  g_wm1);
    cudaGetSymbolAddress((void**)&wm2,  g_wm2);

    static int attr_set = 0;
    if (!attr_set) {
        cudaFuncSetAttribute((const void*)hmma_kernel<EPI_NONE, 1>, cudaFuncAttributeMaxDynamicSharedMemorySize, HMMA_SMEM);
        cudaFuncSetAttribute((const void*)hmma_kernel<EPI_SILU, 1>, cudaFuncAttributeMaxDynamicSharedMemorySize, HMMA_SMEM);
        cudaFuncSetAttribute((const void*)hmma_kernel<EPI_GELU, 1>, cudaFuncAttributeMaxDynamicSharedMemorySize, HMMA_SMEM);
        cudaFuncSetAttribute((const void*)hmma_kernel<EPI_RES,  0>, cudaFuncAttributeMaxDynamicSharedMemorySize, HMMA_SMEM);
        cudaFuncSetAttribute((const void*)hmma_kernel<EPI_MOD,  0>, cudaFuncAttributeMaxDynamicSharedMemorySize, HMMA_SMEM);
        cudaFuncSetAttribute((const void*)attn_mma_kernel, cudaFuncAttributeMaxDynamicSharedMemorySize, ATT_SMEM);
        attr_set = 1;
    }

    dim3 g1024(8, 32);
    dim3 g2048(16, 32);
    dim3 g3072(24, 32);
    dim3 g4096(32, 32);

    // 1) convert all weights + bias pack (one coalesced launch)
    conv_all_kernel<<<U_TOT / 256, 256>>>(q_w, k_w, v_w, o_w, ae2_w, mod_w, m1_w, m2_w,
                                          q_b, k_b, v_b);
    // 2) h = rmsnorm(x, n1_w)
    rmsnorm_kernel<<<BT, 256>>>(x, n1_w, h);
    // 3) a1 = silu(actions @ ae1_w + ae1_b)
    ae1_kernel<<<dim3(BT / 32, 4), 256>>>(actions, ae1_w, ae1_b, a1);
    // 4) ae = silu(a1 @ ae2_w + ae2_b)
    hmma_kernel<EPI_SILU, 1><<<g1024, 256, HMMA_SMEM>>>(a1, wae2, ae2_b, nullptr, ae, BT, DIMD, DIMD);
    // 5) fused qkv projection
    hmma_kernel<EPI_NONE, 1><<<g3072, 256, HMMA_SMEM>>>(h, wqkv, bqkv, nullptr, qkv, BT, QSTR, DIMD);
    // 6) QK head norms
    headnorm_kernel<<<dim3((BT * NH) / 8, 2), 256>>>(qkv, qn_w, kn_w);
    // 7) attention
    attn_mma_kernel<<<dim3(TT / 128, 2 * NH), 256, ATT_SMEM>>>(qkv, ao);
    // 8) x1 = x + ao @ o_w + o_b
    hmma_kernel<EPI_RES, 0><<<g1024, 256, HMMA_SMEM>>>(ao, wo, o_b, x, x1, BT, DIMD, DIMD);
    // 9) fused modulate GEMM
    hmma_kernel<EPI_MOD, 0><<<g2048, 256, HMMA_SMEM>>>(ae, wmod, mod_b, x1, x1, BT, 2048, DIMD);
    // 10) h = rmsnorm(x1, n2_w)
    rmsnorm_kernel<<<BT, 256>>>(x1, n2_w, h);
    // 11) hid = gelu(h @ m1_w + m1_b)
    hmma_kernel<EPI_GELU, 1><<<g4096, 256, HMMA_SMEM>>>(h, wm1, m1_b, nullptr, hid, BT, MLPH, DIMD);
    // 12) out = x1 + hid @ m2_w + m2_b
    hmma_kernel<EPI_RES, 0><<<g1024, 256, HMMA_SMEM>>>(hid, wm2, m2_b, x1, out, BT, DIMD, MLPH);
}

// round 14
// speedup vs baseline: 6.3733x; 1.0419x over previous
#include <cuda_runtime.h>
#include <cuda_fp16.h>
#include <math.h>
#include <stdint.h>

#define BT    4096
#define DIMD  1024
#define NH    16
#define HD    64
#define TT    2048
#define MLPH  4096
#define QSTR  3072

// ---------------- scratch -------------------------------------------------------
__device__ __half g_h  [BT * DIMD];
__device__ __half g_a1 [BT * DIMD];
__device__ __half g_qkv[BT * QSTR];
__device__ __half g_ao [BT * DIMD];
__device__ __half g_ae [BT * DIMD];
__device__ __half g_hid[BT * MLPH];
__device__ float  g_x1 [BT * DIMD];
__device__ float  g_bqkv[QSTR];
// NATURAL layout ([K][N]) fp16 weights
__device__ __half g_wqkv[DIMD * QSTR];
__device__ __half g_wo  [DIMD * DIMD];
__device__ __half g_wae2[DIMD * DIMD];
__device__ __half g_wmod[DIMD * 2048];     // col 2j=shift_j, 2j+1=scale_j
__device__ __half g_wm1 [DIMD * MLPH];
__device__ __half g_wm2 [MLPH * DIMD];

// ---------------- fused weight convert (fp32->fp16, coalesced, one launch) ---------
#define U_QKV  786432
#define U_O    1048576
#define U_AE2  1310720
#define U_M1   2359296
#define U_M2   3407872
#define U_MOD  3670016
#define U_TOT  3670784

__global__ void conv_all_kernel(const float* __restrict__ q_w, const float* __restrict__ k_w,
                                const float* __restrict__ v_w, const float* __restrict__ o_w,
                                const float* __restrict__ ae2_w, const float* __restrict__ mod_w,
                                const float* __restrict__ m1_w, const float* __restrict__ m2_w,
                                const float* __restrict__ q_b, const float* __restrict__ k_b,
                                const float* __restrict__ v_b)
{
    int u = blockIdx.x * 256 + threadIdx.x;
    if (u < U_QKV) {
        int j = u >> 18, r = u & 262143;
        int k = r >> 8, n4 = (r & 255) << 2;
        const float* s = (j == 0) ? q_w : ((j == 1) ? k_w : v_w);
        float4 v = *(const float4*)&s[(size_t)k * 1024 + n4];
        uint2 o;
        ((__half2*)&o)[0] = __floats2half2_rn(v.x, v.y);
        ((__half2*)&o)[1] = __floats2half2_rn(v.z, v.w);
        *(uint2*)&g_wqkv[(size_t)k * QSTR + j * 1024 + n4] = o;
    } else if (u < U_O) {
        int e4 = (u - U_QKV) << 2;
        float4 v = *(const float4*)&o_w[e4];
        uint2 o;
        ((__half2*)&o)[0] = __floats2half2_rn(v.x, v.y);
        ((__half2*)&o)[1] = __floats2half2_rn(v.z, v.w);
        *(uint2*)&g_wo[e4] = o;
    } else if (u < U_AE2) {
        int e4 = (u - U_O) << 2;
        float4 v = *(const float4*)&ae2_w[e4];
        uint2 o;
        ((__half2*)&o)[0] = __floats2half2_rn(v.x, v.y);
        ((__half2*)&o)[1] = __floats2half2_rn(v.z, v.w);
        *(uint2*)&g_wae2[e4] = o;
    } else if (u < U_M1) {
        int e4 = (u - U_AE2) << 2;
        float4 v = *(const float4*)&m1_w[e4];
        uint2 o;
        ((__half2*)&o)[0] = __floats2half2_rn(v.x, v.y);
        ((__half2*)&o)[1] = __floats2half2_rn(v.z, v.w);
        *(uint2*)&g_wm1[e4] = o;
    } else if (u < U_M2) {
        int e4 = (u - U_M1) << 2;
        float4 v = *(const float4*)&m2_w[e4];
        uint2 o;
        ((__half2*)&o)[0] = __floats2half2_rn(v.x, v.y);
        ((__half2*)&o)[1] = __floats2half2_rn(v.z, v.w);
        *(uint2*)&g_wm2[e4] = o;
    } else if (u < U_MOD) {
        int r = u - U_M2;
        int k = r >> 8, j4 = (r & 255) << 2;
        float4 sh = *(const float4*)&mod_w[(size_t)k * 4096 + j4];
        float4 sc = *(const float4*)&mod_w[(size_t)k * 4096 + 1024 + j4];
        uint4 o;
        ((__half2*)&o)[0] = __floats2half2_rn(sh.x, sc.x);
        ((__half2*)&o)[1] = __floats2half2_rn(sh.y, sc.y);
        ((__half2*)&o)[2] = __floats2half2_rn(sh.z, sc.z);
        ((__half2*)&o)[3] = __floats2half2_rn(sh.w, sc.w);
        *(uint4*)&g_wmod[(size_t)k * 2048 + 2 * j4] = o;
    } else {
        int r = u - U_MOD;
        int i = r << 2;
        float4 v;
        if (i < 1024)      v = *(const float4*)&q_b[i];
        else if (i < 2048) v = *(const float4*)&k_b[i - 1024];
        else               v = *(const float4*)&v_b[i - 2048];
        *(float4*)&g_bqkv[i] = v;
    }
}

// ---------------- rmsnorm: float in -> half out ----------------------------------
__global__ void rmsnorm_kernel(const float* __restrict__ x,
                               const float* __restrict__ w,
                               __half* __restrict__ y)
{
    int row = blockIdx.x;
    const float* xr = x + (size_t)row * DIMD;
    float v[4];
    float s = 0.f;
#pragma unroll
    for (int i = 0; i < 4; i++) {
        v[i] = xr[threadIdx.x + i * 256];
        s += v[i] * v[i];
    }
#pragma unroll
    for (int o = 16; o > 0; o >>= 1) s += __shfl_xor_sync(0xffffffffu, s, o);
    __shared__ float red[8];
    if ((threadIdx.x & 31) == 0) red[threadIdx.x >> 5] = s;
    __syncthreads();
    if (threadIdx.x == 0) {
        float t = 0.f;
#pragma unroll
        for (int i = 0; i < 8; i++) t += red[i];
        red[0] = rsqrtf(t * (1.0f / DIMD) + 1e-6f);
    }
    __syncthreads();
    float r = red[0];
    __half* yr = y + (size_t)row * DIMD;
#pragma unroll
    for (int i = 0; i < 4; i++) {
        int c = threadIdx.x + i * 256;
        yr[c] = __float2half_rn(v[i] * r * w[c]);
    }
}

// ---------------- per-head rmsnorm on qkv buffer ------------------------------------
__global__ void headnorm_kernel(__half* __restrict__ qkv,
                                const float* __restrict__ qw, const float* __restrict__ kw)
{
    int sel = blockIdx.y;
    const float* w = sel ? kw : qw;
    float scale = sel ? 1.0f : 0.125f;
    int gw   = (blockIdx.x * blockDim.x + threadIdx.x) >> 5;
    int lane = threadIdx.x & 31;
    if (gw >= BT * NH) return;
    int token = gw >> 4, head = gw & 15;
    __half* p = qkv + (size_t)token * QSTR + sel * 1024 + head * 64;
    float a = __half2float(p[lane]);
    float b = __half2float(p[lane + 32]);
    float s = a * a + b * b;
#pragma unroll
    for (int o = 16; o > 0; o >>= 1) s += __shfl_xor_sync(0xffffffffu, s, o);
    float r = rsqrtf(s * (1.0f / HD) + 1e-6f) * scale;
    p[lane]      = __float2half_rn(a * r * w[lane]);
    p[lane + 32] = __float2half_rn(b * r * w[lane + 32]);
}

// ---------------- ae1 (K=16): 32 rows x 256 cols per block --------------------------
__global__ void __launch_bounds__(256) ae1_kernel(
    const float* __restrict__ A, const float* __restrict__ W,
    const float* __restrict__ bias, __half* __restrict__ C)
{
    __shared__ float Ws[16 * 256];
    __shared__ float As[32 * 16];
    int tid = threadIdx.x;
    int colbase = blockIdx.y * 256;
    for (int i = tid; i < 1024; i += 256) {
        int row = i >> 6, c4 = (i & 63) << 2;
        *(float4*)&Ws[row * 256 + c4] = *(const float4*)&W[(size_t)row * 1024 + colbase + c4];
    }
    int brow = blockIdx.x * 32;
    if (tid < 128)
        ((float4*)As)[tid] = ((const float4*)(A + (size_t)brow * 16))[tid];
    __syncthreads();

    int r = tid >> 3, lane8 = tid & 7;
    float a[16];
#pragma unroll
    for (int kk = 0; kk < 16; kk++) a[kk] = As[r * 16 + kk];
    __half* Cr = C + (size_t)(brow + r) * 1024 + colbase;

#pragma unroll
    for (int j = 0; j < 8; j++) {
        int col = lane8 * 4 + j * 32;
        float4 o = make_float4(bias[colbase + col],     bias[colbase + col + 1],
                               bias[colbase + col + 2], bias[colbase + col + 3]);
#pragma unroll
        for (int kk = 0; kk < 16; kk++) {
            float4 wv = *(float4*)&Ws[kk * 256 + col];
            o.x += a[kk] * wv.x; o.y += a[kk] * wv.y;
            o.z += a[kk] * wv.z; o.w += a[kk] * wv.w;
        }
        o.x = o.x / (1.f + expf(-o.x));
        o.y = o.y / (1.f + expf(-o.y));
        o.z = o.z / (1.f + expf(-o.z));
        o.w = o.w / (1.f + expf(-o.w));
        *(__half2*)&Cr[col]     = __floats2half2_rn(o.x, o.y);
        *(__half2*)&Cr[col + 2] = __floats2half2_rn(o.z, o.w);
    }
}

// ============ fp16 GEMM 128x128x64, 3-stage, natural-layout B via ldmatrix.trans ====
#define EPI_NONE 0
#define EPI_SILU 1
#define EPI_GELU 2
#define EPI_RES  3
#define EPI_MOD  4

#define GBK 64
#define GSTR 72
#define BSTR 136
#define APS  (128 * GSTR)
#define BPS  (64 * BSTR)
#define HMMA_SMEM (3 * (APS + BPS) * 2)

__device__ __forceinline__ void cp16h(__half* s, const __half* g)
{
    uint32_t sa = (uint32_t)__cvta_generic_to_shared(s);
    asm volatile("cp.async.cg.shared.global [%0], [%1], 16;\n" :: "r"(sa), "l"(g));
}

__device__ __forceinline__ void mma_f16(float* c, const uint32_t* a, const uint32_t* b)
{
    asm volatile(
        "mma.sync.aligned.m16n8k16.row.col.f32.f16.f16.f32 "
        "{%0,%1,%2,%3},{%4,%5,%6,%7},{%8,%9},{%0,%1,%2,%3};"
        : "+f"(c[0]), "+f"(c[1]), "+f"(c[2]), "+f"(c[3])
        : "r"(a[0]), "r"(a[1]), "r"(a[2]), "r"(a[3]), "r"(b[0]), "r"(b[1]));
}

__device__ __forceinline__ void ldm_x4(uint32_t* r, const __half* p)
{
    uint32_t addr = (uint32_t)__cvta_generic_to_shared(p);
    asm volatile("ldmatrix.sync.aligned.m8n8.x4.shared.b16 {%0,%1,%2,%3}, [%4];"
                 : "=r"(r[0]), "=r"(r[1]), "=r"(r[2]), "=r"(r[3]) : "r"(addr));
}

__device__ __forceinline__ void ldm_x4t(uint32_t* r, const __half* p)
{
    uint32_t addr = (uint32_t)__cvta_generic_to_shared(p);
    asm volatile("ldmatrix.sync.aligned.m8n8.x4.trans.shared.b16 {%0,%1,%2,%3}, [%4];"
                 : "=r"(r[0]), "=r"(r[1]), "=r"(r[2]), "=r"(r[3]) : "r"(addr));
}

template<int EPI, int HOUT>
__global__ void __launch_bounds__(256, 2) hmma_kernel(
    const __half* __restrict__ A, const __half* __restrict__ Wn,
    const float* __restrict__ bias, const float* __restrict__ Res,
    void* __restrict__ Cv, int M, int N, int K)
{
    extern __shared__ __half hsm[];
    __half* Asm = hsm;
    __half* Bsm = hsm + 3 * APS;

    int tid  = threadIdx.x;
    int brow = blockIdx.y * 128;
    int bcol = blockIdx.x * 128;
    int warp = tid >> 5, lane = tid & 31;
    int g = lane >> 2, t = lane & 3;
    int wr = warp & 1, wc = warp >> 1;

    int ar = tid >> 3, ac = (tid & 7) << 3;
    const __half* Agb = A + (size_t)(brow + ar) * K + ac;
    int br = tid >> 4, bc = (tid & 15) << 3;
    const __half* Bgb = Wn + (size_t)br * N + bcol + bc;

    int a_row  = wr * 64 + (lane & 15);
    int a_koff = (lane >> 4) << 3;

    float acc[4][4][4];
#pragma unroll
    for (int i = 0; i < 4; i++)
#pragma unroll
        for (int j = 0; j < 4; j++)
#pragma unroll
            for (int c = 0; c < 4; c++) acc[i][j][c] = 0.f;

    int nk = K / GBK;

#pragma unroll
    for (int s = 0; s < 2; s++) {
        int kc = s * GBK;
#pragma unroll
        for (int p = 0; p < 4; p++)
            cp16h(&Asm[s * APS + (ar + 32 * p) * GSTR + ac], Agb + (size_t)32 * p * K + kc);
#pragma unroll
        for (int p = 0; p < 4; p++)
            cp16h(&Bsm[s * BPS + (br + 16 * p) * BSTR + bc], Bgb + (size_t)(kc + 16 * p) * N);
        asm volatile("cp.async.commit_group;");
    }

    int st = 0;
    for (int i = 0; i < nk; i++) {
        asm volatile("cp.async.wait_group 1;" ::: "memory");
        __syncthreads();

        if (i + 2 < nk) {
            int kc = (i + 2) * GBK;
            int s2 = st + 2; if (s2 >= 3) s2 -= 3;
#pragma unroll
            for (int p = 0; p < 4; p++)
                cp16h(&Asm[s2 * APS + (ar + 32 * p) * GSTR + ac], Agb + (size_t)32 * p * K + kc);
#pragma unroll
            for (int p = 0; p < 4; p++)
                cp16h(&Bsm[s2 * BPS + (br + 16 * p) * BSTR + bc], Bgb + (size_t)(kc + 16 * p) * N);
        }
        asm volatile("cp.async.commit_group;");

        const __half* Sb = &Asm[st * APS];
        const __half* Tb = &Bsm[st * BPS];
#pragma unroll
        for (int kp2 = 0; kp2 < 2; kp2++) {
            int k0 = kp2 * 32;
            uint32_t af[2][4][4];
#pragma unroll
            for (int ti = 0; ti < 4; ti++) {
                ldm_x4(af[0][ti], Sb + (a_row + ti * 16) * GSTR + k0 + a_koff);
                ldm_x4(af[1][ti], Sb + (a_row + ti * 16) * GSTR + k0 + 16 + a_koff);
            }
#pragma unroll
            for (int tj = 0; tj < 4; tj++) {
                uint32_t vb[4];
                ldm_x4t(vb, Tb + (size_t)(k0 + lane) * BSTR + wc * 32 + tj * 8);
#pragma unroll
                for (int ti = 0; ti < 4; ti++) {
                    mma_f16(acc[ti][tj], af[0][ti], vb);
                    mma_f16(acc[ti][tj], af[1][ti], vb + 2);
                }
            }
        }
        if (++st == 3) st = 0;
    }

#pragma unroll
    for (int ti = 0; ti < 4; ti++) {
        int r0 = brow + wr * 64 + ti * 16 + g;
#pragma unroll
        for (int tj = 0; tj < 4; tj++) {
            int c0 = bcol + wc * 32 + tj * 8 + 2 * t;
#pragma unroll
            for (int half_i = 0; half_i < 2; half_i++) {
                int row = r0 + half_i * 8;
                float vx = acc[ti][tj][half_i * 2 + 0];
                float vy = acc[ti][tj][half_i * 2 + 1];
                if (EPI == EPI_MOD) {
                    int j = c0 >> 1;
                    float shift = vx + bias[j];
                    float scale = vy + bias[1024 + j];
                    float res = Res[(size_t)row * (N >> 1) + j];
                    ((float*)Cv)[(size_t)row * (N >> 1) + j] = res * (1.f + scale) + shift;
                    continue;
                }
                vx += bias[c0]; vy += bias[c0 + 1];
                if (EPI == EPI_SILU) {
                    vx = vx / (1.f + expf(-vx));
                    vy = vy / (1.f + expf(-vy));
                } else if (EPI == EPI_GELU) {
                    const float cst = 0.70710678118654752f;
                    vx = 0.5f * vx * (1.f + erff(vx * cst));
                    vy = 0.5f * vy * (1.f + erff(vy * cst));
                } else if (EPI == EPI_RES) {
                    float2 rv = *(const float2*)&Res[(size_t)row * N + c0];
                    vx += rv.x; vy += rv.y;
                }
                if (HOUT) {
                    *(__half2*)((__half*)Cv + (size_t)row * N + c0) = __floats2half2_rn(vx, vy);
                } else {
                    *(float2*)((float*)Cv + (size_t)row * N + c0) = make_float2(vx, vy);
                }
            }
        }
    }
}

// ---------------- fp16 flash attention, 128x64 tiles (unchanged) -------------------
#define AST 72
#define ATT_SMEM ((128 * AST + 4 * 64 * AST) * 2)

__global__ void __launch_bounds__(256) attn_mma_kernel(
    const __half* __restrict__ QKV, __half* __restrict__ O)
{
    extern __shared__ __half asm_[];
    __half* Qs = asm_;
    __half* Ks = Qs + 128 * AST;
    __half* Vs = Ks + 2 * 64 * AST;
    __half* Ps = Qs;

    int tid = threadIdx.x, warp = tid >> 5, lane = tid & 31;
    int g = lane >> 2, t = lane & 3;
    int qt = (TT / 128 - 1) - blockIdx.x;
    int bh = blockIdx.y, b = bh >> 4, h = bh & 15;

    const __half* Qg = QKV + (size_t)b * TT * QSTR + (size_t)h * HD;
    const __half* Kg = Qg + 1024;
    const __half* Vg = Qg + 2048;

    {
        int lrow = tid >> 1, ld32 = (tid & 1) << 5;
        const __half* src = Qg + (size_t)(qt * 128 + lrow) * QSTR + ld32;
        __half* dst = Qs + lrow * AST + ld32;
        *(uint4*)(dst)      = *(const uint4*)(src);
        *(uint4*)(dst + 8)  = *(const uint4*)(src + 8);
        *(uint4*)(dst + 16) = *(const uint4*)(src + 16);
        *(uint4*)(dst + 24) = *(const uint4*)(src + 24);
    }
    int lrow = tid >> 2, ld16 = (tid & 3) << 4;
    {
        const __half* kp = Kg + (size_t)lrow * QSTR + ld16;
        const __half* vp = Vg + (size_t)lrow * QSTR + ld16;
        cp16h(&Ks[lrow * AST + ld16],     kp);
        cp16h(&Ks[lrow * AST + ld16 + 8], kp + 8);
        cp16h(&Vs[lrow * AST + ld16],     vp);
        cp16h(&Vs[lrow * AST + ld16 + 8], vp + 8);
        asm volatile("cp.async.commit_group;");
    }
    __syncthreads();

    int r0 = warp * 16 + g;
    uint32_t qf[4][4];
#pragma unroll
    for (int ks = 0; ks < 4; ks++) {
        int k0 = ks * 16;
        qf[ks][0] = *(const uint32_t*)&Qs[(r0)     * AST + k0 + 2 * t];
        qf[ks][1] = *(const uint32_t*)&Qs[(r0 + 8) * AST + k0 + 2 * t];
        qf[ks][2] = *(const uint32_t*)&Qs[(r0)     * AST + k0 + 2 * t + 8];
        qf[ks][3] = *(const uint32_t*)&Qs[(r0 + 8) * AST + k0 + 2 * t + 8];
    }
    __half* Pw = Ps + warp * 16 * AST;

    int kb_row  = ((lane >> 4) << 3) + (lane & 7);
    int kb_koff = ((lane >> 3) & 1) << 3;
    int vb_row  = lane;

    float m0 = -1e30f, m1 = -1e30f, l0 = 0.f, l1 = 0.f;
    float acc[8][4];
#pragma unroll
    for (int tj = 0; tj < 8; tj++)
#pragma unroll
        for (int c = 0; c < 4; c++) acc[tj][c] = 0.f;

    int nkt = 2 * qt + 2;
    for (int kt = 0; kt < nkt; kt++) {
        int cur = kt & 1;
        asm volatile("cp.async.wait_group 0;" ::: "memory");
        __syncthreads();

        if (kt + 1 < nkt) {
            int nxt = cur ^ 1;
            const __half* kp = Kg + (size_t)((kt + 1) * 64 + lrow) * QSTR + ld16;
            const __half* vp = Vg + (size_t)((kt + 1) * 64 + lrow) * QSTR + ld16;
            cp16h(&Ks[nxt * 64 * AST + lrow * AST + ld16],     kp);
            cp16h(&Ks[nxt * 64 * AST + lrow * AST + ld16 + 8], kp + 8);
            cp16h(&Vs[nxt * 64 * AST + lrow * AST + ld16],     vp);
            cp16h(&Vs[nxt * 64 * AST + lrow * AST + ld16 + 8], vp + 8);
        }
        asm volatile("cp.async.commit_group;");

        const __half* Kc = Ks + cur * 64 * AST;
        const __half* Vc = Vs + cur * 64 * AST;

        float s[8][4];
#pragma unroll
        for (int tj = 0; tj < 8; tj++)
#pragma unroll
            for (int c = 0; c < 4; c++) s[tj][c] = 0.f;
#pragma unroll
        for (int ks = 0; ks < 4; ks++) {
            int k0 = ks * 16;
#pragma unroll
            for (int tp = 0; tp < 4; tp++) {
                uint32_t bf4[4];
                ldm_x4(bf4, Kc + (tp * 16 + kb_row) * AST + k0 + kb_koff);
                mma_f16(s[2 * tp],     qf[ks], bf4);
                mma_f16(s[2 * tp + 1], qf[ks], bf4 + 2);
            }
        }

        if (kt >= 2 * qt) {
            int cgb = kt * 64;
            int rg0 = qt * 128 + r0, rg1 = rg0 + 8;
#pragma unroll
            for (int tj = 0; tj < 8; tj++) {
                int c0 = cgb + tj * 8 + 2 * t;
                if (c0     > rg0) s[tj][0] = -1e30f;
                if (c0 + 1 > rg0) s[tj][1] = -1e30f;
                if (c0     > rg1) s[tj][2] = -1e30f;
                if (c0 + 1 > rg1) s[tj][3] = -1e30f;
            }
        }

        float rm0 = -1e30f, rm1 = -1e30f;
#pragma unroll
        for (int tj = 0; tj < 8; tj++) {
            rm0 = fmaxf(rm0, fmaxf(s[tj][0], s[tj][1]));
            rm1 = fmaxf(rm1, fmaxf(s[tj][2], s[tj][3]));
        }
#pragma unroll
        for (int o = 1; o < 4; o <<= 1) {
            rm0 = fmaxf(rm0, __shfl_xor_sync(0xffffffffu, rm0, o));
            rm1 = fmaxf(rm1, __shfl_xor_sync(0xffffffffu, rm1, o));
        }
        float nm0 = fmaxf(m0, rm0), nm1 = fmaxf(m1, rm1);
        float a0 = __expf(m0 - nm0), a1 = __expf(m1 - nm1);
        m0 = nm0; m1 = nm1;

        float ls0 = 0.f, ls1 = 0.f;
#pragma unroll
        for (int tj = 0; tj < 8; tj++) {
            s[tj][0] = __expf(s[tj][0] - nm0);
            s[tj][1] = __expf(s[tj][1] - nm0);
            s[tj][2] = __expf(s[tj][2] - nm1);
            s[tj][3] = __expf(s[tj][3] - nm1);
            ls0 += s[tj][0] + s[tj][1];
            ls1 += s[tj][2] + s[tj][3];
        }
#pragma unroll
        for (int o = 1; o < 4; o <<= 1) {
            ls0 += __shfl_xor_sync(0xffffffffu, ls0, o);
            ls1 += __shfl_xor_sync(0xffffffffu, ls1, o);
        }
        l0 = l0 * a0 + ls0;
        l1 = l1 * a1 + ls1;

#pragma unroll
        for (int tj = 0; tj < 8; tj++) {
            int c0 = tj * 8 + 2 * t;
            *(__half2*)&Pw[(g)     * AST + c0] = __floats2half2_rn(s[tj][0], s[tj][1]);
            *(__half2*)&Pw[(g + 8) * AST + c0] = __floats2half2_rn(s[tj][2], s[tj][3]);
        }
        __syncwarp();

#pragma unroll
        for (int tj = 0; tj < 8; tj++) {
            acc[tj][0] *= a0; acc[tj][1] *= a0;
            acc[tj][2] *= a1; acc[tj][3] *= a1;
        }

#pragma unroll
        for (int kp2 = 0; kp2 < 2; kp2++) {
            int k0 = kp2 * 32;
            uint32_t pf0[4], pf1[4];
            pf0[0] = *(const uint32_t*)&Pw[(g)     * AST + k0 + 2 * t];
            pf0[1] = *(const uint32_t*)&Pw[(g + 8) * AST + k0 + 2 * t];
            pf0[2] = *(const uint32_t*)&Pw[(g)     * AST + k0 + 2 * t + 8];
            pf0[3] = *(const uint32_t*)&Pw[(g + 8) * AST + k0 + 2 * t + 8];
            pf1[0] = *(const uint32_t*)&Pw[(g)     * AST + k0 + 16 + 2 * t];
            pf1[1] = *(const uint32_t*)&Pw[(g + 8) * AST + k0 + 16 + 2 * t];
            pf1[2] = *(const uint32_t*)&Pw[(g)     * AST + k0 + 16 + 2 * t + 8];
            pf1[3] = *(const uint32_t*)&Pw[(g + 8) * AST + k0 + 16 + 2 * t + 8];
#pragma unroll
            for (int tj = 0; tj < 8; tj++) {
                uint32_t vb[4];
                ldm_x4t(vb, Vc + (k0 + vb_row) * AST + tj * 8);
                mma_f16(acc[tj], pf0, vb);
                mma_f16(acc[tj], pf1, vb + 2);
            }
        }
    }

    float inv0 = 1.f / l0, inv1 = 1.f / l1;
    __half* Og = O + (size_t)b * TT * DIMD + (size_t)(qt * 128) * DIMD + (size_t)h * HD;
#pragma unroll
    for (int tj = 0; tj < 8; tj++) {
        int c0 = tj * 8 + 2 * t;
        *(__half2*)&Og[(size_t)(r0)     * DIMD + c0] = __floats2half2_rn(acc[tj][0] * inv0, acc[tj][1] * inv0);
        *(__half2*)&Og[(size_t)(r0 + 8) * DIMD + c0] = __floats2half2_rn(acc[tj][2] * inv1, acc[tj][3] * inv1);
    }
}

// ------------------------------- launch --------------------------------------------
extern "C" void kernel_launch(void* const* d_in, const int* in_sizes, int n_in,
                              void* d_out, int out_size)
{
    const float* x       = (const float*)d_in[0];
    const float* actions = (const float*)d_in[1];
    const float* n1_w    = (const float*)d_in[2];
    const float* n2_w    = (const float*)d_in[3];
    const float* q_w     = (const float*)d_in[4];
    const float* q_b     = (const float*)d_in[5];
    const float* k_w     = (const float*)d_in[6];
    const float* k_b     = (const float*)d_in[7];
    const float* v_w     = (const float*)d_in[8];
    const float* v_b     = (const float*)d_in[9];
    const float* qn_w    = (const float*)d_in[10];
    const float* kn_w    = (const float*)d_in[11];
    const float* o_w     = (const float*)d_in[12];
    const float* o_b     = (const float*)d_in[13];
    const float* ae1_w   = (const float*)d_in[14];
    const float* ae1_b   = (const float*)d_in[15];
    const float* ae2_w   = (const float*)d_in[16];
    const float* ae2_b   = (const float*)d_in[17];
    const float* mod_w   = (const float*)d_in[18];
    const float* mod_b   = (const float*)d_in[19];
    const float* m1_w    = (const float*)d_in[20];
    const float* m1_b    = (const float*)d_in[21];
    const float* m2_w    = (const float*)d_in[22];
    const float* m2_b    = (const float*)d_in[23];
    float* out           = (float*)d_out;

    __half *h, *a1, *qkv, *ao, *ae, *hid;
    float *x1, *bqkv;
    __half *wqkv, *wo, *wae2, *wmod, *wm1, *wm2;
    cudaGetSymbolAddress((void**)&h,    g_h);
    cudaGetSymbolAddress((void**)&a1,   g_a1);
    cudaGetSymbolAddress((void**)&qkv,  g_qkv);
    cudaGetSymbolAddress((void**)&ao,   g_ao);
    cudaGetSymbolAddress((void**)&ae,   g_ae);
    cudaGetSymbolAddress((void**)&hid,  g_hid);
    cudaGetSymbolAddress((void**)&x1,   g_x1);
    cudaGetSymbolAddress((void**)&bqkv, g_bqkv);
    cudaGetSymbolAddress((void**)&wqkv, g_wqkv);
    cudaGetSymbolAddress((void**)&wo,   g_wo);
    cudaGetSymbolAddress((void**)&wae2, g_wae2);
    cudaGetSymbolAddress((void**)&wmod, g_wmod);
    cudaGetSymbolAddress((void**)&wm1,  g_wm1);
    cudaGetSymbolAddress((void**)&wm2,  g_wm2);

    static int init_done = 0;
    static cudaStream_t s1, s2;
    static cudaEvent_t evRoot, evConv, evH, evAe;
    if (!init_done) {
        cudaFuncSetAttribute((const void*)hmma_kernel<EPI_NONE, 1>, cudaFuncAttributeMaxDynamicSharedMemorySize, HMMA_SMEM);
        cudaFuncSetAttribute((const void*)hmma_kernel<EPI_SILU, 1>, cudaFuncAttributeMaxDynamicSharedMemorySize, HMMA_SMEM);
        cudaFuncSetAttribute((const void*)hmma_kernel<EPI_GELU, 1>, cudaFuncAttributeMaxDynamicSharedMemorySize, HMMA_SMEM);
        cudaFuncSetAttribute((const void*)hmma_kernel<EPI_RES,  0>, cudaFuncAttributeMaxDynamicSharedMemorySize, HMMA_SMEM);
        cudaFuncSetAttribute((const void*)hmma_kernel<EPI_MOD,  0>, cudaFuncAttributeMaxDynamicSharedMemorySize, HMMA_SMEM);
        cudaFuncSetAttribute((const void*)attn_mma_kernel, cudaFuncAttributeMaxDynamicSharedMemorySize, ATT_SMEM);
        cudaStreamCreateWithFlags(&s1, cudaStreamNonBlocking);
        cudaStreamCreateWithFlags(&s2, cudaStreamNonBlocking);
        cudaEventCreateWithFlags(&evRoot, cudaEventDisableTiming);
        cudaEventCreateWithFlags(&evConv, cudaEventDisableTiming);
        cudaEventCreateWithFlags(&evH,    cudaEventDisableTiming);
        cudaEventCreateWithFlags(&evAe,   cudaEventDisableTiming);
        init_done = 1;
    }

    dim3 g1024(8, 32);
    dim3 g2048(16, 32);
    dim3 g3072(24, 32);
    dim3 g4096(32, 32);

    // ---- fork: s1 (ae branch) and s2 (rmsnorm1) run concurrent with conv on s0 ----
    cudaEventRecord(evRoot, 0);
    cudaStreamWaitEvent(s1, evRoot, 0);
    cudaStreamWaitEvent(s2, evRoot, 0);

    // s1: a1 = silu(actions @ ae1_w + ae1_b)  (fp32 weights — no conv dependency)
    ae1_kernel<<<dim3(BT / 32, 4), 256, 0, s1>>>(actions, ae1_w, ae1_b, a1);
    // s2: h = rmsnorm(x, n1_w)
    rmsnorm_kernel<<<BT, 256, 0, s2>>>(x, n1_w, h);
    cudaEventRecord(evH, s2);
    // s0: weight convert
    conv_all_kernel<<<U_TOT / 256, 256>>>(q_w, k_w, v_w, o_w, ae2_w, mod_w, m1_w, m2_w,
                                          q_b, k_b, v_b);
    cudaEventRecord(evConv, 0);

    // s1: ae = silu(a1 @ wae2 + ae2_b)   (needs conv)
    cudaStreamWaitEvent(s1, evConv, 0);
    hmma_kernel<EPI_SILU, 1><<<g1024, 256, HMMA_SMEM, s1>>>(a1, wae2, ae2_b, nullptr, ae, BT, DIMD, DIMD);
    cudaEventRecord(evAe, s1);

    // s0: qkv projection (needs h from s2; wqkv from conv on s0)
    cudaStreamWaitEvent(0, evH, 0);
    hmma_kernel<EPI_NONE, 1><<<g3072, 256, HMMA_SMEM>>>(h, wqkv, bqkv, nullptr, qkv, BT, QSTR, DIMD);
    // s0: QK head norms
    headnorm_kernel<<<dim3((BT * NH) / 8, 2), 256>>>(qkv, qn_w, kn_w);
    // s0: attention
    attn_mma_kernel<<<dim3(TT / 128, 2 * NH), 256, ATT_SMEM>>>(qkv, ao);
    // s0: x1 = x + ao @ wo + o_b
    hmma_kernel<EPI_RES, 0><<<g1024, 256, HMMA_SMEM>>>(ao, wo, o_b, x, x1, BT, DIMD, DIMD);

    // join: modulate GEMM needs ae (s1) and x1 (s0)
    cudaStreamWaitEvent(0, evAe, 0);
    hmma_kernel<EPI_MOD, 0><<<g2048, 256, HMMA_SMEM>>>(ae, wmod, mod_b, x1, x1, BT, 2048, DIMD);
    // s0: h = rmsnorm(x1, n2_w)
    rmsnorm_kernel<<<BT, 256>>>(x1, n2_w, h);
    // s0: hid = gelu(h @ wm1 + m1_b)
    hmma_kernel<EPI_GELU, 1><<<g4096, 256, HMMA_SMEM>>>(h, wm1, m1_b, nullptr, hid, BT, MLPH, DIMD);
    // s0: out = x1 + hid @ wm2 + m2_b
    hmma_kernel<EPI_RES, 0><<<g1024, 256, HMMA_SMEM>>>(hid, wm2, m2_b, x1, out, BT, DIMD, MLPH);
}